// round 1
// baseline (speedup 1.0000x reference)
#include <cuda_runtime.h>
#include <cuda_bf16.h>
#include <math.h>

// Problem constants
#define BQ 2
#define LQ 2048
#define HQ 1024
#define NHQ 8
#define DQKQ 128
#define DVQ 256
#define VDIMQ 2048
#define MROWS (BQ*LQ)   // 4096

#define QSCALE 0.08838834764831843f          // 128^-0.5
#define RF (-0.20762050593045852f)           // -2*log2(10000)/128

// Scratch (device globals: allocation-free contract)
__device__ float g_Q[MROWS*HQ];
__device__ float g_K[MROWS*HQ];
__device__ float g_V[MROWS*VDIMQ];
__device__ float g_G[MROWS*VDIMQ];
__device__ float g_O[MROWS*VDIMQ];

// ---------------------------------------------------------------------------
// Generic 128x128 tile SGEMM, C = A[MxK] @ B[KxN], row-major, fp32.
// Optional RoPE epilogue (head dim = 128, t = row % LQ).
// ---------------------------------------------------------------------------
template<bool ROPE>
__global__ void __launch_bounds__(256) gemm128(const float* __restrict__ A,
                                               const float* __restrict__ B,
                                               float* __restrict__ C,
                                               int M, int N, int K)
{
    __shared__ float AsT[8][132];   // [k][m] transposed
    __shared__ float Bs[8][132];    // [k][n]

    const int tid  = threadIdx.x;
    const int row0 = blockIdx.y * 128;
    const int col0 = blockIdx.x * 128;
    const int ty = tid >> 4;        // 0..15
    const int tx = tid & 15;        // 0..15

    float acc[8][8];
    #pragma unroll
    for (int i = 0; i < 8; i++)
        #pragma unroll
        for (int j = 0; j < 8; j++) acc[i][j] = 0.0f;

    const int am  = tid >> 1;            // 0..127
    const int ac4 = (tid & 1) * 4;       // 0 or 4
    const int br  = tid >> 5;            // 0..7
    const int bc4 = (tid & 31) * 4;      // 0..124

    const float* Ap = A + (size_t)(row0 + am) * K + ac4;
    const float* Bp = B + (size_t)br * N + col0 + bc4;

    const int nkt = K >> 3;
    for (int kt = 0; kt < nkt; kt++) {
        float4 av = *(const float4*)(Ap + (size_t)kt * 8);
        float4 bv = *(const float4*)(Bp + (size_t)kt * 8 * N);
        AsT[ac4 + 0][am] = av.x;
        AsT[ac4 + 1][am] = av.y;
        AsT[ac4 + 2][am] = av.z;
        AsT[ac4 + 3][am] = av.w;
        *(float4*)&Bs[br][bc4] = bv;
        __syncthreads();

        #pragma unroll
        for (int kk = 0; kk < 8; kk++) {
            float4 a0 = *(float4*)&AsT[kk][4 * ty];
            float4 a1 = *(float4*)&AsT[kk][64 + 4 * ty];
            float4 b0 = *(float4*)&Bs[kk][4 * tx];
            float4 b1 = *(float4*)&Bs[kk][64 + 4 * tx];
            float ar[8] = {a0.x, a0.y, a0.z, a0.w, a1.x, a1.y, a1.z, a1.w};
            float bc[8] = {b0.x, b0.y, b0.z, b0.w, b1.x, b1.y, b1.z, b1.w};
            #pragma unroll
            for (int i = 0; i < 8; i++)
                #pragma unroll
                for (int j = 0; j < 8; j++)
                    acc[i][j] += ar[i] * bc[j];
        }
        __syncthreads();
    }

    // Epilogue
    #pragma unroll
    for (int i = 0; i < 8; i++) {
        const int row = row0 + (i >> 2) * 64 + 4 * ty + (i & 3);
        #pragma unroll
        for (int jg = 0; jg < 2; jg++) {
            const int col = col0 + jg * 64 + 4 * tx;
            float4 v = make_float4(acc[i][4*jg+0], acc[i][4*jg+1],
                                   acc[i][4*jg+2], acc[i][4*jg+3]);
            if (ROPE) {
                const int t = row & (LQ - 1);
                const int p = (col & 127) >> 1;      // pair index (even since col%4==0)
                float inv0 = exp2f((float)p * RF);
                float inv1 = exp2f((float)(p + 1) * RF);
                float s0, c0, s1, c1;
                sincosf((float)t * inv0, &s0, &c0);
                sincosf((float)t * inv1, &s1, &c1);
                float x0 = v.x, x1 = v.y;
                v.x = x0 * c0 - x1 * s0;
                v.y = x1 * c0 + x0 * s0;
                x0 = v.z; x1 = v.w;
                v.z = x0 * c1 - x1 * s1;
                v.w = x1 * c1 + x0 * s1;
            }
            *(float4*)(C + (size_t)row * N + col) = v;
        }
    }
}

// ---------------------------------------------------------------------------
// Retention attention: per (b,h), per 64-row query tile; iterate causal key
// tiles of 64; S (with decay) kept in SMEM; O accumulated in registers.
// Dynamic SMEM: qsT[128][68] + ksT[128][68] + Vs[64][256] + Ssm[64][68]
// ---------------------------------------------------------------------------
#define ATT_SMEM ((2*128*68 + 64*256 + 64*68) * 4)

__global__ void __launch_bounds__(256) attn_kernel()
{
    extern __shared__ float sm[];
    float* qsT = sm;                    // [128][68]  (k-major)
    float* ksT = sm + 128 * 68;         // [128][68]
    float* Vs  = sm + 2 * 128 * 68;     // [64][256]
    float* Ssm = Vs + 64 * 256;         // [64][68]   (S transposed: [j][i])

    const int qt = blockIdx.x;          // 0..31
    const int bh = blockIdx.y;          // 0..15
    const int b  = bh >> 3;
    const int h  = bh & 7;

    const float* Qg = g_Q + (size_t)b * LQ * HQ + h * DQKQ;
    const float* Kg = g_K + (size_t)b * LQ * HQ + h * DQKQ;
    const float* Vg = g_V + (size_t)b * LQ * VDIMQ + h * DVQ;
    float*       Og = g_O + (size_t)b * LQ * VDIMQ + h * DVQ;

    const int tid = threadIdx.x;
    const float sh = log2f(1.0f - exp2f(-5.0f - (float)h));   // per-head decay log2
    const int qb = qt * 64;

    // Load Q tile transposed + scaled (once)
    for (int i = tid; i < 64 * 32; i += 256) {
        int m  = i >> 5;
        int c4 = (i & 31) << 2;
        float4 v = *(const float4*)(Qg + (size_t)(qb + m) * HQ + c4);
        qsT[(c4 + 0) * 68 + m] = v.x * QSCALE;
        qsT[(c4 + 1) * 68 + m] = v.y * QSCALE;
        qsT[(c4 + 2) * 68 + m] = v.z * QSCALE;
        qsT[(c4 + 3) * 68 + m] = v.w * QSCALE;
    }

    const int tm = tid & 15;     // stage-1: m group
    const int tn = tid >> 4;     // stage-1: n group
    const int rm = tid >> 4;     // stage-2: row group
    const int rn = tid & 15;     // stage-2: col group

    float facc[4][4][4];         // [r][g][c] -> O[4rm+r][4rn + 64g + c]
    #pragma unroll
    for (int r = 0; r < 4; r++)
        #pragma unroll
        for (int g = 0; g < 4; g++)
            #pragma unroll
            for (int c = 0; c < 4; c++) facc[r][g][c] = 0.0f;

    for (int jt = 0; jt <= qt; jt++) {
        const int kb = jt * 64;

        // Load K tile transposed
        for (int i = tid; i < 64 * 32; i += 256) {
            int m  = i >> 5;
            int c4 = (i & 31) << 2;
            float4 v = *(const float4*)(Kg + (size_t)(kb + m) * HQ + c4);
            ksT[(c4 + 0) * 68 + m] = v.x;
            ksT[(c4 + 1) * 68 + m] = v.y;
            ksT[(c4 + 2) * 68 + m] = v.z;
            ksT[(c4 + 3) * 68 + m] = v.w;
        }
        // Load V tile (row-major, rows = kv)
        for (int i = tid; i < 64 * 64; i += 256) {
            int r  = i >> 6;
            int c4 = (i & 63) << 2;
            *(float4*)&Vs[r * 256 + c4] =
                *(const float4*)(Vg + (size_t)(kb + r) * VDIMQ + c4);
        }
        __syncthreads();

        // Stage 1: S[4tm+r][4tn+c] = q . k  (sacc[c][r] for float4 STS)
        float sacc[4][4];
        #pragma unroll
        for (int c = 0; c < 4; c++)
            #pragma unroll
            for (int r = 0; r < 4; r++) sacc[c][r] = 0.0f;

        #pragma unroll 8
        for (int kk = 0; kk < 128; kk++) {
            float4 a  = *(float4*)&qsT[kk * 68 + 4 * tm];
            float4 bk = *(float4*)&ksT[kk * 68 + 4 * tn];
            sacc[0][0] += a.x * bk.x; sacc[0][1] += a.y * bk.x;
            sacc[0][2] += a.z * bk.x; sacc[0][3] += a.w * bk.x;
            sacc[1][0] += a.x * bk.y; sacc[1][1] += a.y * bk.y;
            sacc[1][2] += a.z * bk.y; sacc[1][3] += a.w * bk.y;
            sacc[2][0] += a.x * bk.z; sacc[2][1] += a.y * bk.z;
            sacc[2][2] += a.z * bk.z; sacc[2][3] += a.w * bk.z;
            sacc[3][0] += a.x * bk.w; sacc[3][1] += a.y * bk.w;
            sacc[3][2] += a.z * bk.w; sacc[3][3] += a.w * bk.w;
        }

        const bool diag = (jt == qt);
        const int i0 = qb + 4 * tm;
        #pragma unroll
        for (int c = 0; c < 4; c++) {
            const int j = kb + 4 * tn + c;
            float4 o;
            float v0, v1, v2, v3;
            v0 = sacc[c][0] * exp2f(sh * (float)(i0 + 0 - j));
            v1 = sacc[c][1] * exp2f(sh * (float)(i0 + 1 - j));
            v2 = sacc[c][2] * exp2f(sh * (float)(i0 + 2 - j));
            v3 = sacc[c][3] * exp2f(sh * (float)(i0 + 3 - j));
            if (diag) {
                if (j > i0 + 0) v0 = 0.0f;
                if (j > i0 + 1) v1 = 0.0f;
                if (j > i0 + 2) v2 = 0.0f;
                if (j > i0 + 3) v3 = 0.0f;
            }
            o.x = v0; o.y = v1; o.z = v2; o.w = v3;
            *(float4*)&Ssm[(4 * tn + c) * 68 + 4 * tm] = o;
        }
        __syncthreads();

        // Stage 2: O += S^T-read @ V
        #pragma unroll 4
        for (int kv = 0; kv < 64; kv++) {
            float4 a  = *(float4*)&Ssm[kv * 68 + 4 * rm];
            float4 b0 = *(float4*)&Vs[kv * 256 + 4 * rn];
            float4 b1 = *(float4*)&Vs[kv * 256 + 4 * rn + 64];
            float4 b2 = *(float4*)&Vs[kv * 256 + 4 * rn + 128];
            float4 b3 = *(float4*)&Vs[kv * 256 + 4 * rn + 192];
            float ar[4] = {a.x, a.y, a.z, a.w};
            float4 bg[4] = {b0, b1, b2, b3};
            #pragma unroll
            for (int r = 0; r < 4; r++) {
                #pragma unroll
                for (int g = 0; g < 4; g++) {
                    facc[r][g][0] += ar[r] * bg[g].x;
                    facc[r][g][1] += ar[r] * bg[g].y;
                    facc[r][g][2] += ar[r] * bg[g].z;
                    facc[r][g][3] += ar[r] * bg[g].w;
                }
            }
        }
        __syncthreads();
    }

    // Write O tile
    #pragma unroll
    for (int r = 0; r < 4; r++) {
        const int row = qb + 4 * rm + r;
        #pragma unroll
        for (int g = 0; g < 4; g++) {
            *(float4*)(Og + (size_t)row * VDIMQ + 4 * rn + 64 * g) =
                make_float4(facc[r][g][0], facc[r][g][1],
                            facc[r][g][2], facc[r][g][3]);
        }
    }
}

// ---------------------------------------------------------------------------
// Per-(b,l,h) RMSNorm over DV=256 + swish gate, in place on g_O.
// One warp per row; lane handles cols {4*lane..+3} and {128+4*lane..+3}.
// ---------------------------------------------------------------------------
__global__ void __launch_bounds__(256) normgate_kernel(const float* __restrict__ gw)
{
    const int warp = (blockIdx.x << 3) + (threadIdx.x >> 5);   // 0..32767
    const int lane = threadIdx.x & 31;
    const size_t base = (size_t)(warp >> 3) * VDIMQ + (size_t)(warp & 7) * DVQ;
    float* Op = g_O + base;
    const float* Gp = g_G + base;

    const int d0 = lane * 4;
    const int d1 = 128 + lane * 4;
    float4 o0 = *(float4*)(Op + d0);
    float4 o1 = *(float4*)(Op + d1);

    float ss = o0.x*o0.x + o0.y*o0.y + o0.z*o0.z + o0.w*o0.w
             + o1.x*o1.x + o1.y*o1.y + o1.z*o1.z + o1.w*o1.w;
    #pragma unroll
    for (int off = 16; off > 0; off >>= 1)
        ss += __shfl_xor_sync(0xFFFFFFFFu, ss, off);

    const float r = rsqrtf(ss * (1.0f / 256.0f) + 1e-5f);

    float4 g0 = *(const float4*)(Gp + d0);
    float4 g1 = *(const float4*)(Gp + d1);
    float4 w0 = *(const float4*)(gw + d0);
    float4 w1 = *(const float4*)(gw + d1);

    o0.x = o0.x * r * w0.x * (g0.x / (1.0f + expf(-g0.x)));
    o0.y = o0.y * r * w0.y * (g0.y / (1.0f + expf(-g0.y)));
    o0.z = o0.z * r * w0.z * (g0.z / (1.0f + expf(-g0.z)));
    o0.w = o0.w * r * w0.w * (g0.w / (1.0f + expf(-g0.w)));
    o1.x = o1.x * r * w1.x * (g1.x / (1.0f + expf(-g1.x)));
    o1.y = o1.y * r * w1.y * (g1.y / (1.0f + expf(-g1.y)));
    o1.z = o1.z * r * w1.z * (g1.z / (1.0f + expf(-g1.z)));
    o1.w = o1.w * r * w1.w * (g1.w / (1.0f + expf(-g1.w)));

    *(float4*)(Op + d0) = o0;
    *(float4*)(Op + d1) = o1;
}

// ---------------------------------------------------------------------------
// kernel_launch
// Inputs: hidden_states, Wq, Wk, Wv, Wg, Wo, g_norm_w (all fp32)
// ---------------------------------------------------------------------------
extern "C" void kernel_launch(void* const* d_in, const int* in_sizes, int n_in,
                              void* d_out, int out_size)
{
    const float* hs = (const float*)d_in[0];
    const float* Wq = (const float*)d_in[1];
    const float* Wk = (const float*)d_in[2];
    const float* Wv = (const float*)d_in[3];
    const float* Wg = (const float*)d_in[4];
    const float* Wo = (const float*)d_in[5];
    const float* gw = (const float*)d_in[6];
    float* out = (float*)d_out;

    float *Qp, *Kp, *Vp, *Gp, *Op;
    cudaGetSymbolAddress((void**)&Qp, g_Q);
    cudaGetSymbolAddress((void**)&Kp, g_K);
    cudaGetSymbolAddress((void**)&Vp, g_V);
    cudaGetSymbolAddress((void**)&Gp, g_G);
    cudaGetSymbolAddress((void**)&Op, g_O);

    cudaFuncSetAttribute(attn_kernel,
                         cudaFuncAttributeMaxDynamicSharedMemorySize, ATT_SMEM);

    dim3 blk(256);
    // Projections (RoPE fused for Q, K)
    gemm128<true ><<<dim3(HQ/128,    MROWS/128), blk>>>(hs, Wq, Qp, MROWS, HQ,    HQ);
    gemm128<true ><<<dim3(HQ/128,    MROWS/128), blk>>>(hs, Wk, Kp, MROWS, HQ,    HQ);
    gemm128<false><<<dim3(VDIMQ/128, MROWS/128), blk>>>(hs, Wv, Vp, MROWS, VDIMQ, HQ);
    gemm128<false><<<dim3(VDIMQ/128, MROWS/128), blk>>>(hs, Wg, Gp, MROWS, VDIMQ, HQ);

    // Retention attention
    attn_kernel<<<dim3(32, 16), blk, ATT_SMEM>>>();

    // RMSNorm + swish gate (in place on g_O)
    normgate_kernel<<<4096, blk>>>(gw);

    // Output projection
    gemm128<false><<<dim3(HQ/128, MROWS/128), blk>>>(Op, Wo, out, MROWS, HQ, VDIMQ);
}

// round 4
// speedup vs baseline: 1.6182x; 1.6182x over previous
#include <cuda_runtime.h>
#include <cuda_bf16.h>
#include <math.h>
#include <stdint.h>

// Problem constants
#define BQ 2
#define LQ 2048
#define HQ 1024
#define NHQ 8
#define DQKQ 128
#define DVQ 256
#define VDIMQ 2048
#define MROWS (BQ*LQ)   // 4096

#define QSCALE 0.08838834764831843f          // 128^-0.5
#define RF (-0.20762050593045852f)           // -2*log2(10000)/128

// ---------------------------------------------------------------------------
// Scratch (device globals: allocation-free contract)
// ---------------------------------------------------------------------------
__device__ float g_Q[MROWS*HQ];
__device__ float g_K[MROWS*HQ];
__device__ float g_V[MROWS*VDIMQ];
__device__ float g_G[MROWS*VDIMQ];
__device__ float g_O[MROWS*VDIMQ];

__device__ __nv_bfloat16 g_hs_hi[MROWS*HQ];
__device__ __nv_bfloat16 g_hs_lo[MROWS*HQ];
__device__ __nv_bfloat16 g_O_hi[MROWS*VDIMQ];
__device__ __nv_bfloat16 g_O_lo[MROWS*VDIMQ];
// Weights transposed to [N][K] (K-major), split hi/lo
__device__ __nv_bfloat16 g_WqT_hi[HQ*HQ],     g_WqT_lo[HQ*HQ];
__device__ __nv_bfloat16 g_WkT_hi[HQ*HQ],     g_WkT_lo[HQ*HQ];
__device__ __nv_bfloat16 g_WvT_hi[VDIMQ*HQ],  g_WvT_lo[VDIMQ*HQ];
__device__ __nv_bfloat16 g_WgT_hi[VDIMQ*HQ],  g_WgT_lo[VDIMQ*HQ];
__device__ __nv_bfloat16 g_WoT_hi[HQ*VDIMQ],  g_WoT_lo[HQ*VDIMQ];

// ---------------------------------------------------------------------------
// PTX helpers (sm_100-baseline safe: cp.async + ldmatrix + mma.sync only)
// ---------------------------------------------------------------------------
__device__ __forceinline__ uint32_t smem_u32(const void* p) {
    uint32_t a;
    asm("{ .reg .u64 t; cvta.to.shared.u64 t, %1; cvt.u32.u64 %0, t; }"
        : "=r"(a) : "l"(p));
    return a;
}

__device__ __forceinline__ void ldgsts16(uint32_t dst, const void* src) {
    asm volatile("cp.async.cg.shared.global [%0], [%1], 16;" :: "r"(dst), "l"(src));
}
__device__ __forceinline__ void cp_commit() {
    asm volatile("cp.async.commit_group;" ::: "memory");
}
template<int N_>
__device__ __forceinline__ void cp_wait() {
    asm volatile("cp.async.wait_group %0;" :: "n"(N_) : "memory");
}

__device__ __forceinline__ void ldsm4(uint32_t* r, uint32_t addr) {
    asm volatile("ldmatrix.sync.aligned.m8n8.x4.shared.b16 {%0,%1,%2,%3}, [%4];"
        : "=r"(r[0]), "=r"(r[1]), "=r"(r[2]), "=r"(r[3]) : "r"(addr));
}

__device__ __forceinline__ void mma_bf16(float* c, const uint32_t* a, const uint32_t* b) {
    asm volatile("mma.sync.aligned.m16n8k16.row.col.f32.bf16.bf16.f32 "
        "{%0,%1,%2,%3}, {%4,%5,%6,%7}, {%8,%9}, {%0,%1,%2,%3};"
        : "+f"(c[0]), "+f"(c[1]), "+f"(c[2]), "+f"(c[3])
        : "r"(a[0]), "r"(a[1]), "r"(a[2]), "r"(a[3]), "r"(b[0]), "r"(b[1]));
}

// SMEM tile: 128 rows x 32 bf16 (64B/row). 16B chunk index c swizzled with
// XOR key (r>>1)&3 so slot index mod 8 = 4*(r&1) + (c ^ ((r>>1)&3)) is
// injective over any 8 consecutive rows -> conflict-free ldmatrix AND stores.
#define GS_SWZ(r, c) ((uint32_t)((r) * 64u + (((c) ^ (((r) >> 1) & 3)) << 4)))

// Stage layout: AHI | ALO | BHI | BLO, each 8 KB; stage = 32 KB; 2 stages.
#define ST_AHI 0
#define ST_ALO 8192
#define ST_BHI 16384
#define ST_BLO 24576
#define STAGE_BYTES 32768
#define TCG_SMEM (2 * STAGE_BYTES)

// ---------------------------------------------------------------------------
// Split / transpose preprocessing kernels
// ---------------------------------------------------------------------------
__global__ void __launch_bounds__(256) split_kernel(const float* __restrict__ x,
                                                    __nv_bfloat16* __restrict__ hi,
                                                    __nv_bfloat16* __restrict__ lo,
                                                    int n4)
{
    int i = blockIdx.x * 256 + threadIdx.x;
    if (i >= n4) return;
    float4 v = ((const float4*)x)[i];
    __nv_bfloat16 h0 = __float2bfloat16(v.x), h1 = __float2bfloat16(v.y);
    __nv_bfloat16 h2 = __float2bfloat16(v.z), h3 = __float2bfloat16(v.w);
    __nv_bfloat16 l0 = __float2bfloat16(v.x - __bfloat162float(h0));
    __nv_bfloat16 l1 = __float2bfloat16(v.y - __bfloat162float(h1));
    __nv_bfloat16 l2 = __float2bfloat16(v.z - __bfloat162float(h2));
    __nv_bfloat16 l3 = __float2bfloat16(v.w - __bfloat162float(h3));
    ((__nv_bfloat162*)hi)[2*i]   = __nv_bfloat162(h0, h1);
    ((__nv_bfloat162*)hi)[2*i+1] = __nv_bfloat162(h2, h3);
    ((__nv_bfloat162*)lo)[2*i]   = __nv_bfloat162(l0, l1);
    ((__nv_bfloat162*)lo)[2*i+1] = __nv_bfloat162(l2, l3);
}

// W [K][N] fp32 -> WT hi/lo [N][K] bf16
__global__ void __launch_bounds__(256) transpose_split_kernel(const float* __restrict__ W,
                                                              __nv_bfloat16* __restrict__ ThT,
                                                              __nv_bfloat16* __restrict__ TlT,
                                                              int K, int N)
{
    __shared__ float s[32][33];
    const int k0 = blockIdx.y * 32;
    const int n0 = blockIdx.x * 32;
    const int tx = threadIdx.x & 31;
    const int ty = threadIdx.x >> 5;   // 0..7
    #pragma unroll
    for (int i = 0; i < 4; i++)
        s[ty + 8*i][tx] = W[(size_t)(k0 + ty + 8*i) * N + n0 + tx];
    __syncthreads();
    #pragma unroll
    for (int i = 0; i < 4; i++) {
        float v = s[tx][ty + 8*i];                 // = W[k0+tx][n0+ty+8i]
        int row = n0 + ty + 8*i;
        int col = k0 + tx;
        __nv_bfloat16 h = __float2bfloat16(v);
        __nv_bfloat16 l = __float2bfloat16(v - __bfloat162float(h));
        ThT[(size_t)row * K + col] = h;
        TlT[(size_t)row * K + col] = l;
    }
}

// ---------------------------------------------------------------------------
// bf16 HMMA GEMM: C[M x N] = A[M x K] @ B[K x N]; A hi/lo row-major bf16,
// B pre-transposed K-major [N][K] hi/lo bf16. 128x128 CTA tile, 8 warps of
// 64x32, K-chunks of 32, double-buffered cp.async. 3-term split accumulate.
// ---------------------------------------------------------------------------
template<bool ROPE>
__global__ void __launch_bounds__(256) tc_gemm(const __nv_bfloat16* __restrict__ Ahi,
                                               const __nv_bfloat16* __restrict__ Alo,
                                               const __nv_bfloat16* __restrict__ BhiT,
                                               const __nv_bfloat16* __restrict__ BloT,
                                               float* __restrict__ C,
                                               int N, int K)
{
    extern __shared__ char smem[];
    const uint32_t sbase = smem_u32(smem);

    const int tid  = threadIdx.x;
    const int wid  = tid >> 5;
    const int lane = tid & 31;
    const int row0 = blockIdx.y * 128;
    const int col0 = blockIdx.x * 128;
    const int wm   = (wid & 1) * 64;     // warp m offset in tile
    const int wn   = (wid >> 1) * 32;    // warp n offset in tile
    const int nchunks = K >> 5;

    float acc[4][4][4];
    #pragma unroll
    for (int mi = 0; mi < 4; mi++)
        #pragma unroll
        for (int ni = 0; ni < 4; ni++)
            #pragma unroll
            for (int e = 0; e < 4; e++) acc[mi][ni][e] = 0.0f;

    // chunk loader: 512 16B transfers per sub-tile; thread handles 2 rows/sub-tile
    auto load_chunk = [&](uint32_t sb, int k0) {
        #pragma unroll
        for (int t = 0; t < 2; t++) {
            int idx = tid + t * 256;       // 0..511
            int r   = idx >> 2;            // 0..127
            int c   = idx & 3;             // 16B chunk
            uint32_t soff = GS_SWZ(r, c);
            size_t aoff = (size_t)(row0 + r) * K + k0 + c * 8;
            size_t boff = (size_t)(col0 + r) * K + k0 + c * 8;
            ldgsts16(sb + ST_AHI + soff, Ahi  + aoff);
            ldgsts16(sb + ST_ALO + soff, Alo  + aoff);
            ldgsts16(sb + ST_BHI + soff, BhiT + boff);
            ldgsts16(sb + ST_BLO + soff, BloT + boff);
        }
        cp_commit();
    };

    load_chunk(sbase, 0);

    for (int cch = 0; cch < nchunks; cch++) {
        const uint32_t sb = sbase + (uint32_t)(cch & 1) * STAGE_BYTES;
        if (cch + 1 < nchunks) {
            load_chunk(sbase + (uint32_t)((cch + 1) & 1) * STAGE_BYTES, (cch + 1) * 32);
            cp_wait<1>();
        } else {
            cp_wait<0>();
        }
        __syncthreads();

        #pragma unroll
        for (int ks = 0; ks < 2; ks++) {
            uint32_t ahi[4][4], alo[4][4];
            #pragma unroll
            for (int mi = 0; mi < 4; mi++) {
                int r = wm + mi * 16 + (lane & 15);
                int c = ks * 2 + (lane >> 4);
                uint32_t ad = sb + ST_AHI + GS_SWZ(r, c);
                ldsm4(ahi[mi], ad);
                ldsm4(alo[mi], ad + (ST_ALO - ST_AHI));
            }
            uint32_t bhi[4][2], blo[4][2];
            #pragma unroll
            for (int j = 0; j < 2; j++) {
                // x4 covers ntiles 2j and 2j+1: matrices (n0-7,k0),(n0-7,k1),(n8-15,k0),(n8-15,k1)
                int m4 = lane >> 3;                 // matrix index
                int n  = wn + j * 16 + ((m4 >> 1) << 3) + (lane & 7);
                int c  = ks * 2 + (m4 & 1);
                uint32_t bd = sb + ST_BHI + GS_SWZ(n, c);
                uint32_t rh[4], rl[4];
                ldsm4(rh, bd);
                ldsm4(rl, bd + (ST_BLO - ST_BHI));
                bhi[2*j][0] = rh[0]; bhi[2*j][1] = rh[1];
                bhi[2*j+1][0] = rh[2]; bhi[2*j+1][1] = rh[3];
                blo[2*j][0] = rl[0]; blo[2*j][1] = rl[1];
                blo[2*j+1][0] = rl[2]; blo[2*j+1][1] = rl[3];
            }
            #pragma unroll
            for (int mi = 0; mi < 4; mi++)
                #pragma unroll
                for (int ni = 0; ni < 4; ni++) {
                    mma_bf16(acc[mi][ni], ahi[mi], bhi[ni]);
                    mma_bf16(acc[mi][ni], alo[mi], bhi[ni]);
                    mma_bf16(acc[mi][ni], ahi[mi], blo[ni]);
                }
        }
        __syncthreads();
    }

    // Epilogue: c0,c1 at (row, col..col+1); c2,c3 at (row+8, col..col+1)
    #pragma unroll
    for (int mi = 0; mi < 4; mi++) {
        const int row = row0 + wm + mi * 16 + (lane >> 2);
        #pragma unroll
        for (int ni = 0; ni < 4; ni++) {
            const int col = col0 + wn + ni * 8 + 2 * (lane & 3);
            float v0 = acc[mi][ni][0], v1 = acc[mi][ni][1];
            float v2 = acc[mi][ni][2], v3 = acc[mi][ni][3];
            if (ROPE) {
                const int p = (col & 127) >> 1;
                const float inv = exp2f((float)p * RF);
                float s0, c0f, s1, c1f;
                sincosf((float)(row & (LQ - 1)) * inv, &s0, &c0f);
                sincosf((float)((row + 8) & (LQ - 1)) * inv, &s1, &c1f);
                float x0 = v0, x1 = v1;
                v0 = x0 * c0f - x1 * s0;
                v1 = x1 * c0f + x0 * s0;
                x0 = v2; x1 = v3;
                v2 = x0 * c1f - x1 * s1;
                v3 = x1 * c1f + x0 * s1;
            }
            *(float2*)(C + (size_t)row * N + col)       = make_float2(v0, v1);
            *(float2*)(C + (size_t)(row + 8) * N + col) = make_float2(v2, v3);
        }
    }
}

// ---------------------------------------------------------------------------
// Retention attention (fp32 FFMA; unchanged)
// ---------------------------------------------------------------------------
#define ATT_SMEM ((2*128*68 + 64*256 + 64*68) * 4)

__global__ void __launch_bounds__(256) attn_kernel()
{
    extern __shared__ float sm[];
    float* qsT = sm;
    float* ksT = sm + 128 * 68;
    float* Vs  = sm + 2 * 128 * 68;
    float* Ssm = Vs + 64 * 256;

    const int qt = blockIdx.x;
    const int bh = blockIdx.y;
    const int b  = bh >> 3;
    const int h  = bh & 7;

    const float* Qg = g_Q + (size_t)b * LQ * HQ + h * DQKQ;
    const float* Kg = g_K + (size_t)b * LQ * HQ + h * DQKQ;
    const float* Vg = g_V + (size_t)b * LQ * VDIMQ + h * DVQ;
    float*       Og = g_O + (size_t)b * LQ * VDIMQ + h * DVQ;

    const int tid = threadIdx.x;
    const float sh = log2f(1.0f - exp2f(-5.0f - (float)h));
    const int qb = qt * 64;

    for (int i = tid; i < 64 * 32; i += 256) {
        int m  = i >> 5;
        int c4 = (i & 31) << 2;
        float4 v = *(const float4*)(Qg + (size_t)(qb + m) * HQ + c4);
        qsT[(c4 + 0) * 68 + m] = v.x * QSCALE;
        qsT[(c4 + 1) * 68 + m] = v.y * QSCALE;
        qsT[(c4 + 2) * 68 + m] = v.z * QSCALE;
        qsT[(c4 + 3) * 68 + m] = v.w * QSCALE;
    }

    const int tm = tid & 15;
    const int tn = tid >> 4;
    const int rm = tid >> 4;
    const int rn = tid & 15;

    float facc[4][4][4];
    #pragma unroll
    for (int r = 0; r < 4; r++)
        #pragma unroll
        for (int g = 0; g < 4; g++)
            #pragma unroll
            for (int c = 0; c < 4; c++) facc[r][g][c] = 0.0f;

    for (int jt = 0; jt <= qt; jt++) {
        const int kb = jt * 64;

        for (int i = tid; i < 64 * 32; i += 256) {
            int m  = i >> 5;
            int c4 = (i & 31) << 2;
            float4 v = *(const float4*)(Kg + (size_t)(kb + m) * HQ + c4);
            ksT[(c4 + 0) * 68 + m] = v.x;
            ksT[(c4 + 1) * 68 + m] = v.y;
            ksT[(c4 + 2) * 68 + m] = v.z;
            ksT[(c4 + 3) * 68 + m] = v.w;
        }
        for (int i = tid; i < 64 * 64; i += 256) {
            int r  = i >> 6;
            int c4 = (i & 63) << 2;
            *(float4*)&Vs[r * 256 + c4] =
                *(const float4*)(Vg + (size_t)(kb + r) * VDIMQ + c4);
        }
        __syncthreads();

        float sacc[4][4];
        #pragma unroll
        for (int c = 0; c < 4; c++)
            #pragma unroll
            for (int r = 0; r < 4; r++) sacc[c][r] = 0.0f;

        #pragma unroll 8
        for (int kk = 0; kk < 128; kk++) {
            float4 a  = *(float4*)&qsT[kk * 68 + 4 * tm];
            float4 bk = *(float4*)&ksT[kk * 68 + 4 * tn];
            sacc[0][0] += a.x * bk.x; sacc[0][1] += a.y * bk.x;
            sacc[0][2] += a.z * bk.x; sacc[0][3] += a.w * bk.x;
            sacc[1][0] += a.x * bk.y; sacc[1][1] += a.y * bk.y;
            sacc[1][2] += a.z * bk.y; sacc[1][3] += a.w * bk.y;
            sacc[2][0] += a.x * bk.z; sacc[2][1] += a.y * bk.z;
            sacc[2][2] += a.z * bk.z; sacc[2][3] += a.w * bk.z;
            sacc[3][0] += a.x * bk.w; sacc[3][1] += a.y * bk.w;
            sacc[3][2] += a.z * bk.w; sacc[3][3] += a.w * bk.w;
        }

        const bool diag = (jt == qt);
        const int i0 = qb + 4 * tm;
        #pragma unroll
        for (int c = 0; c < 4; c++) {
            const int j = kb + 4 * tn + c;
            float v0 = sacc[c][0] * exp2f(sh * (float)(i0 + 0 - j));
            float v1 = sacc[c][1] * exp2f(sh * (float)(i0 + 1 - j));
            float v2 = sacc[c][2] * exp2f(sh * (float)(i0 + 2 - j));
            float v3 = sacc[c][3] * exp2f(sh * (float)(i0 + 3 - j));
            if (diag) {
                if (j > i0 + 0) v0 = 0.0f;
                if (j > i0 + 1) v1 = 0.0f;
                if (j > i0 + 2) v2 = 0.0f;
                if (j > i0 + 3) v3 = 0.0f;
            }
            *(float4*)&Ssm[(4 * tn + c) * 68 + 4 * tm] = make_float4(v0, v1, v2, v3);
        }
        __syncthreads();

        #pragma unroll 4
        for (int kv = 0; kv < 64; kv++) {
            float4 a  = *(float4*)&Ssm[kv * 68 + 4 * rm];
            float4 b0 = *(float4*)&Vs[kv * 256 + 4 * rn];
            float4 b1 = *(float4*)&Vs[kv * 256 + 4 * rn + 64];
            float4 b2 = *(float4*)&Vs[kv * 256 + 4 * rn + 128];
            float4 b3 = *(float4*)&Vs[kv * 256 + 4 * rn + 192];
            float ar[4] = {a.x, a.y, a.z, a.w};
            float4 bg[4] = {b0, b1, b2, b3};
            #pragma unroll
            for (int r = 0; r < 4; r++) {
                #pragma unroll
                for (int g = 0; g < 4; g++) {
                    facc[r][g][0] += ar[r] * bg[g].x;
                    facc[r][g][1] += ar[r] * bg[g].y;
                    facc[r][g][2] += ar[r] * bg[g].z;
                    facc[r][g][3] += ar[r] * bg[g].w;
                }
            }
        }
        __syncthreads();
    }

    #pragma unroll
    for (int r = 0; r < 4; r++) {
        const int row = qb + 4 * rm + r;
        #pragma unroll
        for (int g = 0; g < 4; g++) {
            *(float4*)(Og + (size_t)row * VDIMQ + 4 * rn + 64 * g) =
                make_float4(facc[r][g][0], facc[r][g][1],
                            facc[r][g][2], facc[r][g][3]);
        }
    }
}

// ---------------------------------------------------------------------------
// RMSNorm + swish gate, in place on g_O.
// ---------------------------------------------------------------------------
__global__ void __launch_bounds__(256) normgate_kernel(const float* __restrict__ gw)
{
    const int warp = (blockIdx.x << 3) + (threadIdx.x >> 5);
    const int lane = threadIdx.x & 31;
    const size_t base = (size_t)(warp >> 3) * VDIMQ + (size_t)(warp & 7) * DVQ;
    float* Op = g_O + base;
    const float* Gp = g_G + base;

    const int d0 = lane * 4;
    const int d1 = 128 + lane * 4;
    float4 o0 = *(float4*)(Op + d0);
    float4 o1 = *(float4*)(Op + d1);

    float ss = o0.x*o0.x + o0.y*o0.y + o0.z*o0.z + o0.w*o0.w
             + o1.x*o1.x + o1.y*o1.y + o1.z*o1.z + o1.w*o1.w;
    #pragma unroll
    for (int off = 16; off > 0; off >>= 1)
        ss += __shfl_xor_sync(0xFFFFFFFFu, ss, off);

    const float r = rsqrtf(ss * (1.0f / 256.0f) + 1e-5f);

    float4 g0 = *(const float4*)(Gp + d0);
    float4 g1 = *(const float4*)(Gp + d1);
    float4 w0 = *(const float4*)(gw + d0);
    float4 w1 = *(const float4*)(gw + d1);

    o0.x = o0.x * r * w0.x * (g0.x / (1.0f + expf(-g0.x)));
    o0.y = o0.y * r * w0.y * (g0.y / (1.0f + expf(-g0.y)));
    o0.z = o0.z * r * w0.z * (g0.z / (1.0f + expf(-g0.z)));
    o0.w = o0.w * r * w0.w * (g0.w / (1.0f + expf(-g0.w)));
    o1.x = o1.x * r * w1.x * (g1.x / (1.0f + expf(-g1.x)));
    o1.y = o1.y * r * w1.y * (g1.y / (1.0f + expf(-g1.y)));
    o1.z = o1.z * r * w1.z * (g1.z / (1.0f + expf(-g1.z)));
    o1.w = o1.w * r * w1.w * (g1.w / (1.0f + expf(-g1.w)));

    *(float4*)(Op + d0) = o0;
    *(float4*)(Op + d1) = o1;
}

// ---------------------------------------------------------------------------
// kernel_launch
// ---------------------------------------------------------------------------
extern "C" void kernel_launch(void* const* d_in, const int* in_sizes, int n_in,
                              void* d_out, int out_size)
{
    const float* hs = (const float*)d_in[0];
    const float* Wq = (const float*)d_in[1];
    const float* Wk = (const float*)d_in[2];
    const float* Wv = (const float*)d_in[3];
    const float* Wg = (const float*)d_in[4];
    const float* Wo = (const float*)d_in[5];
    const float* gw = (const float*)d_in[6];
    float* out = (float*)d_out;

    float *Qp, *Kp, *Vp, *Gp, *Op;
    cudaGetSymbolAddress((void**)&Qp, g_Q);
    cudaGetSymbolAddress((void**)&Kp, g_K);
    cudaGetSymbolAddress((void**)&Vp, g_V);
    cudaGetSymbolAddress((void**)&Gp, g_G);
    cudaGetSymbolAddress((void**)&Op, g_O);

    __nv_bfloat16 *hsh, *hsl, *Ohh, *Oll;
    __nv_bfloat16 *qh, *ql, *kh, *kl, *vh, *vl, *gh, *gl, *oh, *ol;
    cudaGetSymbolAddress((void**)&hsh, g_hs_hi);
    cudaGetSymbolAddress((void**)&hsl, g_hs_lo);
    cudaGetSymbolAddress((void**)&Ohh, g_O_hi);
    cudaGetSymbolAddress((void**)&Oll, g_O_lo);
    cudaGetSymbolAddress((void**)&qh, g_WqT_hi); cudaGetSymbolAddress((void**)&ql, g_WqT_lo);
    cudaGetSymbolAddress((void**)&kh, g_WkT_hi); cudaGetSymbolAddress((void**)&kl, g_WkT_lo);
    cudaGetSymbolAddress((void**)&vh, g_WvT_hi); cudaGetSymbolAddress((void**)&vl, g_WvT_lo);
    cudaGetSymbolAddress((void**)&gh, g_WgT_hi); cudaGetSymbolAddress((void**)&gl, g_WgT_lo);
    cudaGetSymbolAddress((void**)&oh, g_WoT_hi); cudaGetSymbolAddress((void**)&ol, g_WoT_lo);

    cudaFuncSetAttribute(attn_kernel,
                         cudaFuncAttributeMaxDynamicSharedMemorySize, ATT_SMEM);
    cudaFuncSetAttribute(tc_gemm<true>,
                         cudaFuncAttributeMaxDynamicSharedMemorySize, TCG_SMEM);
    cudaFuncSetAttribute(tc_gemm<false>,
                         cudaFuncAttributeMaxDynamicSharedMemorySize, TCG_SMEM);

    dim3 blk(256);

    // 1) precompute: split hs, split+transpose weights
    split_kernel<<<(MROWS*HQ/4 + 255)/256, blk>>>(hs, hsh, hsl, MROWS*HQ/4);
    transpose_split_kernel<<<dim3(HQ/32,    HQ/32),    blk>>>(Wq, qh, ql, HQ,    HQ);
    transpose_split_kernel<<<dim3(HQ/32,    HQ/32),    blk>>>(Wk, kh, kl, HQ,    HQ);
    transpose_split_kernel<<<dim3(VDIMQ/32, HQ/32),    blk>>>(Wv, vh, vl, HQ,    VDIMQ);
    transpose_split_kernel<<<dim3(VDIMQ/32, HQ/32),    blk>>>(Wg, gh, gl, HQ,    VDIMQ);
    transpose_split_kernel<<<dim3(HQ/32,    VDIMQ/32), blk>>>(Wo, oh, ol, VDIMQ, HQ);

    // 2) projections on tensor cores (RoPE fused into Q/K epilogues)
    tc_gemm<true ><<<dim3(HQ/128,    MROWS/128), blk, TCG_SMEM>>>(hsh, hsl, qh, ql, Qp, HQ,    HQ);
    tc_gemm<true ><<<dim3(HQ/128,    MROWS/128), blk, TCG_SMEM>>>(hsh, hsl, kh, kl, Kp, HQ,    HQ);
    tc_gemm<false><<<dim3(VDIMQ/128, MROWS/128), blk, TCG_SMEM>>>(hsh, hsl, vh, vl, Vp, VDIMQ, HQ);
    tc_gemm<false><<<dim3(VDIMQ/128, MROWS/128), blk, TCG_SMEM>>>(hsh, hsl, gh, gl, Gp, VDIMQ, HQ);

    // 3) retention attention
    attn_kernel<<<dim3(32, 16), blk, ATT_SMEM>>>();

    // 4) RMSNorm + swish gate
    normgate_kernel<<<4096, blk>>>(gw);

    // 5) split O, output projection
    split_kernel<<<(MROWS*VDIMQ/4 + 255)/256, blk>>>(Op, Ohh, Oll, MROWS*VDIMQ/4);
    tc_gemm<false><<<dim3(HQ/128, MROWS/128), blk, TCG_SMEM>>>(Ohh, Oll, oh, ol, out, HQ, VDIMQ);
}

// round 5
// speedup vs baseline: 2.6970x; 1.6667x over previous
#include <cuda_runtime.h>
#include <cuda_bf16.h>
#include <math.h>
#include <stdint.h>

// Problem constants
#define BQ 2
#define LQ 2048
#define HQ 1024
#define NHQ 8
#define DQKQ 128
#define DVQ 256
#define VDIMQ 2048
#define MROWS (BQ*LQ)   // 4096

#define QSCALE 0.08838834764831843f          // 128^-0.5
#define RF (-0.20762050593045852f)           // -2*log2(10000)/128

// ---------------------------------------------------------------------------
// Scratch (device globals: allocation-free contract)
// ---------------------------------------------------------------------------
__device__ float g_G[MROWS*VDIMQ];
__device__ float g_O[MROWS*VDIMQ];

__device__ __nv_bfloat16 g_hs_hi[MROWS*HQ];
__device__ __nv_bfloat16 g_hs_lo[MROWS*HQ];
__device__ __nv_bfloat16 g_O_hi[MROWS*VDIMQ];
__device__ __nv_bfloat16 g_O_lo[MROWS*VDIMQ];
__device__ __nv_bfloat16 g_Qhi[MROWS*HQ],    g_Qlo[MROWS*HQ];
__device__ __nv_bfloat16 g_Khi[MROWS*HQ],    g_Klo[MROWS*HQ];
__device__ __nv_bfloat16 g_Vhi[MROWS*VDIMQ], g_Vlo[MROWS*VDIMQ];
// Weights transposed to [N][K] (K-major), split hi/lo
__device__ __nv_bfloat16 g_WqT_hi[HQ*HQ],     g_WqT_lo[HQ*HQ];
__device__ __nv_bfloat16 g_WkT_hi[HQ*HQ],     g_WkT_lo[HQ*HQ];
__device__ __nv_bfloat16 g_WvT_hi[VDIMQ*HQ],  g_WvT_lo[VDIMQ*HQ];
__device__ __nv_bfloat16 g_WgT_hi[VDIMQ*HQ],  g_WgT_lo[VDIMQ*HQ];
__device__ __nv_bfloat16 g_WoT_hi[HQ*VDIMQ],  g_WoT_lo[HQ*VDIMQ];

// ---------------------------------------------------------------------------
// PTX helpers (sm_100-baseline safe)
// ---------------------------------------------------------------------------
__device__ __forceinline__ uint32_t smem_u32(const void* p) {
    uint32_t a;
    asm("{ .reg .u64 t; cvta.to.shared.u64 t, %1; cvt.u32.u64 %0, t; }"
        : "=r"(a) : "l"(p));
    return a;
}
__device__ __forceinline__ void ldgsts16(uint32_t dst, const void* src) {
    asm volatile("cp.async.cg.shared.global [%0], [%1], 16;" :: "r"(dst), "l"(src));
}
__device__ __forceinline__ void cp_commit() {
    asm volatile("cp.async.commit_group;" ::: "memory");
}
template<int N_>
__device__ __forceinline__ void cp_wait() {
    asm volatile("cp.async.wait_group %0;" :: "n"(N_) : "memory");
}
__device__ __forceinline__ void ldsm4(uint32_t* r, uint32_t addr) {
    asm volatile("ldmatrix.sync.aligned.m8n8.x4.shared.b16 {%0,%1,%2,%3}, [%4];"
        : "=r"(r[0]), "=r"(r[1]), "=r"(r[2]), "=r"(r[3]) : "r"(addr));
}
__device__ __forceinline__ void ldsm4t(uint32_t* r, uint32_t addr) {
    asm volatile("ldmatrix.sync.aligned.m8n8.x4.trans.shared.b16 {%0,%1,%2,%3}, [%4];"
        : "=r"(r[0]), "=r"(r[1]), "=r"(r[2]), "=r"(r[3]) : "r"(addr));
}
__device__ __forceinline__ void sts32(uint32_t addr, uint32_t v) {
    asm volatile("st.shared.b32 [%0], %1;" :: "r"(addr), "r"(v) : "memory");
}
__device__ __forceinline__ void mma_bf16(float* c, const uint32_t* a, const uint32_t* b) {
    asm volatile("mma.sync.aligned.m16n8k16.row.col.f32.bf16.bf16.f32 "
        "{%0,%1,%2,%3}, {%4,%5,%6,%7}, {%8,%9}, {%0,%1,%2,%3};"
        : "+f"(c[0]), "+f"(c[1]), "+f"(c[2]), "+f"(c[3])
        : "r"(a[0]), "r"(a[1]), "r"(a[2]), "r"(a[3]), "r"(b[0]), "r"(b[1]));
}
__device__ __forceinline__ uint32_t pack_bf2(float a, float b) {
    __nv_bfloat162 t(__float2bfloat16(a), __float2bfloat16(b));
    return *(uint32_t*)&t;
}

// GEMM staging swizzle (64B rows)
#define GS_SWZ(r, c) ((uint32_t)((r) * 64u + (((c) ^ (((r) >> 1) & 3)) << 4)))
// Attention swizzles (256B / 512B / 128B rows), 16B chunk xor by (r&7)
#define SW256(r, c)  ((uint32_t)((r) * 256u + ((uint32_t)((c) ^ ((r) & 7)) << 4)))
#define SW512(r, c)  ((uint32_t)((r) * 512u + ((uint32_t)((c) ^ ((r) & 7)) << 4)))
#define SW128R(r, c) ((uint32_t)((r) * 128u + ((uint32_t)((c) ^ ((r) & 7)) << 4)))

// GEMM stage layout
#define ST_AHI 0
#define ST_ALO 8192
#define ST_BHI 16384
#define ST_BLO 24576
#define STAGE_BYTES 32768
#define TCG_SMEM (2 * STAGE_BYTES)

// ---------------------------------------------------------------------------
// Split / transpose preprocessing
// ---------------------------------------------------------------------------
__global__ void __launch_bounds__(256) split_kernel(const float* __restrict__ x,
                                                    __nv_bfloat16* __restrict__ hi,
                                                    __nv_bfloat16* __restrict__ lo,
                                                    int n4)
{
    int i = blockIdx.x * 256 + threadIdx.x;
    if (i >= n4) return;
    float4 v = ((const float4*)x)[i];
    __nv_bfloat16 h0 = __float2bfloat16(v.x), h1 = __float2bfloat16(v.y);
    __nv_bfloat16 h2 = __float2bfloat16(v.z), h3 = __float2bfloat16(v.w);
    __nv_bfloat16 l0 = __float2bfloat16(v.x - __bfloat162float(h0));
    __nv_bfloat16 l1 = __float2bfloat16(v.y - __bfloat162float(h1));
    __nv_bfloat16 l2 = __float2bfloat16(v.z - __bfloat162float(h2));
    __nv_bfloat16 l3 = __float2bfloat16(v.w - __bfloat162float(h3));
    ((__nv_bfloat162*)hi)[2*i]   = __nv_bfloat162(h0, h1);
    ((__nv_bfloat162*)hi)[2*i+1] = __nv_bfloat162(h2, h3);
    ((__nv_bfloat162*)lo)[2*i]   = __nv_bfloat162(l0, l1);
    ((__nv_bfloat162*)lo)[2*i+1] = __nv_bfloat162(l2, l3);
}

__global__ void __launch_bounds__(256) transpose_split_kernel(const float* __restrict__ W,
                                                              __nv_bfloat16* __restrict__ ThT,
                                                              __nv_bfloat16* __restrict__ TlT,
                                                              int K, int N)
{
    __shared__ float s[32][33];
    const int k0 = blockIdx.y * 32;
    const int n0 = blockIdx.x * 32;
    const int tx = threadIdx.x & 31;
    const int ty = threadIdx.x >> 5;
    #pragma unroll
    for (int i = 0; i < 4; i++)
        s[ty + 8*i][tx] = W[(size_t)(k0 + ty + 8*i) * N + n0 + tx];
    __syncthreads();
    #pragma unroll
    for (int i = 0; i < 4; i++) {
        float v = s[tx][ty + 8*i];
        int row = n0 + ty + 8*i;
        int col = k0 + tx;
        __nv_bfloat16 h = __float2bfloat16(v);
        __nv_bfloat16 l = __float2bfloat16(v - __bfloat162float(h));
        ThT[(size_t)row * K + col] = h;
        TlT[(size_t)row * K + col] = l;
    }
}

// ---------------------------------------------------------------------------
// bf16 HMMA GEMM. MODE: 0 = fp32 C; 1 = scale+RoPE -> bf16 hi/lo; 2 = bf16 hi/lo
// ---------------------------------------------------------------------------
template<int MODE>
__global__ void __launch_bounds__(256) tc_gemm(const __nv_bfloat16* __restrict__ Ahi,
                                               const __nv_bfloat16* __restrict__ Alo,
                                               const __nv_bfloat16* __restrict__ BhiT,
                                               const __nv_bfloat16* __restrict__ BloT,
                                               float* __restrict__ C,
                                               __nv_bfloat16* __restrict__ Chi,
                                               __nv_bfloat16* __restrict__ Clo,
                                               float scale, int N, int K)
{
    extern __shared__ char smem[];
    const uint32_t sbase = smem_u32(smem);

    const int tid  = threadIdx.x;
    const int wid  = tid >> 5;
    const int lane = tid & 31;
    const int row0 = blockIdx.y * 128;
    const int col0 = blockIdx.x * 128;
    const int wm   = (wid & 1) * 64;
    const int wn   = (wid >> 1) * 32;
    const int nchunks = K >> 5;

    float acc[4][4][4];
    #pragma unroll
    for (int mi = 0; mi < 4; mi++)
        #pragma unroll
        for (int ni = 0; ni < 4; ni++)
            #pragma unroll
            for (int e = 0; e < 4; e++) acc[mi][ni][e] = 0.0f;

    auto load_chunk = [&](uint32_t sb, int k0) {
        #pragma unroll
        for (int t = 0; t < 2; t++) {
            int idx = tid + t * 256;
            int r   = idx >> 2;
            int c   = idx & 3;
            uint32_t soff = GS_SWZ(r, c);
            size_t aoff = (size_t)(row0 + r) * K + k0 + c * 8;
            size_t boff = (size_t)(col0 + r) * K + k0 + c * 8;
            ldgsts16(sb + ST_AHI + soff, Ahi  + aoff);
            ldgsts16(sb + ST_ALO + soff, Alo  + aoff);
            ldgsts16(sb + ST_BHI + soff, BhiT + boff);
            ldgsts16(sb + ST_BLO + soff, BloT + boff);
        }
        cp_commit();
    };

    load_chunk(sbase, 0);

    for (int cch = 0; cch < nchunks; cch++) {
        const uint32_t sb = sbase + (uint32_t)(cch & 1) * STAGE_BYTES;
        if (cch + 1 < nchunks) {
            load_chunk(sbase + (uint32_t)((cch + 1) & 1) * STAGE_BYTES, (cch + 1) * 32);
            cp_wait<1>();
        } else {
            cp_wait<0>();
        }
        __syncthreads();

        #pragma unroll
        for (int ks = 0; ks < 2; ks++) {
            uint32_t ahi[4][4], alo[4][4];
            #pragma unroll
            for (int mi = 0; mi < 4; mi++) {
                int r = wm + mi * 16 + (lane & 15);
                int c = ks * 2 + (lane >> 4);
                uint32_t ad = sb + ST_AHI + GS_SWZ(r, c);
                ldsm4(ahi[mi], ad);
                ldsm4(alo[mi], ad + (ST_ALO - ST_AHI));
            }
            uint32_t bhi[4][2], blo[4][2];
            #pragma unroll
            for (int j = 0; j < 2; j++) {
                int m4 = lane >> 3;
                int n  = wn + j * 16 + ((m4 >> 1) << 3) + (lane & 7);
                int c  = ks * 2 + (m4 & 1);
                uint32_t bd = sb + ST_BHI + GS_SWZ(n, c);
                uint32_t rh[4], rl[4];
                ldsm4(rh, bd);
                ldsm4(rl, bd + (ST_BLO - ST_BHI));
                bhi[2*j][0] = rh[0]; bhi[2*j][1] = rh[1];
                bhi[2*j+1][0] = rh[2]; bhi[2*j+1][1] = rh[3];
                blo[2*j][0] = rl[0]; blo[2*j][1] = rl[1];
                blo[2*j+1][0] = rl[2]; blo[2*j+1][1] = rl[3];
            }
            #pragma unroll
            for (int mi = 0; mi < 4; mi++)
                #pragma unroll
                for (int ni = 0; ni < 4; ni++) {
                    mma_bf16(acc[mi][ni], ahi[mi], bhi[ni]);
                    mma_bf16(acc[mi][ni], alo[mi], bhi[ni]);
                    mma_bf16(acc[mi][ni], ahi[mi], blo[ni]);
                }
        }
        __syncthreads();
    }

    #pragma unroll
    for (int mi = 0; mi < 4; mi++) {
        const int row = row0 + wm + mi * 16 + (lane >> 2);
        #pragma unroll
        for (int ni = 0; ni < 4; ni++) {
            const int col = col0 + wn + ni * 8 + 2 * (lane & 3);
            float v0 = acc[mi][ni][0], v1 = acc[mi][ni][1];
            float v2 = acc[mi][ni][2], v3 = acc[mi][ni][3];
            if (MODE == 1) {
                v0 *= scale; v1 *= scale; v2 *= scale; v3 *= scale;
                const int p = (col & 127) >> 1;
                const float inv = exp2f((float)p * RF);
                float s0, c0f, s1, c1f;
                sincosf((float)(row & (LQ - 1)) * inv, &s0, &c0f);
                sincosf((float)((row + 8) & (LQ - 1)) * inv, &s1, &c1f);
                float x0 = v0, x1 = v1;
                v0 = x0 * c0f - x1 * s0;
                v1 = x1 * c0f + x0 * s0;
                x0 = v2; x1 = v3;
                v2 = x0 * c1f - x1 * s1;
                v3 = x1 * c1f + x0 * s1;
            }
            if (MODE == 0) {
                *(float2*)(C + (size_t)row * N + col)       = make_float2(v0, v1);
                *(float2*)(C + (size_t)(row + 8) * N + col) = make_float2(v2, v3);
            } else {
                __nv_bfloat16 h0 = __float2bfloat16(v0), h1 = __float2bfloat16(v1);
                __nv_bfloat16 h2 = __float2bfloat16(v2), h3 = __float2bfloat16(v3);
                __nv_bfloat16 l0 = __float2bfloat16(v0 - __bfloat162float(h0));
                __nv_bfloat16 l1 = __float2bfloat16(v1 - __bfloat162float(h1));
                __nv_bfloat16 l2 = __float2bfloat16(v2 - __bfloat162float(h2));
                __nv_bfloat16 l3 = __float2bfloat16(v3 - __bfloat162float(h3));
                *(__nv_bfloat162*)(Chi + (size_t)row * N + col)       = __nv_bfloat162(h0, h1);
                *(__nv_bfloat162*)(Chi + (size_t)(row + 8) * N + col) = __nv_bfloat162(h2, h3);
                *(__nv_bfloat162*)(Clo + (size_t)row * N + col)       = __nv_bfloat162(l0, l1);
                *(__nv_bfloat162*)(Clo + (size_t)(row + 8) * N + col) = __nv_bfloat162(l2, l3);
            }
        }
    }
}

// ---------------------------------------------------------------------------
// Tensor-core retention attention.
// Per CTA: (b,h), 128-row q tile; loop 64-row k tiles (causal).
// S = Q K^T (3-term split HMMA) -> decay/mask -> re-split -> O += S V (3-term).
// SMEM: Qhi/lo 64K | K dbl-buf 64K | Vhi/lo 64K | Shi/lo 32K = 224K.
// ---------------------------------------------------------------------------
#define ATT2_SMEM 229376

__global__ void __launch_bounds__(256) attn_tc_kernel()
{
    extern __shared__ char smem[];
    const uint32_t SB  = smem_u32(smem);
    const uint32_t sQh = SB,           sQl = SB + 32768;
    const uint32_t sKB = SB + 65536;                      // +(jt&1)*32768; lo at +16384
    const uint32_t sVh = SB + 131072,  sVl = SB + 163840;
    const uint32_t sSh = SB + 196608,  sSl = SB + 212992;

    const int qt = blockIdx.x, bh = blockIdx.y;
    const int b = bh >> 3, h = bh & 7;
    const int qb = qt * 128;
    const int nkt = 2 * qt + 2;
    const int tid = threadIdx.x, wid = tid >> 5, lane = tid & 31;
    const float sdec = log2f(1.0f - exp2f(-5.0f - (float)h));

    const __nv_bfloat16* Qh_g = g_Qhi + (size_t)(b * LQ + qb) * HQ + h * DQKQ;
    const __nv_bfloat16* Ql_g = g_Qlo + (size_t)(b * LQ + qb) * HQ + h * DQKQ;
    const __nv_bfloat16* Kh_g = g_Khi + (size_t)(b * LQ) * HQ + h * DQKQ;
    const __nv_bfloat16* Kl_g = g_Klo + (size_t)(b * LQ) * HQ + h * DQKQ;
    const __nv_bfloat16* Vh_g = g_Vhi + (size_t)(b * LQ) * VDIMQ + h * DVQ;
    const __nv_bfloat16* Vl_g = g_Vlo + (size_t)(b * LQ) * VDIMQ + h * DVQ;

    auto load_k = [&](uint32_t kbuf, int kb) {
        #pragma unroll
        for (int t = 0; t < 8; t++) {
            int idx = tid + t * 256;           // 0..2047
            int hl = idx >> 10, rem = idx & 1023;
            int r = rem >> 4, c = rem & 15;
            const __nv_bfloat16* src = (hl ? Kl_g : Kh_g) + (size_t)(kb + r) * HQ + c * 8;
            ldgsts16(kbuf + (uint32_t)hl * 16384 + SW256(r, c), src);
        }
    };
    auto load_v = [&](int kb) {
        #pragma unroll
        for (int t = 0; t < 16; t++) {
            int idx = tid + t * 256;           // 0..4095
            int hl = idx >> 11, rem = idx & 2047;
            int r = rem >> 5, c = rem & 31;
            const __nv_bfloat16* src = (hl ? Vl_g : Vh_g) + (size_t)(kb + r) * VDIMQ + c * 8;
            ldgsts16((hl ? sVl : sVh) + SW512(r, c), src);
        }
    };

    // Prologue: Q (128x128 hi/lo) + K0 + V0
    #pragma unroll
    for (int t = 0; t < 16; t++) {
        int idx = tid + t * 256;               // 0..4095
        int hl = idx >> 11, rem = idx & 2047;
        int r = rem >> 4, c = rem & 15;
        const __nv_bfloat16* src = (hl ? Ql_g : Qh_g) + (size_t)r * HQ + c * 8;
        ldgsts16((hl ? sQl : sQh) + SW256(r, c), src);
    }
    load_k(sKB, 0);
    load_v(0);
    cp_commit();

    const int wms = (wid >> 1) * 32, wns = (wid & 1) * 32;   // S warp tile 32x32
    const int wmo = (wid & 1) * 64,  wno = (wid >> 1) * 64;  // O warp tile 64x64

    float oacc[4][8][4];
    #pragma unroll
    for (int mi = 0; mi < 4; mi++)
        #pragma unroll
        for (int nt = 0; nt < 8; nt++)
            #pragma unroll
            for (int e = 0; e < 4; e++) oacc[mi][nt][e] = 0.0f;

    for (int jt = 0; jt < nkt; jt++) {
        const int kb = jt * 64;
        const uint32_t kh = sKB + (uint32_t)(jt & 1) * 32768;
        cp_wait<0>();
        __syncthreads();

        // ---- S = Q K^T (128x64), warp tile 32x32 ----
        float sacc[2][4][4];
        #pragma unroll
        for (int mi = 0; mi < 2; mi++)
            #pragma unroll
            for (int ni = 0; ni < 4; ni++)
                #pragma unroll
                for (int e = 0; e < 4; e++) sacc[mi][ni][e] = 0.0f;

        #pragma unroll
        for (int ks = 0; ks < 8; ks++) {
            uint32_t ah[2][4], al[2][4];
            #pragma unroll
            for (int mi = 0; mi < 2; mi++) {
                int r = wms + mi * 16 + (lane & 15);
                int c = ks * 2 + (lane >> 4);
                uint32_t ad = sQh + SW256(r, c);
                ldsm4(ah[mi], ad);
                ldsm4(al[mi], ad + 32768);
            }
            uint32_t bhf[4][2], blf[4][2];
            #pragma unroll
            for (int j = 0; j < 2; j++) {
                int m4 = lane >> 3;
                int n  = wns + j * 16 + ((m4 >> 1) << 3) + (lane & 7);
                int c  = ks * 2 + (m4 & 1);
                uint32_t bd = kh + SW256(n, c);
                uint32_t rh[4], rl[4];
                ldsm4(rh, bd);
                ldsm4(rl, bd + 16384);
                bhf[2*j][0] = rh[0]; bhf[2*j][1] = rh[1];
                bhf[2*j+1][0] = rh[2]; bhf[2*j+1][1] = rh[3];
                blf[2*j][0] = rl[0]; blf[2*j][1] = rl[1];
                blf[2*j+1][0] = rl[2]; blf[2*j+1][1] = rl[3];
            }
            #pragma unroll
            for (int mi = 0; mi < 2; mi++)
                #pragma unroll
                for (int ni = 0; ni < 4; ni++) {
                    mma_bf16(sacc[mi][ni], ah[mi], bhf[ni]);
                    mma_bf16(sacc[mi][ni], al[mi], bhf[ni]);
                    mma_bf16(sacc[mi][ni], ah[mi], blf[ni]);
                }
        }

        // prefetch next K into alternate buffer (overlaps with mask/store + O-MMA)
        if (jt + 1 < nkt) load_k(sKB + (uint32_t)((jt + 1) & 1) * 32768, kb + 64);

        // ---- decay + causal mask + split + store S ----
        #pragma unroll
        for (int mi = 0; mi < 2; mi++) {
            int r0 = wms + mi * 16 + (lane >> 2);
            int i0 = qb + r0, i1 = i0 + 8;
            #pragma unroll
            for (int ni = 0; ni < 4; ni++) {
                int c0 = wns + ni * 8 + 2 * (lane & 3);
                int j0 = kb + c0;
                float d00 = (i0 >= j0)     ? exp2f(sdec * (float)(i0 - j0))     : 0.0f;
                float d01 = (i0 >= j0 + 1) ? exp2f(sdec * (float)(i0 - j0 - 1)) : 0.0f;
                float d10 = (i1 >= j0)     ? exp2f(sdec * (float)(i1 - j0))     : 0.0f;
                float d11 = (i1 >= j0 + 1) ? exp2f(sdec * (float)(i1 - j0 - 1)) : 0.0f;
                float v0 = sacc[mi][ni][0] * d00, v1 = sacc[mi][ni][1] * d01;
                float v2 = sacc[mi][ni][2] * d10, v3 = sacc[mi][ni][3] * d11;
                float h0 = __bfloat162float(__float2bfloat16(v0));
                float h1 = __bfloat162float(__float2bfloat16(v1));
                float h2 = __bfloat162float(__float2bfloat16(v2));
                float h3 = __bfloat162float(__float2bfloat16(v3));
                int ch = c0 >> 3;
                int off = (c0 & 7) * 2;
                sts32(sSh + SW128R(r0, ch) + off,     pack_bf2(v0, v1));
                sts32(sSl + SW128R(r0, ch) + off,     pack_bf2(v0 - h0, v1 - h1));
                sts32(sSh + SW128R(r0 + 8, ch) + off, pack_bf2(v2, v3));
                sts32(sSl + SW128R(r0 + 8, ch) + off, pack_bf2(v2 - h2, v3 - h3));
            }
        }
        __syncthreads();

        // ---- O += S V (128x256), warp tile 64x64 ----
        #pragma unroll
        for (int ks = 0; ks < 4; ks++) {
            uint32_t ah[4][4], al[4][4];
            #pragma unroll
            for (int mi = 0; mi < 4; mi++) {
                int r = wmo + mi * 16 + (lane & 15);
                int c = ks * 2 + (lane >> 4);
                uint32_t ad = sSh + SW128R(r, c);
                ldsm4(ah[mi], ad);
                ldsm4(al[mi], ad + 16384);
            }
            uint32_t bhf[8][2], blf[8][2];
            #pragma unroll
            for (int np = 0; np < 4; np++) {
                int row = ks * 16 + ((lane >> 3) & 1) * 8 + (lane & 7);
                int cn  = (wno + np * 16 + (lane >> 4) * 8) >> 3;
                uint32_t vd = sVh + SW512(row, cn);
                uint32_t rh[4], rl[4];
                ldsm4t(rh, vd);
                ldsm4t(rl, vd + 32768);
                bhf[2*np][0] = rh[0]; bhf[2*np][1] = rh[1];
                bhf[2*np+1][0] = rh[2]; bhf[2*np+1][1] = rh[3];
                blf[2*np][0] = rl[0]; blf[2*np][1] = rl[1];
                blf[2*np+1][0] = rl[2]; blf[2*np+1][1] = rl[3];
            }
            #pragma unroll
            for (int mi = 0; mi < 4; mi++)
                #pragma unroll
                for (int nt = 0; nt < 8; nt++) {
                    mma_bf16(oacc[mi][nt], ah[mi], bhf[nt]);
                    mma_bf16(oacc[mi][nt], al[mi], bhf[nt]);
                    mma_bf16(oacc[mi][nt], ah[mi], blf[nt]);
                }
        }
        __syncthreads();
        if (jt + 1 < nkt) load_v(kb + 64);
        cp_commit();
    }

    // ---- write O (fp32) ----
    float* Og = g_O + (size_t)(b * LQ + qb) * VDIMQ + h * DVQ;
    #pragma unroll
    for (int mi = 0; mi < 4; mi++) {
        int r = wmo + mi * 16 + (lane >> 2);
        #pragma unroll
        for (int nt = 0; nt < 8; nt++) {
            int col = wno + nt * 8 + 2 * (lane & 3);
            *(float2*)(Og + (size_t)r * VDIMQ + col) =
                make_float2(oacc[mi][nt][0], oacc[mi][nt][1]);
            *(float2*)(Og + (size_t)(r + 8) * VDIMQ + col) =
                make_float2(oacc[mi][nt][2], oacc[mi][nt][3]);
        }
    }
}

// ---------------------------------------------------------------------------
// RMSNorm + swish gate, in place on g_O.
// ---------------------------------------------------------------------------
__global__ void __launch_bounds__(256) normgate_kernel(const float* __restrict__ gw)
{
    const int warp = (blockIdx.x << 3) + (threadIdx.x >> 5);
    const int lane = threadIdx.x & 31;
    const size_t base = (size_t)(warp >> 3) * VDIMQ + (size_t)(warp & 7) * DVQ;
    float* Op = g_O + base;
    const float* Gp = g_G + base;

    const int d0 = lane * 4;
    const int d1 = 128 + lane * 4;
    float4 o0 = *(float4*)(Op + d0);
    float4 o1 = *(float4*)(Op + d1);

    float ss = o0.x*o0.x + o0.y*o0.y + o0.z*o0.z + o0.w*o0.w
             + o1.x*o1.x + o1.y*o1.y + o1.z*o1.z + o1.w*o1.w;
    #pragma unroll
    for (int off = 16; off > 0; off >>= 1)
        ss += __shfl_xor_sync(0xFFFFFFFFu, ss, off);

    const float r = rsqrtf(ss * (1.0f / 256.0f) + 1e-5f);

    float4 g0 = *(const float4*)(Gp + d0);
    float4 g1 = *(const float4*)(Gp + d1);
    float4 w0 = *(const float4*)(gw + d0);
    float4 w1 = *(const float4*)(gw + d1);

    o0.x = o0.x * r * w0.x * (g0.x / (1.0f + expf(-g0.x)));
    o0.y = o0.y * r * w0.y * (g0.y / (1.0f + expf(-g0.y)));
    o0.z = o0.z * r * w0.z * (g0.z / (1.0f + expf(-g0.z)));
    o0.w = o0.w * r * w0.w * (g0.w / (1.0f + expf(-g0.w)));
    o1.x = o1.x * r * w1.x * (g1.x / (1.0f + expf(-g1.x)));
    o1.y = o1.y * r * w1.y * (g1.y / (1.0f + expf(-g1.y)));
    o1.z = o1.z * r * w1.z * (g1.z / (1.0f + expf(-g1.z)));
    o1.w = o1.w * r * w1.w * (g1.w / (1.0f + expf(-g1.w)));

    *(float4*)(Op + d0) = o0;
    *(float4*)(Op + d1) = o1;
}

// ---------------------------------------------------------------------------
// kernel_launch
// ---------------------------------------------------------------------------
extern "C" void kernel_launch(void* const* d_in, const int* in_sizes, int n_in,
                              void* d_out, int out_size)
{
    const float* hs = (const float*)d_in[0];
    const float* Wq = (const float*)d_in[1];
    const float* Wk = (const float*)d_in[2];
    const float* Wv = (const float*)d_in[3];
    const float* Wg = (const float*)d_in[4];
    const float* Wo = (const float*)d_in[5];
    const float* gw = (const float*)d_in[6];
    float* out = (float*)d_out;

    float *Gp, *Op;
    cudaGetSymbolAddress((void**)&Gp, g_G);
    cudaGetSymbolAddress((void**)&Op, g_O);

    __nv_bfloat16 *hsh, *hsl, *Ohh, *Oll;
    __nv_bfloat16 *Qh, *Ql, *Kh, *Kl, *Vh, *Vl;
    __nv_bfloat16 *qh, *ql, *kh, *kl, *vh, *vl, *gh, *gl, *oh, *ol;
    cudaGetSymbolAddress((void**)&hsh, g_hs_hi);
    cudaGetSymbolAddress((void**)&hsl, g_hs_lo);
    cudaGetSymbolAddress((void**)&Ohh, g_O_hi);
    cudaGetSymbolAddress((void**)&Oll, g_O_lo);
    cudaGetSymbolAddress((void**)&Qh, g_Qhi); cudaGetSymbolAddress((void**)&Ql, g_Qlo);
    cudaGetSymbolAddress((void**)&Kh, g_Khi); cudaGetSymbolAddress((void**)&Kl, g_Klo);
    cudaGetSymbolAddress((void**)&Vh, g_Vhi); cudaGetSymbolAddress((void**)&Vl, g_Vlo);
    cudaGetSymbolAddress((void**)&qh, g_WqT_hi); cudaGetSymbolAddress((void**)&ql, g_WqT_lo);
    cudaGetSymbolAddress((void**)&kh, g_WkT_hi); cudaGetSymbolAddress((void**)&kl, g_WkT_lo);
    cudaGetSymbolAddress((void**)&vh, g_WvT_hi); cudaGetSymbolAddress((void**)&vl, g_WvT_lo);
    cudaGetSymbolAddress((void**)&gh, g_WgT_hi); cudaGetSymbolAddress((void**)&gl, g_WgT_lo);
    cudaGetSymbolAddress((void**)&oh, g_WoT_hi); cudaGetSymbolAddress((void**)&ol, g_WoT_lo);

    cudaFuncSetAttribute(tc_gemm<0>, cudaFuncAttributeMaxDynamicSharedMemorySize, TCG_SMEM);
    cudaFuncSetAttribute(tc_gemm<1>, cudaFuncAttributeMaxDynamicSharedMemorySize, TCG_SMEM);
    cudaFuncSetAttribute(tc_gemm<2>, cudaFuncAttributeMaxDynamicSharedMemorySize, TCG_SMEM);
    cudaFuncSetAttribute(attn_tc_kernel, cudaFuncAttributeMaxDynamicSharedMemorySize, ATT2_SMEM);

    dim3 blk(256);

    // 1) precompute: split hs, split+transpose weights
    split_kernel<<<(MROWS*HQ/4 + 255)/256, blk>>>(hs, hsh, hsl, MROWS*HQ/4);
    transpose_split_kernel<<<dim3(HQ/32,    HQ/32),    blk>>>(Wq, qh, ql, HQ,    HQ);
    transpose_split_kernel<<<dim3(HQ/32,    HQ/32),    blk>>>(Wk, kh, kl, HQ,    HQ);
    transpose_split_kernel<<<dim3(VDIMQ/32, HQ/32),    blk>>>(Wv, vh, vl, HQ,    VDIMQ);
    transpose_split_kernel<<<dim3(VDIMQ/32, HQ/32),    blk>>>(Wg, gh, gl, HQ,    VDIMQ);
    transpose_split_kernel<<<dim3(HQ/32,    VDIMQ/32), blk>>>(Wo, oh, ol, VDIMQ, HQ);

    // 2) projections: Q/K -> scale+RoPE+split bf16; V -> split bf16; G -> fp32
    tc_gemm<1><<<dim3(HQ/128,    MROWS/128), blk, TCG_SMEM>>>(hsh, hsl, qh, ql, nullptr, Qh, Ql, QSCALE, HQ, HQ);
    tc_gemm<1><<<dim3(HQ/128,    MROWS/128), blk, TCG_SMEM>>>(hsh, hsl, kh, kl, nullptr, Kh, Kl, 1.0f,  HQ, HQ);
    tc_gemm<2><<<dim3(VDIMQ/128, MROWS/128), blk, TCG_SMEM>>>(hsh, hsl, vh, vl, nullptr, Vh, Vl, 1.0f,  VDIMQ, HQ);
    tc_gemm<0><<<dim3(VDIMQ/128, MROWS/128), blk, TCG_SMEM>>>(hsh, hsl, gh, gl, Gp, nullptr, nullptr, 1.0f, VDIMQ, HQ);

    // 3) retention attention on tensor cores
    attn_tc_kernel<<<dim3(16, 16), blk, ATT2_SMEM>>>();

    // 4) RMSNorm + swish gate
    normgate_kernel<<<4096, blk>>>(gw);

    // 5) split O, output projection
    split_kernel<<<(MROWS*VDIMQ/4 + 255)/256, blk>>>(Op, Ohh, Oll, MROWS*VDIMQ/4);
    tc_gemm<0><<<dim3(HQ/128, MROWS/128), blk, TCG_SMEM>>>(Ohh, Oll, oh, ol, out, nullptr, nullptr, 1.0f, HQ, VDIMQ);
}

// round 6
// speedup vs baseline: 3.0544x; 1.1325x over previous
#include <cuda_runtime.h>
#include <cuda_bf16.h>
#include <math.h>
#include <stdint.h>

// Problem constants
#define BQ 2
#define LQ 2048
#define HQ 1024
#define NHQ 8
#define DQKQ 128
#define DVQ 256
#define VDIMQ 2048
#define MROWS (BQ*LQ)   // 4096

#define QSCALE 0.08838834764831843f          // 128^-0.5
#define RF (-0.20762050593045852f)           // -2*log2(10000)/128

// ---------------------------------------------------------------------------
// Scratch (device globals: allocation-free contract)
// ---------------------------------------------------------------------------
__device__ float g_G[MROWS*VDIMQ];
__device__ float g_O[MROWS*VDIMQ];

__device__ __nv_bfloat16 g_hs_hi[MROWS*HQ];
__device__ __nv_bfloat16 g_hs_lo[MROWS*HQ];
__device__ __nv_bfloat16 g_O_hi[MROWS*VDIMQ];
__device__ __nv_bfloat16 g_O_lo[MROWS*VDIMQ];
__device__ __nv_bfloat16 g_Qhi[MROWS*HQ],    g_Qlo[MROWS*HQ];
__device__ __nv_bfloat16 g_Khi[MROWS*HQ],    g_Klo[MROWS*HQ];
__device__ __nv_bfloat16 g_Vhi[MROWS*VDIMQ], g_Vlo[MROWS*VDIMQ];
__device__ __nv_bfloat16 g_WqT_hi[HQ*HQ],     g_WqT_lo[HQ*HQ];
__device__ __nv_bfloat16 g_WkT_hi[HQ*HQ],     g_WkT_lo[HQ*HQ];
__device__ __nv_bfloat16 g_WvT_hi[VDIMQ*HQ],  g_WvT_lo[VDIMQ*HQ];
__device__ __nv_bfloat16 g_WgT_hi[VDIMQ*HQ],  g_WgT_lo[VDIMQ*HQ];
__device__ __nv_bfloat16 g_WoT_hi[HQ*VDIMQ],  g_WoT_lo[HQ*VDIMQ];

// ---------------------------------------------------------------------------
// PTX helpers (sm_100-baseline safe)
// ---------------------------------------------------------------------------
__device__ __forceinline__ uint32_t smem_u32(const void* p) {
    uint32_t a;
    asm("{ .reg .u64 t; cvta.to.shared.u64 t, %1; cvt.u32.u64 %0, t; }"
        : "=r"(a) : "l"(p));
    return a;
}
__device__ __forceinline__ void ldgsts16(uint32_t dst, const void* src) {
    asm volatile("cp.async.cg.shared.global [%0], [%1], 16;" :: "r"(dst), "l"(src));
}
__device__ __forceinline__ void cp_commit() {
    asm volatile("cp.async.commit_group;" ::: "memory");
}
template<int N_>
__device__ __forceinline__ void cp_wait() {
    asm volatile("cp.async.wait_group %0;" :: "n"(N_) : "memory");
}
__device__ __forceinline__ void ldsm4(uint32_t* r, uint32_t addr) {
    asm volatile("ldmatrix.sync.aligned.m8n8.x4.shared.b16 {%0,%1,%2,%3}, [%4];"
        : "=r"(r[0]), "=r"(r[1]), "=r"(r[2]), "=r"(r[3]) : "r"(addr));
}
__device__ __forceinline__ void ldsm4t(uint32_t* r, uint32_t addr) {
    asm volatile("ldmatrix.sync.aligned.m8n8.x4.trans.shared.b16 {%0,%1,%2,%3}, [%4];"
        : "=r"(r[0]), "=r"(r[1]), "=r"(r[2]), "=r"(r[3]) : "r"(addr));
}
__device__ __forceinline__ void sts32(uint32_t addr, uint32_t v) {
    asm volatile("st.shared.b32 [%0], %1;" :: "r"(addr), "r"(v) : "memory");
}
__device__ __forceinline__ void mma_bf16(float* c, const uint32_t* a, const uint32_t* b) {
    asm volatile("mma.sync.aligned.m16n8k16.row.col.f32.bf16.bf16.f32 "
        "{%0,%1,%2,%3}, {%4,%5,%6,%7}, {%8,%9}, {%0,%1,%2,%3};"
        : "+f"(c[0]), "+f"(c[1]), "+f"(c[2]), "+f"(c[3])
        : "r"(a[0]), "r"(a[1]), "r"(a[2]), "r"(a[3]), "r"(b[0]), "r"(b[1]));
}
__device__ __forceinline__ uint32_t pack_bf2(float a, float b) {
    __nv_bfloat162 t(__float2bfloat16(a), __float2bfloat16(b));
    return *(uint32_t*)&t;
}

// GEMM staging swizzle (64B rows)
#define GS_SWZ(r, c) ((uint32_t)((r) * 64u + (((c) ^ (((r) >> 1) & 3)) << 4)))
// Attention swizzles (256B / 512B / 128B rows)
#define SW256(r, c)  ((uint32_t)((r) * 256u + ((uint32_t)((c) ^ ((r) & 7)) << 4)))
#define SW512(r, c)  ((uint32_t)((r) * 512u + ((uint32_t)((c) ^ ((r) & 7)) << 4)))
#define SW128R(r, c) ((uint32_t)((r) * 128u + ((uint32_t)((c) ^ ((r) & 7)) << 4)))

#define ST_AHI 0
#define ST_ALO 8192
#define ST_BHI 16384
#define ST_BLO 24576
#define STAGE_BYTES 32768
#define TCG_SMEM (2 * STAGE_BYTES)

// ---------------------------------------------------------------------------
// hs split
// ---------------------------------------------------------------------------
__global__ void __launch_bounds__(256) split_kernel(const float* __restrict__ x,
                                                    __nv_bfloat16* __restrict__ hi,
                                                    __nv_bfloat16* __restrict__ lo,
                                                    int n4)
{
    int i = blockIdx.x * 256 + threadIdx.x;
    if (i >= n4) return;
    float4 v = ((const float4*)x)[i];
    __nv_bfloat16 h0 = __float2bfloat16(v.x), h1 = __float2bfloat16(v.y);
    __nv_bfloat16 h2 = __float2bfloat16(v.z), h3 = __float2bfloat16(v.w);
    __nv_bfloat16 l0 = __float2bfloat16(v.x - __bfloat162float(h0));
    __nv_bfloat16 l1 = __float2bfloat16(v.y - __bfloat162float(h1));
    __nv_bfloat16 l2 = __float2bfloat16(v.z - __bfloat162float(h2));
    __nv_bfloat16 l3 = __float2bfloat16(v.w - __bfloat162float(h3));
    ((__nv_bfloat162*)hi)[2*i]   = __nv_bfloat162(h0, h1);
    ((__nv_bfloat162*)hi)[2*i+1] = __nv_bfloat162(h2, h3);
    ((__nv_bfloat162*)lo)[2*i]   = __nv_bfloat162(l0, l1);
    ((__nv_bfloat162*)lo)[2*i+1] = __nv_bfloat162(l2, l3);
}

// ---------------------------------------------------------------------------
// Merged weight transpose+split: one launch for all 5 weights.
// Tile ids: Wq [0,1024) Wk [1024,2048) Wv [2048,4096) Wg [4096,6144) Wo [6144,8192)
// ---------------------------------------------------------------------------
struct TDesc { const float* W; __nv_bfloat16* hi; __nv_bfloat16* lo; int K, N, start; };
struct TDescs { TDesc d[5]; };

__global__ void __launch_bounds__(256) transpose_split_multi(TDescs ds)
{
    __shared__ float s[32][33];
    int t = blockIdx.x;
    int i = 0;
    #pragma unroll
    for (int j = 1; j < 5; j++) if (t >= ds.d[j].start) i = j;
    const float* W = ds.d[i].W;
    __nv_bfloat16* Th = ds.d[i].hi;
    __nv_bfloat16* Tl = ds.d[i].lo;
    const int K = ds.d[i].K, N = ds.d[i].N;
    int lt = t - ds.d[i].start;
    int ncols = N >> 5;
    int k0 = (lt / ncols) * 32;
    int n0 = (lt % ncols) * 32;

    const int tx = threadIdx.x & 31;
    const int ty = threadIdx.x >> 5;
    #pragma unroll
    for (int q = 0; q < 4; q++)
        s[ty + 8*q][tx] = W[(size_t)(k0 + ty + 8*q) * N + n0 + tx];
    __syncthreads();
    #pragma unroll
    for (int q = 0; q < 4; q++) {
        float v = s[tx][ty + 8*q];
        int row = n0 + ty + 8*q;
        int col = k0 + tx;
        __nv_bfloat16 h = __float2bfloat16(v);
        __nv_bfloat16 l = __float2bfloat16(v - __bfloat162float(h));
        Th[(size_t)row * K + col] = h;
        Tl[(size_t)row * K + col] = l;
    }
}

// ---------------------------------------------------------------------------
// Mega QKVG GEMM: one launch. grid (48, 32). Column block selects output:
// cb<8: Q (scale+RoPE+split), cb<16: K (RoPE+split), cb<32: V (split), else G (fp32)
// ---------------------------------------------------------------------------
__global__ void __launch_bounds__(256) qkvg_gemm()
{
    extern __shared__ char smem[];
    const uint32_t sbase = smem_u32(smem);

    const int tid  = threadIdx.x;
    const int wid  = tid >> 5;
    const int lane = tid & 31;
    const int row0 = blockIdx.y * 128;
    const int cb   = blockIdx.x;
    const int wm   = (wid & 1) * 64;
    const int wn   = (wid >> 1) * 32;
    const int K    = HQ;

    int mode, lcol0;
    const __nv_bfloat16 *Bh, *Bl;
    if (cb < 8)       { mode = 0; lcol0 = cb * 128;        Bh = g_WqT_hi; Bl = g_WqT_lo; }
    else if (cb < 16) { mode = 1; lcol0 = (cb - 8) * 128;  Bh = g_WkT_hi; Bl = g_WkT_lo; }
    else if (cb < 32) { mode = 2; lcol0 = (cb - 16) * 128; Bh = g_WvT_hi; Bl = g_WvT_lo; }
    else              { mode = 3; lcol0 = (cb - 32) * 128; Bh = g_WgT_hi; Bl = g_WgT_lo; }

    float acc[4][4][4];
    #pragma unroll
    for (int mi = 0; mi < 4; mi++)
        #pragma unroll
        for (int ni = 0; ni < 4; ni++)
            #pragma unroll
            for (int e = 0; e < 4; e++) acc[mi][ni][e] = 0.0f;

    auto load_chunk = [&](uint32_t sb, int k0) {
        #pragma unroll
        for (int t = 0; t < 2; t++) {
            int idx = tid + t * 256;
            int r   = idx >> 2;
            int c   = idx & 3;
            uint32_t soff = GS_SWZ(r, c);
            size_t aoff = (size_t)(row0 + r) * K + k0 + c * 8;
            size_t boff = (size_t)(lcol0 + r) * K + k0 + c * 8;
            ldgsts16(sb + ST_AHI + soff, g_hs_hi + aoff);
            ldgsts16(sb + ST_ALO + soff, g_hs_lo + aoff);
            ldgsts16(sb + ST_BHI + soff, Bh + boff);
            ldgsts16(sb + ST_BLO + soff, Bl + boff);
        }
        cp_commit();
    };

    load_chunk(sbase, 0);

    const int nchunks = K >> 5;
    for (int cch = 0; cch < nchunks; cch++) {
        const uint32_t sb = sbase + (uint32_t)(cch & 1) * STAGE_BYTES;
        if (cch + 1 < nchunks) {
            load_chunk(sbase + (uint32_t)((cch + 1) & 1) * STAGE_BYTES, (cch + 1) * 32);
            cp_wait<1>();
        } else {
            cp_wait<0>();
        }
        __syncthreads();

        #pragma unroll
        for (int ks = 0; ks < 2; ks++) {
            uint32_t ahi[4][4], alo[4][4];
            #pragma unroll
            for (int mi = 0; mi < 4; mi++) {
                int r = wm + mi * 16 + (lane & 15);
                int c = ks * 2 + (lane >> 4);
                uint32_t ad = sb + ST_AHI + GS_SWZ(r, c);
                ldsm4(ahi[mi], ad);
                ldsm4(alo[mi], ad + (ST_ALO - ST_AHI));
            }
            uint32_t bhi[4][2], blo[4][2];
            #pragma unroll
            for (int j = 0; j < 2; j++) {
                int m4 = lane >> 3;
                int n  = wn + j * 16 + ((m4 >> 1) << 3) + (lane & 7);
                int c  = ks * 2 + (m4 & 1);
                uint32_t bd = sb + ST_BHI + GS_SWZ(n, c);
                uint32_t rh[4], rl[4];
                ldsm4(rh, bd);
                ldsm4(rl, bd + (ST_BLO - ST_BHI));
                bhi[2*j][0] = rh[0]; bhi[2*j][1] = rh[1];
                bhi[2*j+1][0] = rh[2]; bhi[2*j+1][1] = rh[3];
                blo[2*j][0] = rl[0]; blo[2*j][1] = rl[1];
                blo[2*j+1][0] = rl[2]; blo[2*j+1][1] = rl[3];
            }
            #pragma unroll
            for (int mi = 0; mi < 4; mi++)
                #pragma unroll
                for (int ni = 0; ni < 4; ni++) {
                    mma_bf16(acc[mi][ni], ahi[mi], bhi[ni]);
                    mma_bf16(acc[mi][ni], alo[mi], bhi[ni]);
                    mma_bf16(acc[mi][ni], ahi[mi], blo[ni]);
                }
        }
        __syncthreads();
    }

    // Epilogue by mode
    #pragma unroll
    for (int mi = 0; mi < 4; mi++) {
        const int row = row0 + wm + mi * 16 + (lane >> 2);
        #pragma unroll
        for (int ni = 0; ni < 4; ni++) {
            const int col = lcol0 + wn + ni * 8 + 2 * (lane & 3);
            float v0 = acc[mi][ni][0], v1 = acc[mi][ni][1];
            float v2 = acc[mi][ni][2], v3 = acc[mi][ni][3];
            if (mode <= 1) {   // Q or K: scale + RoPE + split, N = HQ
                if (mode == 0) { v0 *= QSCALE; v1 *= QSCALE; v2 *= QSCALE; v3 *= QSCALE; }
                const int p = (col & 127) >> 1;
                const float inv = exp2f((float)p * RF);
                float s0, c0f, s1, c1f;
                sincosf((float)(row & (LQ - 1)) * inv, &s0, &c0f);
                sincosf((float)((row + 8) & (LQ - 1)) * inv, &s1, &c1f);
                float x0 = v0, x1 = v1;
                v0 = x0 * c0f - x1 * s0;
                v1 = x1 * c0f + x0 * s0;
                x0 = v2; x1 = v3;
                v2 = x0 * c1f - x1 * s1;
                v3 = x1 * c1f + x0 * s1;
                __nv_bfloat16 h0 = __float2bfloat16(v0), h1 = __float2bfloat16(v1);
                __nv_bfloat16 h2 = __float2bfloat16(v2), h3 = __float2bfloat16(v3);
                __nv_bfloat16 l0 = __float2bfloat16(v0 - __bfloat162float(h0));
                __nv_bfloat16 l1 = __float2bfloat16(v1 - __bfloat162float(h1));
                __nv_bfloat16 l2 = __float2bfloat16(v2 - __bfloat162float(h2));
                __nv_bfloat16 l3 = __float2bfloat16(v3 - __bfloat162float(h3));
                __nv_bfloat16* Chi = (mode == 0) ? g_Qhi : g_Khi;
                __nv_bfloat16* Clo = (mode == 0) ? g_Qlo : g_Klo;
                *(__nv_bfloat162*)(Chi + (size_t)row * HQ + col)       = __nv_bfloat162(h0, h1);
                *(__nv_bfloat162*)(Chi + (size_t)(row + 8) * HQ + col) = __nv_bfloat162(h2, h3);
                *(__nv_bfloat162*)(Clo + (size_t)row * HQ + col)       = __nv_bfloat162(l0, l1);
                *(__nv_bfloat162*)(Clo + (size_t)(row + 8) * HQ + col) = __nv_bfloat162(l2, l3);
            } else if (mode == 2) {  // V: split, N = VDIMQ
                __nv_bfloat16 h0 = __float2bfloat16(v0), h1 = __float2bfloat16(v1);
                __nv_bfloat16 h2 = __float2bfloat16(v2), h3 = __float2bfloat16(v3);
                __nv_bfloat16 l0 = __float2bfloat16(v0 - __bfloat162float(h0));
                __nv_bfloat16 l1 = __float2bfloat16(v1 - __bfloat162float(h1));
                __nv_bfloat16 l2 = __float2bfloat16(v2 - __bfloat162float(h2));
                __nv_bfloat16 l3 = __float2bfloat16(v3 - __bfloat162float(h3));
                *(__nv_bfloat162*)(g_Vhi + (size_t)row * VDIMQ + col)       = __nv_bfloat162(h0, h1);
                *(__nv_bfloat162*)(g_Vhi + (size_t)(row + 8) * VDIMQ + col) = __nv_bfloat162(h2, h3);
                *(__nv_bfloat162*)(g_Vlo + (size_t)row * VDIMQ + col)       = __nv_bfloat162(l0, l1);
                *(__nv_bfloat162*)(g_Vlo + (size_t)(row + 8) * VDIMQ + col) = __nv_bfloat162(l2, l3);
            } else {                 // G: fp32, N = VDIMQ
                *(float2*)(g_G + (size_t)row * VDIMQ + col)       = make_float2(v0, v1);
                *(float2*)(g_G + (size_t)(row + 8) * VDIMQ + col) = make_float2(v2, v3);
            }
        }
    }
}

// ---------------------------------------------------------------------------
// Wo GEMM: fp32 out. A = O hi/lo, B = WoT hi/lo, K=2048, N=1024.
// ---------------------------------------------------------------------------
__global__ void __launch_bounds__(256) wo_gemm(float* __restrict__ C)
{
    extern __shared__ char smem[];
    const uint32_t sbase = smem_u32(smem);

    const int tid  = threadIdx.x;
    const int wid  = tid >> 5;
    const int lane = tid & 31;
    const int row0 = blockIdx.y * 128;
    const int col0 = blockIdx.x * 128;
    const int wm   = (wid & 1) * 64;
    const int wn   = (wid >> 1) * 32;
    const int K    = VDIMQ;
    const int N    = HQ;

    float acc[4][4][4];
    #pragma unroll
    for (int mi = 0; mi < 4; mi++)
        #pragma unroll
        for (int ni = 0; ni < 4; ni++)
            #pragma unroll
            for (int e = 0; e < 4; e++) acc[mi][ni][e] = 0.0f;

    auto load_chunk = [&](uint32_t sb, int k0) {
        #pragma unroll
        for (int t = 0; t < 2; t++) {
            int idx = tid + t * 256;
            int r   = idx >> 2;
            int c   = idx & 3;
            uint32_t soff = GS_SWZ(r, c);
            size_t aoff = (size_t)(row0 + r) * K + k0 + c * 8;
            size_t boff = (size_t)(col0 + r) * K + k0 + c * 8;
            ldgsts16(sb + ST_AHI + soff, g_O_hi + aoff);
            ldgsts16(sb + ST_ALO + soff, g_O_lo + aoff);
            ldgsts16(sb + ST_BHI + soff, g_WoT_hi + boff);
            ldgsts16(sb + ST_BLO + soff, g_WoT_lo + boff);
        }
        cp_commit();
    };

    load_chunk(sbase, 0);

    const int nchunks = K >> 5;
    for (int cch = 0; cch < nchunks; cch++) {
        const uint32_t sb = sbase + (uint32_t)(cch & 1) * STAGE_BYTES;
        if (cch + 1 < nchunks) {
            load_chunk(sbase + (uint32_t)((cch + 1) & 1) * STAGE_BYTES, (cch + 1) * 32);
            cp_wait<1>();
        } else {
            cp_wait<0>();
        }
        __syncthreads();

        #pragma unroll
        for (int ks = 0; ks < 2; ks++) {
            uint32_t ahi[4][4], alo[4][4];
            #pragma unroll
            for (int mi = 0; mi < 4; mi++) {
                int r = wm + mi * 16 + (lane & 15);
                int c = ks * 2 + (lane >> 4);
                uint32_t ad = sb + ST_AHI + GS_SWZ(r, c);
                ldsm4(ahi[mi], ad);
                ldsm4(alo[mi], ad + (ST_ALO - ST_AHI));
            }
            uint32_t bhi[4][2], blo[4][2];
            #pragma unroll
            for (int j = 0; j < 2; j++) {
                int m4 = lane >> 3;
                int n  = wn + j * 16 + ((m4 >> 1) << 3) + (lane & 7);
                int c  = ks * 2 + (m4 & 1);
                uint32_t bd = sb + ST_BHI + GS_SWZ(n, c);
                uint32_t rh[4], rl[4];
                ldsm4(rh, bd);
                ldsm4(rl, bd + (ST_BLO - ST_BHI));
                bhi[2*j][0] = rh[0]; bhi[2*j][1] = rh[1];
                bhi[2*j+1][0] = rh[2]; bhi[2*j+1][1] = rh[3];
                blo[2*j][0] = rl[0]; blo[2*j][1] = rl[1];
                blo[2*j+1][0] = rl[2]; blo[2*j+1][1] = rl[3];
            }
            #pragma unroll
            for (int mi = 0; mi < 4; mi++)
                #pragma unroll
                for (int ni = 0; ni < 4; ni++) {
                    mma_bf16(acc[mi][ni], ahi[mi], bhi[ni]);
                    mma_bf16(acc[mi][ni], alo[mi], bhi[ni]);
                    mma_bf16(acc[mi][ni], ahi[mi], blo[ni]);
                }
        }
        __syncthreads();
    }

    #pragma unroll
    for (int mi = 0; mi < 4; mi++) {
        const int row = row0 + wm + mi * 16 + (lane >> 2);
        #pragma unroll
        for (int ni = 0; ni < 4; ni++) {
            const int col = col0 + wn + ni * 8 + 2 * (lane & 3);
            *(float2*)(C + (size_t)row * N + col) =
                make_float2(acc[mi][ni][0], acc[mi][ni][1]);
            *(float2*)(C + (size_t)(row + 8) * N + col) =
                make_float2(acc[mi][ni][2], acc[mi][ni][3]);
        }
    }
}

// ---------------------------------------------------------------------------
// Split-K tensor-core retention attention.
// 640 CTAs: cid -> (bh = cid&15, c = 39-(cid>>4)) ; c -> (qt, chunk of <=8 k-tiles)
// Heavy chunks (qt=15) run first. Partial O accumulated by fp32 atomicAdd.
// ---------------------------------------------------------------------------
#define ATT2_SMEM 229376

__global__ void __launch_bounds__(256) attn_tc_kernel()
{
    extern __shared__ char smem[];
    const uint32_t SB  = smem_u32(smem);
    const uint32_t sQh = SB,           sQl = SB + 32768;
    const uint32_t sKB = SB + 65536;
    const uint32_t sVh = SB + 131072,  sVl = SB + 163840;
    const uint32_t sSh = SB + 196608,  sSl = SB + 212992;

    const int cid = blockIdx.x;
    const int bh  = cid & 15;
    const int c   = 39 - (cid >> 4);
    const unsigned char cum[17] = {0,1,2,3,4,6,8,10,12,15,18,21,24,28,32,36,40};
    int qt = 0;
    #pragma unroll
    for (int q = 1; q < 16; q++) if (c >= cum[q]) qt = q;
    const int chunk = c - cum[qt];
    const int t0 = chunk * 8;
    const int nkt = 2 * qt + 2;
    const int t1 = (t0 + 8 < nkt) ? t0 + 8 : nkt;

    const int b = bh >> 3, h = bh & 7;
    const int qb = qt * 128;
    const int tid = threadIdx.x, wid = tid >> 5, lane = tid & 31;
    const float sdec = log2f(1.0f - exp2f(-5.0f - (float)h));

    const __nv_bfloat16* Qh_g = g_Qhi + (size_t)(b * LQ + qb) * HQ + h * DQKQ;
    const __nv_bfloat16* Ql_g = g_Qlo + (size_t)(b * LQ + qb) * HQ + h * DQKQ;
    const __nv_bfloat16* Kh_g = g_Khi + (size_t)(b * LQ) * HQ + h * DQKQ;
    const __nv_bfloat16* Kl_g = g_Klo + (size_t)(b * LQ) * HQ + h * DQKQ;
    const __nv_bfloat16* Vh_g = g_Vhi + (size_t)(b * LQ) * VDIMQ + h * DVQ;
    const __nv_bfloat16* Vl_g = g_Vlo + (size_t)(b * LQ) * VDIMQ + h * DVQ;

    auto load_k = [&](uint32_t kbuf, int kb) {
        #pragma unroll
        for (int t = 0; t < 8; t++) {
            int idx = tid + t * 256;
            int hl = idx >> 10, rem = idx & 1023;
            int r = rem >> 4, cc = rem & 15;
            const __nv_bfloat16* src = (hl ? Kl_g : Kh_g) + (size_t)(kb + r) * HQ + cc * 8;
            ldgsts16(kbuf + (uint32_t)hl * 16384 + SW256(r, cc), src);
        }
    };
    auto load_v = [&](int kb) {
        #pragma unroll
        for (int t = 0; t < 16; t++) {
            int idx = tid + t * 256;
            int hl = idx >> 11, rem = idx & 2047;
            int r = rem >> 5, cc = rem & 31;
            const __nv_bfloat16* src = (hl ? Vl_g : Vh_g) + (size_t)(kb + r) * VDIMQ + cc * 8;
            ldgsts16((hl ? sVl : sVh) + SW512(r, cc), src);
        }
    };

    // Prologue: Q tile + first K/V of this chunk
    #pragma unroll
    for (int t = 0; t < 16; t++) {
        int idx = tid + t * 256;
        int hl = idx >> 11, rem = idx & 2047;
        int r = rem >> 4, cc = rem & 15;
        const __nv_bfloat16* src = (hl ? Ql_g : Qh_g) + (size_t)r * HQ + cc * 8;
        ldgsts16((hl ? sQl : sQh) + SW256(r, cc), src);
    }
    load_k(sKB + (uint32_t)(t0 & 1) * 32768, t0 * 64);
    load_v(t0 * 64);
    cp_commit();

    const int wms = (wid >> 1) * 32, wns = (wid & 1) * 32;
    const int wmo = (wid & 1) * 64,  wno = (wid >> 1) * 64;

    float oacc[4][8][4];
    #pragma unroll
    for (int mi = 0; mi < 4; mi++)
        #pragma unroll
        for (int nt = 0; nt < 8; nt++)
            #pragma unroll
            for (int e = 0; e < 4; e++) oacc[mi][nt][e] = 0.0f;

    for (int jt = t0; jt < t1; jt++) {
        const int kb = jt * 64;
        const uint32_t kh = sKB + (uint32_t)(jt & 1) * 32768;
        cp_wait<0>();
        __syncthreads();

        // ---- S = Q K^T ----
        float sacc[2][4][4];
        #pragma unroll
        for (int mi = 0; mi < 2; mi++)
            #pragma unroll
            for (int ni = 0; ni < 4; ni++)
                #pragma unroll
                for (int e = 0; e < 4; e++) sacc[mi][ni][e] = 0.0f;

        #pragma unroll
        for (int ks = 0; ks < 8; ks++) {
            uint32_t ah[2][4], al[2][4];
            #pragma unroll
            for (int mi = 0; mi < 2; mi++) {
                int r = wms + mi * 16 + (lane & 15);
                int cc = ks * 2 + (lane >> 4);
                uint32_t ad = sQh + SW256(r, cc);
                ldsm4(ah[mi], ad);
                ldsm4(al[mi], ad + 32768);
            }
            uint32_t bhf[4][2], blf[4][2];
            #pragma unroll
            for (int j = 0; j < 2; j++) {
                int m4 = lane >> 3;
                int n  = wns + j * 16 + ((m4 >> 1) << 3) + (lane & 7);
                int cc = ks * 2 + (m4 & 1);
                uint32_t bd = kh + SW256(n, cc);
                uint32_t rh[4], rl[4];
                ldsm4(rh, bd);
                ldsm4(rl, bd + 16384);
                bhf[2*j][0] = rh[0]; bhf[2*j][1] = rh[1];
                bhf[2*j+1][0] = rh[2]; bhf[2*j+1][1] = rh[3];
                blf[2*j][0] = rl[0]; blf[2*j][1] = rl[1];
                blf[2*j+1][0] = rl[2]; blf[2*j+1][1] = rl[3];
            }
            #pragma unroll
            for (int mi = 0; mi < 2; mi++)
                #pragma unroll
                for (int ni = 0; ni < 4; ni++) {
                    mma_bf16(sacc[mi][ni], ah[mi], bhf[ni]);
                    mma_bf16(sacc[mi][ni], al[mi], bhf[ni]);
                    mma_bf16(sacc[mi][ni], ah[mi], blf[ni]);
                }
        }

        if (jt + 1 < t1) load_k(sKB + (uint32_t)((jt + 1) & 1) * 32768, kb + 64);

        // ---- decay + causal + split + store S ----
        #pragma unroll
        for (int mi = 0; mi < 2; mi++) {
            int r0 = wms + mi * 16 + (lane >> 2);
            int i0 = qb + r0, i1 = i0 + 8;
            #pragma unroll
            for (int ni = 0; ni < 4; ni++) {
                int c0 = wns + ni * 8 + 2 * (lane & 3);
                int j0 = kb + c0;
                float d00 = (i0 >= j0)     ? exp2f(sdec * (float)(i0 - j0))     : 0.0f;
                float d01 = (i0 >= j0 + 1) ? exp2f(sdec * (float)(i0 - j0 - 1)) : 0.0f;
                float d10 = (i1 >= j0)     ? exp2f(sdec * (float)(i1 - j0))     : 0.0f;
                float d11 = (i1 >= j0 + 1) ? exp2f(sdec * (float)(i1 - j0 - 1)) : 0.0f;
                float v0 = sacc[mi][ni][0] * d00, v1 = sacc[mi][ni][1] * d01;
                float v2 = sacc[mi][ni][2] * d10, v3 = sacc[mi][ni][3] * d11;
                float h0 = __bfloat162float(__float2bfloat16(v0));
                float h1 = __bfloat162float(__float2bfloat16(v1));
                float h2 = __bfloat162float(__float2bfloat16(v2));
                float h3 = __bfloat162float(__float2bfloat16(v3));
                int ch = c0 >> 3;
                int off = (c0 & 7) * 2;
                sts32(sSh + SW128R(r0, ch) + off,     pack_bf2(v0, v1));
                sts32(sSl + SW128R(r0, ch) + off,     pack_bf2(v0 - h0, v1 - h1));
                sts32(sSh + SW128R(r0 + 8, ch) + off, pack_bf2(v2, v3));
                sts32(sSl + SW128R(r0 + 8, ch) + off, pack_bf2(v2 - h2, v3 - h3));
            }
        }
        __syncthreads();

        // ---- O += S V ----
        #pragma unroll
        for (int ks = 0; ks < 4; ks++) {
            uint32_t ah[4][4], al[4][4];
            #pragma unroll
            for (int mi = 0; mi < 4; mi++) {
                int r = wmo + mi * 16 + (lane & 15);
                int cc = ks * 2 + (lane >> 4);
                uint32_t ad = sSh + SW128R(r, cc);
                ldsm4(ah[mi], ad);
                ldsm4(al[mi], ad + 16384);
            }
            uint32_t bhf[8][2], blf[8][2];
            #pragma unroll
            for (int np = 0; np < 4; np++) {
                int row = ks * 16 + ((lane >> 3) & 1) * 8 + (lane & 7);
                int cn  = (wno + np * 16 + (lane >> 4) * 8) >> 3;
                uint32_t vd = sVh + SW512(row, cn);
                uint32_t rh[4], rl[4];
                ldsm4t(rh, vd);
                ldsm4t(rl, vd + 32768);
                bhf[2*np][0] = rh[0]; bhf[2*np][1] = rh[1];
                bhf[2*np+1][0] = rh[2]; bhf[2*np+1][1] = rh[3];
                blf[2*np][0] = rl[0]; blf[2*np][1] = rl[1];
                blf[2*np+1][0] = rl[2]; blf[2*np+1][1] = rl[3];
            }
            #pragma unroll
            for (int mi = 0; mi < 4; mi++)
                #pragma unroll
                for (int nt = 0; nt < 8; nt++) {
                    mma_bf16(oacc[mi][nt], ah[mi], bhf[nt]);
                    mma_bf16(oacc[mi][nt], al[mi], bhf[nt]);
                    mma_bf16(oacc[mi][nt], ah[mi], blf[nt]);
                }
        }
        __syncthreads();
        if (jt + 1 < t1) load_v(kb + 64);
        cp_commit();
    }

    // ---- accumulate partial O via atomicAdd ----
    float* Og = g_O + (size_t)(b * LQ + qb) * VDIMQ + h * DVQ;
    #pragma unroll
    for (int mi = 0; mi < 4; mi++) {
        int r = wmo + mi * 16 + (lane >> 2);
        #pragma unroll
        for (int nt = 0; nt < 8; nt++) {
            int col = wno + nt * 8 + 2 * (lane & 3);
            atomicAdd(Og + (size_t)r * VDIMQ + col,           oacc[mi][nt][0]);
            atomicAdd(Og + (size_t)r * VDIMQ + col + 1,       oacc[mi][nt][1]);
            atomicAdd(Og + (size_t)(r + 8) * VDIMQ + col,     oacc[mi][nt][2]);
            atomicAdd(Og + (size_t)(r + 8) * VDIMQ + col + 1, oacc[mi][nt][3]);
        }
    }
}

// ---------------------------------------------------------------------------
// Fused RMSNorm + swish gate + split -> bf16 hi/lo
// ---------------------------------------------------------------------------
__global__ void __launch_bounds__(256) normgate_split_kernel(const float* __restrict__ gw)
{
    const int warp = (blockIdx.x << 3) + (threadIdx.x >> 5);
    const int lane = threadIdx.x & 31;
    const size_t base = (size_t)(warp >> 3) * VDIMQ + (size_t)(warp & 7) * DVQ;
    const float* Op = g_O + base;
    const float* Gp = g_G + base;
    __nv_bfloat16* Oh = g_O_hi + base;
    __nv_bfloat16* Ol = g_O_lo + base;

    const int d0 = lane * 4;
    const int d1 = 128 + lane * 4;
    float4 o0 = *(const float4*)(Op + d0);
    float4 o1 = *(const float4*)(Op + d1);

    float ss = o0.x*o0.x + o0.y*o0.y + o0.z*o0.z + o0.w*o0.w
             + o1.x*o1.x + o1.y*o1.y + o1.z*o1.z + o1.w*o1.w;
    #pragma unroll
    for (int off = 16; off > 0; off >>= 1)
        ss += __shfl_xor_sync(0xFFFFFFFFu, ss, off);

    const float r = rsqrtf(ss * (1.0f / 256.0f) + 1e-5f);

    float4 g0 = *(const float4*)(Gp + d0);
    float4 g1 = *(const float4*)(Gp + d1);
    float4 w0 = *(const float4*)(gw + d0);
    float4 w1 = *(const float4*)(gw + d1);

    float v[8];
    v[0] = o0.x * r * w0.x * (g0.x / (1.0f + expf(-g0.x)));
    v[1] = o0.y * r * w0.y * (g0.y / (1.0f + expf(-g0.y)));
    v[2] = o0.z * r * w0.z * (g0.z / (1.0f + expf(-g0.z)));
    v[3] = o0.w * r * w0.w * (g0.w / (1.0f + expf(-g0.w)));
    v[4] = o1.x * r * w1.x * (g1.x / (1.0f + expf(-g1.x)));
    v[5] = o1.y * r * w1.y * (g1.y / (1.0f + expf(-g1.y)));
    v[6] = o1.z * r * w1.z * (g1.z / (1.0f + expf(-g1.z)));
    v[7] = o1.w * r * w1.w * (g1.w / (1.0f + expf(-g1.w)));

    __nv_bfloat16 h[8], l[8];
    #pragma unroll
    for (int i = 0; i < 8; i++) {
        h[i] = __float2bfloat16(v[i]);
        l[i] = __float2bfloat16(v[i] - __bfloat162float(h[i]));
    }
    *(__nv_bfloat162*)(Oh + d0)     = __nv_bfloat162(h[0], h[1]);
    *(__nv_bfloat162*)(Oh + d0 + 2) = __nv_bfloat162(h[2], h[3]);
    *(__nv_bfloat162*)(Oh + d1)     = __nv_bfloat162(h[4], h[5]);
    *(__nv_bfloat162*)(Oh + d1 + 2) = __nv_bfloat162(h[6], h[7]);
    *(__nv_bfloat162*)(Ol + d0)     = __nv_bfloat162(l[0], l[1]);
    *(__nv_bfloat162*)(Ol + d0 + 2) = __nv_bfloat162(l[2], l[3]);
    *(__nv_bfloat162*)(Ol + d1)     = __nv_bfloat162(l[4], l[5]);
    *(__nv_bfloat162*)(Ol + d1 + 2) = __nv_bfloat162(l[6], l[7]);
}

// ---------------------------------------------------------------------------
// kernel_launch
// ---------------------------------------------------------------------------
extern "C" void kernel_launch(void* const* d_in, const int* in_sizes, int n_in,
                              void* d_out, int out_size)
{
    const float* hs = (const float*)d_in[0];
    const float* Wq = (const float*)d_in[1];
    const float* Wk = (const float*)d_in[2];
    const float* Wv = (const float*)d_in[3];
    const float* Wg = (const float*)d_in[4];
    const float* Wo = (const float*)d_in[5];
    const float* gw = (const float*)d_in[6];
    float* out = (float*)d_out;

    float* Op;
    cudaGetSymbolAddress((void**)&Op, g_O);

    __nv_bfloat16 *hsh, *hsl;
    __nv_bfloat16 *qh, *ql, *kh, *kl, *vh, *vl, *gh, *gl, *oh, *ol;
    cudaGetSymbolAddress((void**)&hsh, g_hs_hi);
    cudaGetSymbolAddress((void**)&hsl, g_hs_lo);
    cudaGetSymbolAddress((void**)&qh, g_WqT_hi); cudaGetSymbolAddress((void**)&ql, g_WqT_lo);
    cudaGetSymbolAddress((void**)&kh, g_WkT_hi); cudaGetSymbolAddress((void**)&kl, g_WkT_lo);
    cudaGetSymbolAddress((void**)&vh, g_WvT_hi); cudaGetSymbolAddress((void**)&vl, g_WvT_lo);
    cudaGetSymbolAddress((void**)&gh, g_WgT_hi); cudaGetSymbolAddress((void**)&gl, g_WgT_lo);
    cudaGetSymbolAddress((void**)&oh, g_WoT_hi); cudaGetSymbolAddress((void**)&ol, g_WoT_lo);

    cudaFuncSetAttribute(qkvg_gemm, cudaFuncAttributeMaxDynamicSharedMemorySize, TCG_SMEM);
    cudaFuncSetAttribute(wo_gemm,   cudaFuncAttributeMaxDynamicSharedMemorySize, TCG_SMEM);
    cudaFuncSetAttribute(attn_tc_kernel, cudaFuncAttributeMaxDynamicSharedMemorySize, ATT2_SMEM);

    dim3 blk(256);

    // 1) prep: split hs + all weight transposes (one launch each)
    split_kernel<<<(MROWS*HQ/4 + 255)/256, blk>>>(hs, hsh, hsl, MROWS*HQ/4);
    TDescs ds;
    ds.d[0] = { Wq, qh, ql, HQ,    HQ,    0    };
    ds.d[1] = { Wk, kh, kl, HQ,    HQ,    1024 };
    ds.d[2] = { Wv, vh, vl, HQ,    VDIMQ, 2048 };
    ds.d[3] = { Wg, gh, gl, HQ,    VDIMQ, 4096 };
    ds.d[4] = { Wo, oh, ol, VDIMQ, HQ,    6144 };
    transpose_split_multi<<<8192, blk>>>(ds);

    // 2) mega QKVG projection (one launch, 1536 CTAs)
    qkvg_gemm<<<dim3(48, MROWS/128), blk, TCG_SMEM>>>();

    // 3) zero O accumulator, then split-K attention (640 CTAs, heavy-first)
    cudaMemsetAsync(Op, 0, (size_t)MROWS * VDIMQ * sizeof(float));
    attn_tc_kernel<<<640, blk, ATT2_SMEM>>>();

    // 4) fused RMSNorm + swish gate + split
    normgate_split_kernel<<<4096, blk>>>(gw);

    // 5) output projection
    wo_gemm<<<dim3(HQ/128, MROWS/128), blk, TCG_SMEM>>>(out);
}

// round 7
// speedup vs baseline: 3.2737x; 1.0718x over previous
#include <cuda_runtime.h>
#include <cuda_bf16.h>
#include <math.h>
#include <stdint.h>

// Problem constants
#define BQ 2
#define LQ 2048
#define HQ 1024
#define NHQ 8
#define DQKQ 128
#define DVQ 256
#define VDIMQ 2048
#define MROWS (BQ*LQ)   // 4096

#define QSCALE 0.08838834764831843f          // 128^-0.5
#define RF (-0.20762050593045852f)           // -2*log2(10000)/128

// ---------------------------------------------------------------------------
// Scratch (device globals)
// ---------------------------------------------------------------------------
__device__ float g_G[MROWS*VDIMQ];
__device__ float g_O[MROWS*VDIMQ];

__device__ __nv_bfloat16 g_hs_hi[MROWS*HQ];
__device__ __nv_bfloat16 g_hs_lo[MROWS*HQ];
__device__ __nv_bfloat16 g_O_hi[MROWS*VDIMQ];
__device__ __nv_bfloat16 g_O_lo[MROWS*VDIMQ];
__device__ __nv_bfloat16 g_Qhi[MROWS*HQ],    g_Qlo[MROWS*HQ];
__device__ __nv_bfloat16 g_Khi[MROWS*HQ],    g_Klo[MROWS*HQ];
__device__ __nv_bfloat16 g_Vhi[MROWS*VDIMQ], g_Vlo[MROWS*VDIMQ];
__device__ __nv_bfloat16 g_WqT_hi[HQ*HQ],     g_WqT_lo[HQ*HQ];
__device__ __nv_bfloat16 g_WkT_hi[HQ*HQ],     g_WkT_lo[HQ*HQ];
__device__ __nv_bfloat16 g_WvT_hi[VDIMQ*HQ],  g_WvT_lo[VDIMQ*HQ];
__device__ __nv_bfloat16 g_WgT_hi[VDIMQ*HQ],  g_WgT_lo[VDIMQ*HQ];
__device__ __nv_bfloat16 g_WoT_hi[HQ*VDIMQ],  g_WoT_lo[HQ*VDIMQ];

// ---------------------------------------------------------------------------
// PTX helpers
// ---------------------------------------------------------------------------
__device__ __forceinline__ uint32_t smem_u32(const void* p) {
    uint32_t a;
    asm("{ .reg .u64 t; cvta.to.shared.u64 t, %1; cvt.u32.u64 %0, t; }"
        : "=r"(a) : "l"(p));
    return a;
}
__device__ __forceinline__ void ldgsts16(uint32_t dst, const void* src) {
    asm volatile("cp.async.cg.shared.global [%0], [%1], 16;" :: "r"(dst), "l"(src));
}
__device__ __forceinline__ void cp_commit() {
    asm volatile("cp.async.commit_group;" ::: "memory");
}
template<int N_>
__device__ __forceinline__ void cp_wait() {
    asm volatile("cp.async.wait_group %0;" :: "n"(N_) : "memory");
}
__device__ __forceinline__ void ldsm4(uint32_t* r, uint32_t addr) {
    asm volatile("ldmatrix.sync.aligned.m8n8.x4.shared.b16 {%0,%1,%2,%3}, [%4];"
        : "=r"(r[0]), "=r"(r[1]), "=r"(r[2]), "=r"(r[3]) : "r"(addr));
}
__device__ __forceinline__ void ldsm4t(uint32_t* r, uint32_t addr) {
    asm volatile("ldmatrix.sync.aligned.m8n8.x4.trans.shared.b16 {%0,%1,%2,%3}, [%4];"
        : "=r"(r[0]), "=r"(r[1]), "=r"(r[2]), "=r"(r[3]) : "r"(addr));
}
__device__ __forceinline__ void sts32(uint32_t addr, uint32_t v) {
    asm volatile("st.shared.b32 [%0], %1;" :: "r"(addr), "r"(v) : "memory");
}
__device__ __forceinline__ void mma_bf16(float* c, const uint32_t* a, const uint32_t* b) {
    asm volatile("mma.sync.aligned.m16n8k16.row.col.f32.bf16.bf16.f32 "
        "{%0,%1,%2,%3}, {%4,%5,%6,%7}, {%8,%9}, {%0,%1,%2,%3};"
        : "+f"(c[0]), "+f"(c[1]), "+f"(c[2]), "+f"(c[3])
        : "r"(a[0]), "r"(a[1]), "r"(a[2]), "r"(a[3]), "r"(b[0]), "r"(b[1]));
}
__device__ __forceinline__ uint32_t pack_bf2(float a, float b) {
    __nv_bfloat162 t(__float2bfloat16(a), __float2bfloat16(b));
    return *(uint32_t*)&t;
}

// Swizzles: row stride in bytes; 16B chunk xor'd by (r&7)
#define SW128R(r, c) ((uint32_t)((r) * 128u + ((uint32_t)((c) ^ ((r) & 7)) << 4)))
#define SW256(r, c)  ((uint32_t)((r) * 256u + ((uint32_t)((c) ^ ((r) & 7)) << 4)))
#define SW512(r, c)  ((uint32_t)((r) * 512u + ((uint32_t)((c) ^ ((r) & 7)) << 4)))

// GEMM: K-chunk 64, tile per operand 128x64 bf16 = 16KB; stage = 64KB; 3 stages
#define GST_AHI 0
#define GST_ALO 16384
#define GST_BHI 32768
#define GST_BLO 49152
#define G_STAGE 65536
#define TCG_SMEM (3 * G_STAGE)

// ---------------------------------------------------------------------------
// hs split
// ---------------------------------------------------------------------------
__global__ void __launch_bounds__(256) split_kernel(const float* __restrict__ x,
                                                    __nv_bfloat16* __restrict__ hi,
                                                    __nv_bfloat16* __restrict__ lo,
                                                    int n4)
{
    int i = blockIdx.x * 256 + threadIdx.x;
    if (i >= n4) return;
    float4 v = ((const float4*)x)[i];
    __nv_bfloat16 h0 = __float2bfloat16(v.x), h1 = __float2bfloat16(v.y);
    __nv_bfloat16 h2 = __float2bfloat16(v.z), h3 = __float2bfloat16(v.w);
    __nv_bfloat16 l0 = __float2bfloat16(v.x - __bfloat162float(h0));
    __nv_bfloat16 l1 = __float2bfloat16(v.y - __bfloat162float(h1));
    __nv_bfloat16 l2 = __float2bfloat16(v.z - __bfloat162float(h2));
    __nv_bfloat16 l3 = __float2bfloat16(v.w - __bfloat162float(h3));
    ((__nv_bfloat162*)hi)[2*i]   = __nv_bfloat162(h0, h1);
    ((__nv_bfloat162*)hi)[2*i+1] = __nv_bfloat162(h2, h3);
    ((__nv_bfloat162*)lo)[2*i]   = __nv_bfloat162(l0, l1);
    ((__nv_bfloat162*)lo)[2*i+1] = __nv_bfloat162(l2, l3);
}

// ---------------------------------------------------------------------------
// Merged weight transpose+split (one launch for all 5 weights)
// ---------------------------------------------------------------------------
struct TDesc { const float* W; __nv_bfloat16* hi; __nv_bfloat16* lo; int K, N, start; };
struct TDescs { TDesc d[5]; };

__global__ void __launch_bounds__(256) transpose_split_multi(TDescs ds)
{
    __shared__ float s[32][33];
    int t = blockIdx.x;
    int i = 0;
    #pragma unroll
    for (int j = 1; j < 5; j++) if (t >= ds.d[j].start) i = j;
    const float* W = ds.d[i].W;
    __nv_bfloat16* Th = ds.d[i].hi;
    __nv_bfloat16* Tl = ds.d[i].lo;
    const int K = ds.d[i].K, N = ds.d[i].N;
    int lt = t - ds.d[i].start;
    int ncols = N >> 5;
    int k0 = (lt / ncols) * 32;
    int n0 = (lt % ncols) * 32;

    const int tx = threadIdx.x & 31;
    const int ty = threadIdx.x >> 5;
    #pragma unroll
    for (int q = 0; q < 4; q++)
        s[ty + 8*q][tx] = W[(size_t)(k0 + ty + 8*q) * N + n0 + tx];
    __syncthreads();
    #pragma unroll
    for (int q = 0; q < 4; q++) {
        float v = s[tx][ty + 8*q];
        int row = n0 + ty + 8*q;
        int col = k0 + tx;
        __nv_bfloat16 h = __float2bfloat16(v);
        __nv_bfloat16 l = __float2bfloat16(v - __bfloat162float(h));
        Th[(size_t)row * K + col] = h;
        Tl[(size_t)row * K + col] = l;
    }
}

// ---------------------------------------------------------------------------
// GEMM mainloop core: 128x128 tile, 8 warps (64x32 warp tiles), K-chunk 64,
// 3-stage cp.async pipeline. Returns with acc filled.
// ---------------------------------------------------------------------------
struct GemmOps {
    const __nv_bfloat16 *Ah, *Al, *Bh, *Bl;
    int K, row0, bcol0;   // bcol0 = row offset into B^T
};

__device__ __forceinline__ void gemm_mainloop(const GemmOps& op, uint32_t sbase,
                                              float acc[4][4][4])
{
    const int tid  = threadIdx.x;
    const int wid  = tid >> 5;
    const int lane = tid & 31;
    const int wm   = (wid & 1) * 64;
    const int wn   = (wid >> 1) * 32;
    const int K    = op.K;
    const int nchunks = K >> 6;

    auto load_chunk = [&](uint32_t sb, int k0) {
        #pragma unroll
        for (int t = 0; t < 4; t++) {
            int idx = tid + t * 256;     // 0..1023
            int r   = idx >> 3;          // 0..127
            int c   = idx & 7;           // 16B chunk
            uint32_t soff = SW128R(r, c);
            size_t aoff = (size_t)(op.row0 + r) * K + k0 + c * 8;
            size_t boff = (size_t)(op.bcol0 + r) * K + k0 + c * 8;
            ldgsts16(sb + GST_AHI + soff, op.Ah + aoff);
            ldgsts16(sb + GST_ALO + soff, op.Al + aoff);
            ldgsts16(sb + GST_BHI + soff, op.Bh + boff);
            ldgsts16(sb + GST_BLO + soff, op.Bl + boff);
        }
        cp_commit();
    };

    load_chunk(sbase, 0);
    if (nchunks > 1) load_chunk(sbase + G_STAGE, 64);

    uint32_t stage_of[3] = { sbase, sbase + G_STAGE, sbase + 2 * G_STAGE };

    for (int cch = 0; cch < nchunks; cch++) {
        const uint32_t sb = stage_of[cch % 3];
        if (cch + 2 < nchunks) {
            load_chunk(stage_of[(cch + 2) % 3], (cch + 2) * 64);
            cp_wait<2>();
        } else if (cch + 1 < nchunks) {
            cp_wait<1>();
        } else {
            cp_wait<0>();
        }
        __syncthreads();

        #pragma unroll
        for (int ks = 0; ks < 4; ks++) {
            uint32_t ahi[4][4], alo[4][4];
            #pragma unroll
            for (int mi = 0; mi < 4; mi++) {
                int r = wm + mi * 16 + (lane & 15);
                int c = ks * 2 + (lane >> 4);
                uint32_t ad = sb + GST_AHI + SW128R(r, c);
                ldsm4(ahi[mi], ad);
                ldsm4(alo[mi], ad + (GST_ALO - GST_AHI));
            }
            uint32_t bhi[4][2], blo[4][2];
            #pragma unroll
            for (int j = 0; j < 2; j++) {
                int m4 = lane >> 3;
                int n  = wn + j * 16 + ((m4 >> 1) << 3) + (lane & 7);
                int c  = ks * 2 + (m4 & 1);
                uint32_t bd = sb + GST_BHI + SW128R(n, c);
                uint32_t rh[4], rl[4];
                ldsm4(rh, bd);
                ldsm4(rl, bd + (GST_BLO - GST_BHI));
                bhi[2*j][0] = rh[0]; bhi[2*j][1] = rh[1];
                bhi[2*j+1][0] = rh[2]; bhi[2*j+1][1] = rh[3];
                blo[2*j][0] = rl[0]; blo[2*j][1] = rl[1];
                blo[2*j+1][0] = rl[2]; blo[2*j+1][1] = rl[3];
            }
            #pragma unroll
            for (int mi = 0; mi < 4; mi++)
                #pragma unroll
                for (int ni = 0; ni < 4; ni++) {
                    mma_bf16(acc[mi][ni], ahi[mi], bhi[ni]);
                    mma_bf16(acc[mi][ni], alo[mi], bhi[ni]);
                    mma_bf16(acc[mi][ni], ahi[mi], blo[ni]);
                }
        }
        __syncthreads();
    }
}

// ---------------------------------------------------------------------------
// Mega QKVG GEMM: grid (48, 32). cb<8: Q | cb<16: K | cb<32: V | else G
// ---------------------------------------------------------------------------
__global__ void __launch_bounds__(256) qkvg_gemm()
{
    extern __shared__ char smem[];
    const uint32_t sbase = smem_u32(smem);
    const int tid  = threadIdx.x;
    const int wid  = tid >> 5;
    const int lane = tid & 31;
    const int row0 = blockIdx.y * 128;
    const int cb   = blockIdx.x;
    const int wm   = (wid & 1) * 64;
    const int wn   = (wid >> 1) * 32;

    int mode, lcol0;
    const __nv_bfloat16 *Bh, *Bl;
    if (cb < 8)       { mode = 0; lcol0 = cb * 128;        Bh = g_WqT_hi; Bl = g_WqT_lo; }
    else if (cb < 16) { mode = 1; lcol0 = (cb - 8) * 128;  Bh = g_WkT_hi; Bl = g_WkT_lo; }
    else if (cb < 32) { mode = 2; lcol0 = (cb - 16) * 128; Bh = g_WvT_hi; Bl = g_WvT_lo; }
    else              { mode = 3; lcol0 = (cb - 32) * 128; Bh = g_WgT_hi; Bl = g_WgT_lo; }

    float acc[4][4][4];
    #pragma unroll
    for (int mi = 0; mi < 4; mi++)
        #pragma unroll
        for (int ni = 0; ni < 4; ni++)
            #pragma unroll
            for (int e = 0; e < 4; e++) acc[mi][ni][e] = 0.0f;

    GemmOps op{ g_hs_hi, g_hs_lo, Bh, Bl, HQ, row0, lcol0 };
    gemm_mainloop(op, sbase, acc);

    #pragma unroll
    for (int mi = 0; mi < 4; mi++) {
        const int row = row0 + wm + mi * 16 + (lane >> 2);
        #pragma unroll
        for (int ni = 0; ni < 4; ni++) {
            const int col = lcol0 + wn + ni * 8 + 2 * (lane & 3);
            float v0 = acc[mi][ni][0], v1 = acc[mi][ni][1];
            float v2 = acc[mi][ni][2], v3 = acc[mi][ni][3];
            if (mode <= 1) {
                if (mode == 0) { v0 *= QSCALE; v1 *= QSCALE; v2 *= QSCALE; v3 *= QSCALE; }
                const int p = (col & 127) >> 1;
                const float inv = exp2f((float)p * RF);
                float s0, c0f, s1, c1f;
                sincosf((float)(row & (LQ - 1)) * inv, &s0, &c0f);
                sincosf((float)((row + 8) & (LQ - 1)) * inv, &s1, &c1f);
                float x0 = v0, x1 = v1;
                v0 = x0 * c0f - x1 * s0;
                v1 = x1 * c0f + x0 * s0;
                x0 = v2; x1 = v3;
                v2 = x0 * c1f - x1 * s1;
                v3 = x1 * c1f + x0 * s1;
                __nv_bfloat16 h0 = __float2bfloat16(v0), h1 = __float2bfloat16(v1);
                __nv_bfloat16 h2 = __float2bfloat16(v2), h3 = __float2bfloat16(v3);
                __nv_bfloat16 l0 = __float2bfloat16(v0 - __bfloat162float(h0));
                __nv_bfloat16 l1 = __float2bfloat16(v1 - __bfloat162float(h1));
                __nv_bfloat16 l2 = __float2bfloat16(v2 - __bfloat162float(h2));
                __nv_bfloat16 l3 = __float2bfloat16(v3 - __bfloat162float(h3));
                __nv_bfloat16* Chi = (mode == 0) ? g_Qhi : g_Khi;
                __nv_bfloat16* Clo = (mode == 0) ? g_Qlo : g_Klo;
                *(__nv_bfloat162*)(Chi + (size_t)row * HQ + col)       = __nv_bfloat162(h0, h1);
                *(__nv_bfloat162*)(Chi + (size_t)(row + 8) * HQ + col) = __nv_bfloat162(h2, h3);
                *(__nv_bfloat162*)(Clo + (size_t)row * HQ + col)       = __nv_bfloat162(l0, l1);
                *(__nv_bfloat162*)(Clo + (size_t)(row + 8) * HQ + col) = __nv_bfloat162(l2, l3);
            } else if (mode == 2) {
                __nv_bfloat16 h0 = __float2bfloat16(v0), h1 = __float2bfloat16(v1);
                __nv_bfloat16 h2 = __float2bfloat16(v2), h3 = __float2bfloat16(v3);
                __nv_bfloat16 l0 = __float2bfloat16(v0 - __bfloat162float(h0));
                __nv_bfloat16 l1 = __float2bfloat16(v1 - __bfloat162float(h1));
                __nv_bfloat16 l2 = __float2bfloat16(v2 - __bfloat162float(h2));
                __nv_bfloat16 l3 = __float2bfloat16(v3 - __bfloat162float(h3));
                *(__nv_bfloat162*)(g_Vhi + (size_t)row * VDIMQ + col)       = __nv_bfloat162(h0, h1);
                *(__nv_bfloat162*)(g_Vhi + (size_t)(row + 8) * VDIMQ + col) = __nv_bfloat162(h2, h3);
                *(__nv_bfloat162*)(g_Vlo + (size_t)row * VDIMQ + col)       = __nv_bfloat162(l0, l1);
                *(__nv_bfloat162*)(g_Vlo + (size_t)(row + 8) * VDIMQ + col) = __nv_bfloat162(l2, l3);
            } else {
                *(float2*)(g_G + (size_t)row * VDIMQ + col)       = make_float2(v0, v1);
                *(float2*)(g_G + (size_t)(row + 8) * VDIMQ + col) = make_float2(v2, v3);
            }
        }
    }
}

// ---------------------------------------------------------------------------
// Wo GEMM: fp32 out. K=2048, N=1024.
// ---------------------------------------------------------------------------
__global__ void __launch_bounds__(256) wo_gemm(float* __restrict__ C)
{
    extern __shared__ char smem[];
    const uint32_t sbase = smem_u32(smem);
    const int tid  = threadIdx.x;
    const int wid  = tid >> 5;
    const int lane = tid & 31;
    const int row0 = blockIdx.y * 128;
    const int col0 = blockIdx.x * 128;
    const int wm   = (wid & 1) * 64;
    const int wn   = (wid >> 1) * 32;

    float acc[4][4][4];
    #pragma unroll
    for (int mi = 0; mi < 4; mi++)
        #pragma unroll
        for (int ni = 0; ni < 4; ni++)
            #pragma unroll
            for (int e = 0; e < 4; e++) acc[mi][ni][e] = 0.0f;

    GemmOps op{ g_O_hi, g_O_lo, g_WoT_hi, g_WoT_lo, VDIMQ, row0, col0 };
    gemm_mainloop(op, sbase, acc);

    #pragma unroll
    for (int mi = 0; mi < 4; mi++) {
        const int row = row0 + wm + mi * 16 + (lane >> 2);
        #pragma unroll
        for (int ni = 0; ni < 4; ni++) {
            const int col = col0 + wn + ni * 8 + 2 * (lane & 3);
            *(float2*)(C + (size_t)row * HQ + col) =
                make_float2(acc[mi][ni][0], acc[mi][ni][1]);
            *(float2*)(C + (size_t)(row + 8) * HQ + col) =
                make_float2(acc[mi][ni][2], acc[mi][ni][3]);
        }
    }
}

// ---------------------------------------------------------------------------
// Split-K tensor-core retention attention, 512 threads (16 warps).
// 640 CTAs: cid -> (bh = cid&15, c = 39-(cid>>4)); heavy chunks first.
// S warp tile 16x32 (8x2 warp grid), O warp tile 32x64 (4x4 warp grid).
// ---------------------------------------------------------------------------
#define ATT2_SMEM 229376

__global__ void __launch_bounds__(512) attn_tc_kernel()
{
    extern __shared__ char smem[];
    const uint32_t SB  = smem_u32(smem);
    const uint32_t sQh = SB,           sQl = SB + 32768;
    const uint32_t sKB = SB + 65536;
    const uint32_t sVh = SB + 131072,  sVl = SB + 163840;
    const uint32_t sSh = SB + 196608,  sSl = SB + 212992;

    const int cid = blockIdx.x;
    const int bh  = cid & 15;
    const int c   = 39 - (cid >> 4);
    const unsigned char cum[17] = {0,1,2,3,4,6,8,10,12,15,18,21,24,28,32,36,40};
    int qt = 0;
    #pragma unroll
    for (int q = 1; q < 16; q++) if (c >= cum[q]) qt = q;
    const int chunk = c - cum[qt];
    const int t0 = chunk * 8;
    const int nkt = 2 * qt + 2;
    const int t1 = (t0 + 8 < nkt) ? t0 + 8 : nkt;

    const int b = bh >> 3, h = bh & 7;
    const int qb = qt * 128;
    const int tid = threadIdx.x, wid = tid >> 5, lane = tid & 31;
    const float sdec = log2f(1.0f - exp2f(-5.0f - (float)h));

    const __nv_bfloat16* Qh_g = g_Qhi + (size_t)(b * LQ + qb) * HQ + h * DQKQ;
    const __nv_bfloat16* Ql_g = g_Qlo + (size_t)(b * LQ + qb) * HQ + h * DQKQ;
    const __nv_bfloat16* Kh_g = g_Khi + (size_t)(b * LQ) * HQ + h * DQKQ;
    const __nv_bfloat16* Kl_g = g_Klo + (size_t)(b * LQ) * HQ + h * DQKQ;
    const __nv_bfloat16* Vh_g = g_Vhi + (size_t)(b * LQ) * VDIMQ + h * DVQ;
    const __nv_bfloat16* Vl_g = g_Vlo + (size_t)(b * LQ) * VDIMQ + h * DVQ;

    auto load_k = [&](uint32_t kbuf, int kb) {
        #pragma unroll
        for (int t = 0; t < 4; t++) {
            int idx = tid + t * 512;
            int hl = idx >> 10, rem = idx & 1023;
            int r = rem >> 4, cc = rem & 15;
            const __nv_bfloat16* src = (hl ? Kl_g : Kh_g) + (size_t)(kb + r) * HQ + cc * 8;
            ldgsts16(kbuf + (uint32_t)hl * 16384 + SW256(r, cc), src);
        }
    };
    auto load_v = [&](int kb) {
        #pragma unroll
        for (int t = 0; t < 8; t++) {
            int idx = tid + t * 512;
            int hl = idx >> 11, rem = idx & 2047;
            int r = rem >> 5, cc = rem & 31;
            const __nv_bfloat16* src = (hl ? Vl_g : Vh_g) + (size_t)(kb + r) * VDIMQ + cc * 8;
            ldgsts16((hl ? sVl : sVh) + SW512(r, cc), src);
        }
    };

    // Prologue: Q tile + first K/V
    #pragma unroll
    for (int t = 0; t < 8; t++) {
        int idx = tid + t * 512;
        int hl = idx >> 11, rem = idx & 2047;
        int r = rem >> 4, cc = rem & 15;
        const __nv_bfloat16* src = (hl ? Ql_g : Qh_g) + (size_t)r * HQ + cc * 8;
        ldgsts16((hl ? sQl : sQh) + SW256(r, cc), src);
    }
    load_k(sKB + (uint32_t)(t0 & 1) * 32768, t0 * 64);
    load_v(t0 * 64);
    cp_commit();

    const int wms = (wid >> 1) * 16, wns = (wid & 1) * 32;   // S: 16x32
    const int wmo = (wid & 3) * 32,  wno = (wid >> 2) * 64;  // O: 32x64

    float oacc[2][8][4];
    #pragma unroll
    for (int mi = 0; mi < 2; mi++)
        #pragma unroll
        for (int nt = 0; nt < 8; nt++)
            #pragma unroll
            for (int e = 0; e < 4; e++) oacc[mi][nt][e] = 0.0f;

    for (int jt = t0; jt < t1; jt++) {
        const int kb = jt * 64;
        const uint32_t kh = sKB + (uint32_t)(jt & 1) * 32768;
        cp_wait<0>();
        __syncthreads();

        // ---- S = Q K^T (128x64) ----
        float sacc[4][4];
        #pragma unroll
        for (int ni = 0; ni < 4; ni++)
            #pragma unroll
            for (int e = 0; e < 4; e++) sacc[ni][e] = 0.0f;

        #pragma unroll
        for (int ks = 0; ks < 8; ks++) {
            uint32_t ah[4], al[4];
            {
                int r = wms + (lane & 15);
                int cc = ks * 2 + (lane >> 4);
                uint32_t ad = sQh + SW256(r, cc);
                ldsm4(ah, ad);
                ldsm4(al, ad + 32768);
            }
            uint32_t bhf[4][2], blf[4][2];
            #pragma unroll
            for (int j = 0; j < 2; j++) {
                int m4 = lane >> 3;
                int n  = wns + j * 16 + ((m4 >> 1) << 3) + (lane & 7);
                int cc = ks * 2 + (m4 & 1);
                uint32_t bd = kh + SW256(n, cc);
                uint32_t rh[4], rl[4];
                ldsm4(rh, bd);
                ldsm4(rl, bd + 16384);
                bhf[2*j][0] = rh[0]; bhf[2*j][1] = rh[1];
                bhf[2*j+1][0] = rh[2]; bhf[2*j+1][1] = rh[3];
                blf[2*j][0] = rl[0]; blf[2*j][1] = rl[1];
                blf[2*j+1][0] = rl[2]; blf[2*j+1][1] = rl[3];
            }
            #pragma unroll
            for (int ni = 0; ni < 4; ni++) {
                mma_bf16(sacc[ni], ah, bhf[ni]);
                mma_bf16(sacc[ni], al, bhf[ni]);
                mma_bf16(sacc[ni], ah, blf[ni]);
            }
        }

        if (jt + 1 < t1) load_k(sKB + (uint32_t)((jt + 1) & 1) * 32768, kb + 64);

        // ---- decay + causal + split + store S ----
        {
            int r0 = wms + (lane >> 2);
            int i0 = qb + r0, i1 = i0 + 8;
            #pragma unroll
            for (int ni = 0; ni < 4; ni++) {
                int c0 = wns + ni * 8 + 2 * (lane & 3);
                int j0 = kb + c0;
                float d00 = (i0 >= j0)     ? exp2f(sdec * (float)(i0 - j0))     : 0.0f;
                float d01 = (i0 >= j0 + 1) ? exp2f(sdec * (float)(i0 - j0 - 1)) : 0.0f;
                float d10 = (i1 >= j0)     ? exp2f(sdec * (float)(i1 - j0))     : 0.0f;
                float d11 = (i1 >= j0 + 1) ? exp2f(sdec * (float)(i1 - j0 - 1)) : 0.0f;
                float v0 = sacc[ni][0] * d00, v1 = sacc[ni][1] * d01;
                float v2 = sacc[ni][2] * d10, v3 = sacc[ni][3] * d11;
                float h0 = __bfloat162float(__float2bfloat16(v0));
                float h1 = __bfloat162float(__float2bfloat16(v1));
                float h2 = __bfloat162float(__float2bfloat16(v2));
                float h3 = __bfloat162float(__float2bfloat16(v3));
                int ch = c0 >> 3;
                int off = (c0 & 7) * 2;
                sts32(sSh + SW128R(r0, ch) + off,     pack_bf2(v0, v1));
                sts32(sSl + SW128R(r0, ch) + off,     pack_bf2(v0 - h0, v1 - h1));
                sts32(sSh + SW128R(r0 + 8, ch) + off, pack_bf2(v2, v3));
                sts32(sSl + SW128R(r0 + 8, ch) + off, pack_bf2(v2 - h2, v3 - h3));
            }
        }
        __syncthreads();

        // ---- O += S V (128x256) ----
        #pragma unroll
        for (int ks = 0; ks < 4; ks++) {
            uint32_t ah[2][4], al[2][4];
            #pragma unroll
            for (int mi = 0; mi < 2; mi++) {
                int r = wmo + mi * 16 + (lane & 15);
                int cc = ks * 2 + (lane >> 4);
                uint32_t ad = sSh + SW128R(r, cc);
                ldsm4(ah[mi], ad);
                ldsm4(al[mi], ad + 16384);
            }
            uint32_t bhf[8][2], blf[8][2];
            #pragma unroll
            for (int np = 0; np < 4; np++) {
                int row = ks * 16 + ((lane >> 3) & 1) * 8 + (lane & 7);
                int cn  = (wno + np * 16 + (lane >> 4) * 8) >> 3;
                uint32_t vd = sVh + SW512(row, cn);
                uint32_t rh[4], rl[4];
                ldsm4t(rh, vd);
                ldsm4t(rl, vd + 32768);
                bhf[2*np][0] = rh[0]; bhf[2*np][1] = rh[1];
                bhf[2*np+1][0] = rh[2]; bhf[2*np+1][1] = rh[3];
                blf[2*np][0] = rl[0]; blf[2*np][1] = rl[1];
                blf[2*np+1][0] = rl[2]; blf[2*np+1][1] = rl[3];
            }
            #pragma unroll
            for (int mi = 0; mi < 2; mi++)
                #pragma unroll
                for (int nt = 0; nt < 8; nt++) {
                    mma_bf16(oacc[mi][nt], ah[mi], bhf[nt]);
                    mma_bf16(oacc[mi][nt], al[mi], bhf[nt]);
                    mma_bf16(oacc[mi][nt], ah[mi], blf[nt]);
                }
        }
        __syncthreads();
        if (jt + 1 < t1) load_v(kb + 64);
        cp_commit();
    }

    // ---- accumulate partial O via atomicAdd ----
    float* Og = g_O + (size_t)(b * LQ + qb) * VDIMQ + h * DVQ;
    #pragma unroll
    for (int mi = 0; mi < 2; mi++) {
        int r = wmo + mi * 16 + (lane >> 2);
        #pragma unroll
        for (int nt = 0; nt < 8; nt++) {
            int col = wno + nt * 8 + 2 * (lane & 3);
            atomicAdd(Og + (size_t)r * VDIMQ + col,           oacc[mi][nt][0]);
            atomicAdd(Og + (size_t)r * VDIMQ + col + 1,       oacc[mi][nt][1]);
            atomicAdd(Og + (size_t)(r + 8) * VDIMQ + col,     oacc[mi][nt][2]);
            atomicAdd(Og + (size_t)(r + 8) * VDIMQ + col + 1, oacc[mi][nt][3]);
        }
    }
}

// ---------------------------------------------------------------------------
// Fused RMSNorm + swish gate + split -> bf16 hi/lo
// ---------------------------------------------------------------------------
__global__ void __launch_bounds__(256) normgate_split_kernel(const float* __restrict__ gw)
{
    const int warp = (blockIdx.x << 3) + (threadIdx.x >> 5);
    const int lane = threadIdx.x & 31;
    const size_t base = (size_t)(warp >> 3) * VDIMQ + (size_t)(warp & 7) * DVQ;
    const float* Op = g_O + base;
    const float* Gp = g_G + base;
    __nv_bfloat16* Oh = g_O_hi + base;
    __nv_bfloat16* Ol = g_O_lo + base;

    const int d0 = lane * 4;
    const int d1 = 128 + lane * 4;
    float4 o0 = *(const float4*)(Op + d0);
    float4 o1 = *(const float4*)(Op + d1);

    float ss = o0.x*o0.x + o0.y*o0.y + o0.z*o0.z + o0.w*o0.w
             + o1.x*o1.x + o1.y*o1.y + o1.z*o1.z + o1.w*o1.w;
    #pragma unroll
    for (int off = 16; off > 0; off >>= 1)
        ss += __shfl_xor_sync(0xFFFFFFFFu, ss, off);

    const float r = rsqrtf(ss * (1.0f / 256.0f) + 1e-5f);

    float4 g0 = *(const float4*)(Gp + d0);
    float4 g1 = *(const float4*)(Gp + d1);
    float4 w0 = *(const float4*)(gw + d0);
    float4 w1 = *(const float4*)(gw + d1);

    float v[8];
    v[0] = o0.x * r * w0.x * (g0.x / (1.0f + expf(-g0.x)));
    v[1] = o0.y * r * w0.y * (g0.y / (1.0f + expf(-g0.y)));
    v[2] = o0.z * r * w0.z * (g0.z / (1.0f + expf(-g0.z)));
    v[3] = o0.w * r * w0.w * (g0.w / (1.0f + expf(-g0.w)));
    v[4] = o1.x * r * w1.x * (g1.x / (1.0f + expf(-g1.x)));
    v[5] = o1.y * r * w1.y * (g1.y / (1.0f + expf(-g1.y)));
    v[6] = o1.z * r * w1.z * (g1.z / (1.0f + expf(-g1.z)));
    v[7] = o1.w * r * w1.w * (g1.w / (1.0f + expf(-g1.w)));

    __nv_bfloat16 h[8], l[8];
    #pragma unroll
    for (int i = 0; i < 8; i++) {
        h[i] = __float2bfloat16(v[i]);
        l[i] = __float2bfloat16(v[i] - __bfloat162float(h[i]));
    }
    *(__nv_bfloat162*)(Oh + d0)     = __nv_bfloat162(h[0], h[1]);
    *(__nv_bfloat162*)(Oh + d0 + 2) = __nv_bfloat162(h[2], h[3]);
    *(__nv_bfloat162*)(Oh + d1)     = __nv_bfloat162(h[4], h[5]);
    *(__nv_bfloat162*)(Oh + d1 + 2) = __nv_bfloat162(h[6], h[7]);
    *(__nv_bfloat162*)(Ol + d0)     = __nv_bfloat162(l[0], l[1]);
    *(__nv_bfloat162*)(Ol + d0 + 2) = __nv_bfloat162(l[2], l[3]);
    *(__nv_bfloat162*)(Ol + d1)     = __nv_bfloat162(l[4], l[5]);
    *(__nv_bfloat162*)(Ol + d1 + 2) = __nv_bfloat162(l[6], l[7]);
}

// ---------------------------------------------------------------------------
// kernel_launch
// ---------------------------------------------------------------------------
extern "C" void kernel_launch(void* const* d_in, const int* in_sizes, int n_in,
                              void* d_out, int out_size)
{
    const float* hs = (const float*)d_in[0];
    const float* Wq = (const float*)d_in[1];
    const float* Wk = (const float*)d_in[2];
    const float* Wv = (const float*)d_in[3];
    const float* Wg = (const float*)d_in[4];
    const float* Wo = (const float*)d_in[5];
    const float* gw = (const float*)d_in[6];
    float* out = (float*)d_out;

    float* Op;
    cudaGetSymbolAddress((void**)&Op, g_O);

    __nv_bfloat16 *hsh, *hsl;
    __nv_bfloat16 *qh, *ql, *kh, *kl, *vh, *vl, *gh, *gl, *oh, *ol;
    cudaGetSymbolAddress((void**)&hsh, g_hs_hi);
    cudaGetSymbolAddress((void**)&hsl, g_hs_lo);
    cudaGetSymbolAddress((void**)&qh, g_WqT_hi); cudaGetSymbolAddress((void**)&ql, g_WqT_lo);
    cudaGetSymbolAddress((void**)&kh, g_WkT_hi); cudaGetSymbolAddress((void**)&kl, g_WkT_lo);
    cudaGetSymbolAddress((void**)&vh, g_WvT_hi); cudaGetSymbolAddress((void**)&vl, g_WvT_lo);
    cudaGetSymbolAddress((void**)&gh, g_WgT_hi); cudaGetSymbolAddress((void**)&gl, g_WgT_lo);
    cudaGetSymbolAddress((void**)&oh, g_WoT_hi); cudaGetSymbolAddress((void**)&ol, g_WoT_lo);

    cudaFuncSetAttribute(qkvg_gemm, cudaFuncAttributeMaxDynamicSharedMemorySize, TCG_SMEM);
    cudaFuncSetAttribute(wo_gemm,   cudaFuncAttributeMaxDynamicSharedMemorySize, TCG_SMEM);
    cudaFuncSetAttribute(attn_tc_kernel, cudaFuncAttributeMaxDynamicSharedMemorySize, ATT2_SMEM);

    dim3 blk(256);

    // 1) prep
    split_kernel<<<(MROWS*HQ/4 + 255)/256, blk>>>(hs, hsh, hsl, MROWS*HQ/4);
    TDescs ds;
    ds.d[0] = { Wq, qh, ql, HQ,    HQ,    0    };
    ds.d[1] = { Wk, kh, kl, HQ,    HQ,    1024 };
    ds.d[2] = { Wv, vh, vl, HQ,    VDIMQ, 2048 };
    ds.d[3] = { Wg, gh, gl, HQ,    VDIMQ, 4096 };
    ds.d[4] = { Wo, oh, ol, VDIMQ, HQ,    6144 };
    transpose_split_multi<<<8192, blk>>>(ds);

    // 2) mega QKVG projection
    qkvg_gemm<<<dim3(48, MROWS/128), blk, TCG_SMEM>>>();

    // 3) zero O accumulator + split-K attention (512 threads, heavy-first)
    cudaMemsetAsync(Op, 0, (size_t)MROWS * VDIMQ * sizeof(float));
    attn_tc_kernel<<<640, 512, ATT2_SMEM>>>();

    // 4) fused RMSNorm + swish gate + split
    normgate_split_kernel<<<4096, blk>>>(gw);

    // 5) output projection
    wo_gemm<<<dim3(HQ/128, MROWS/128), blk, TCG_SMEM>>>(out);
}

// round 8
// speedup vs baseline: 4.5627x; 1.3938x over previous
#include <cuda_runtime.h>
#include <cuda_fp16.h>
#include <math.h>
#include <stdint.h>

// Problem constants
#define BQ 2
#define LQ 2048
#define HQ 1024
#define NHQ 8
#define DQKQ 128
#define DVQ 256
#define VDIMQ 2048
#define MROWS (BQ*LQ)   // 4096

#define QSCALE 0.08838834764831843f          // 128^-0.5
#define RF (-0.20762050593045852f)           // -2*log2(10000)/128

// ---------------------------------------------------------------------------
// Scratch (device globals). A-side operands: fp16 hi/lo. B-side: fp16 hi only.
// ---------------------------------------------------------------------------
__device__ float g_G[MROWS*VDIMQ];
__device__ float g_O[MROWS*VDIMQ];

__device__ __half g_hs_hi[MROWS*HQ],  g_hs_lo[MROWS*HQ];
__device__ __half g_O_hi[MROWS*VDIMQ], g_O_lo[MROWS*VDIMQ];
__device__ __half g_Qhi[MROWS*HQ],    g_Qlo[MROWS*HQ];
__device__ __half g_Khi[MROWS*HQ];
__device__ __half g_Vhi[MROWS*VDIMQ];
__device__ __half g_WqT[HQ*HQ];
__device__ __half g_WkT[HQ*HQ];
__device__ __half g_WvT[VDIMQ*HQ];
__device__ __half g_WgT[VDIMQ*HQ];
__device__ __half g_WoT[HQ*VDIMQ];

// ---------------------------------------------------------------------------
// PTX helpers
// ---------------------------------------------------------------------------
__device__ __forceinline__ uint32_t smem_u32(const void* p) {
    uint32_t a;
    asm("{ .reg .u64 t; cvta.to.shared.u64 t, %1; cvt.u32.u64 %0, t; }"
        : "=r"(a) : "l"(p));
    return a;
}
__device__ __forceinline__ void ldgsts16(uint32_t dst, const void* src) {
    asm volatile("cp.async.cg.shared.global [%0], [%1], 16;" :: "r"(dst), "l"(src));
}
__device__ __forceinline__ void cp_commit() {
    asm volatile("cp.async.commit_group;" ::: "memory");
}
template<int N_>
__device__ __forceinline__ void cp_wait() {
    asm volatile("cp.async.wait_group %0;" :: "n"(N_) : "memory");
}
__device__ __forceinline__ void ldsm4(uint32_t* r, uint32_t addr) {
    asm volatile("ldmatrix.sync.aligned.m8n8.x4.shared.b16 {%0,%1,%2,%3}, [%4];"
        : "=r"(r[0]), "=r"(r[1]), "=r"(r[2]), "=r"(r[3]) : "r"(addr));
}
__device__ __forceinline__ void ldsm4t(uint32_t* r, uint32_t addr) {
    asm volatile("ldmatrix.sync.aligned.m8n8.x4.trans.shared.b16 {%0,%1,%2,%3}, [%4];"
        : "=r"(r[0]), "=r"(r[1]), "=r"(r[2]), "=r"(r[3]) : "r"(addr));
}
__device__ __forceinline__ void sts32(uint32_t addr, uint32_t v) {
    asm volatile("st.shared.b32 [%0], %1;" :: "r"(addr), "r"(v) : "memory");
}
__device__ __forceinline__ void mma_fp16(float* c, const uint32_t* a, const uint32_t* b) {
    asm volatile("mma.sync.aligned.m16n8k16.row.col.f32.f16.f16.f32 "
        "{%0,%1,%2,%3}, {%4,%5,%6,%7}, {%8,%9}, {%0,%1,%2,%3};"
        : "+f"(c[0]), "+f"(c[1]), "+f"(c[2]), "+f"(c[3])
        : "r"(a[0]), "r"(a[1]), "r"(a[2]), "r"(a[3]), "r"(b[0]), "r"(b[1]));
}
__device__ __forceinline__ uint32_t pack_h2(float a, float b) {
    __half2 t = __floats2half2_rn(a, b);
    return *(uint32_t*)&t;
}

// Swizzles: row stride in bytes; 16B chunk xor'd by (r&7)
#define SW128R(r, c) ((uint32_t)((r) * 128u + ((uint32_t)((c) ^ ((r) & 7)) << 4)))
#define SW256(r, c)  ((uint32_t)((r) * 256u + ((uint32_t)((c) ^ ((r) & 7)) << 4)))
#define SW512(r, c)  ((uint32_t)((r) * 512u + ((uint32_t)((c) ^ ((r) & 7)) << 4)))

// GEMM: K-chunk 64; tiles Ahi|Alo|Bhi of 128x64 fp16 = 16KB each; 3 stages
#define GST_AHI 0
#define GST_ALO 16384
#define GST_BHI 32768
#define G_STAGE 49152
#define TCG_SMEM (3 * G_STAGE)

// ---------------------------------------------------------------------------
// hs split -> fp16 hi/lo
// ---------------------------------------------------------------------------
__global__ void __launch_bounds__(256) split_kernel(const float* __restrict__ x,
                                                    __half* __restrict__ hi,
                                                    __half* __restrict__ lo,
                                                    int n4)
{
    int i = blockIdx.x * 256 + threadIdx.x;
    if (i >= n4) return;
    float4 v = ((const float4*)x)[i];
    __half h0 = __float2half(v.x), h1 = __float2half(v.y);
    __half h2 = __float2half(v.z), h3 = __float2half(v.w);
    __half l0 = __float2half(v.x - __half2float(h0));
    __half l1 = __float2half(v.y - __half2float(h1));
    __half l2 = __float2half(v.z - __half2float(h2));
    __half l3 = __float2half(v.w - __half2float(h3));
    ((__half2*)hi)[2*i]   = __half2(h0, h1);
    ((__half2*)hi)[2*i+1] = __half2(h2, h3);
    ((__half2*)lo)[2*i]   = __half2(l0, l1);
    ((__half2*)lo)[2*i+1] = __half2(l2, l3);
}

// ---------------------------------------------------------------------------
// Merged weight transpose (fp16 hi only): one launch for all 5 weights.
// ---------------------------------------------------------------------------
struct TDesc { const float* W; __half* hi; int K, N, start; };
struct TDescs { TDesc d[5]; };

__global__ void __launch_bounds__(256) transpose_multi(TDescs ds)
{
    __shared__ float s[32][33];
    int t = blockIdx.x;
    int i = 0;
    #pragma unroll
    for (int j = 1; j < 5; j++) if (t >= ds.d[j].start) i = j;
    const float* W = ds.d[i].W;
    __half* Th = ds.d[i].hi;
    const int K = ds.d[i].K, N = ds.d[i].N;
    int lt = t - ds.d[i].start;
    int ncols = N >> 5;
    int k0 = (lt / ncols) * 32;
    int n0 = (lt % ncols) * 32;

    const int tx = threadIdx.x & 31;
    const int ty = threadIdx.x >> 5;
    #pragma unroll
    for (int q = 0; q < 4; q++)
        s[ty + 8*q][tx] = W[(size_t)(k0 + ty + 8*q) * N + n0 + tx];
    __syncthreads();
    #pragma unroll
    for (int q = 0; q < 4; q++) {
        float v = s[tx][ty + 8*q];
        Th[(size_t)(n0 + ty + 8*q) * K + k0 + tx] = __float2half(v);
    }
}

// ---------------------------------------------------------------------------
// GEMM mainloop: 128x128 tile, 8 warps (64x32), K-chunk 64, 3-stage pipeline.
// 2-term fp16: A hi/lo, B hi.
// ---------------------------------------------------------------------------
struct GemmOps {
    const __half *Ah, *Al, *Bh;
    int K, row0, bcol0;
};

__device__ __forceinline__ void gemm_mainloop(const GemmOps& op, uint32_t sbase,
                                              float acc[4][4][4])
{
    const int tid  = threadIdx.x;
    const int wid  = tid >> 5;
    const int lane = tid & 31;
    const int wm   = (wid & 1) * 64;
    const int wn   = (wid >> 1) * 32;
    const int K    = op.K;
    const int nchunks = K >> 6;

    auto load_chunk = [&](uint32_t sb, int k0) {
        #pragma unroll
        for (int t = 0; t < 4; t++) {
            int idx = tid + t * 256;     // 0..1023
            int r   = idx >> 3;
            int c   = idx & 7;
            uint32_t soff = SW128R(r, c);
            size_t aoff = (size_t)(op.row0 + r) * K + k0 + c * 8;
            size_t boff = (size_t)(op.bcol0 + r) * K + k0 + c * 8;
            ldgsts16(sb + GST_AHI + soff, op.Ah + aoff);
            ldgsts16(sb + GST_ALO + soff, op.Al + aoff);
            ldgsts16(sb + GST_BHI + soff, op.Bh + boff);
        }
        cp_commit();
    };

    load_chunk(sbase, 0);
    if (nchunks > 1) load_chunk(sbase + G_STAGE, 64);

    uint32_t stage_of[3] = { sbase, sbase + G_STAGE, sbase + 2 * G_STAGE };

    for (int cch = 0; cch < nchunks; cch++) {
        const uint32_t sb = stage_of[cch % 3];
        if (cch + 2 < nchunks) {
            load_chunk(stage_of[(cch + 2) % 3], (cch + 2) * 64);
            cp_wait<2>();
        } else if (cch + 1 < nchunks) {
            cp_wait<1>();
        } else {
            cp_wait<0>();
        }
        __syncthreads();

        #pragma unroll
        for (int ks = 0; ks < 4; ks++) {
            uint32_t ahi[4][4], alo[4][4];
            #pragma unroll
            for (int mi = 0; mi < 4; mi++) {
                int r = wm + mi * 16 + (lane & 15);
                int c = ks * 2 + (lane >> 4);
                uint32_t ad = sb + GST_AHI + SW128R(r, c);
                ldsm4(ahi[mi], ad);
                ldsm4(alo[mi], ad + (GST_ALO - GST_AHI));
            }
            uint32_t bhi[4][2];
            #pragma unroll
            for (int j = 0; j < 2; j++) {
                int m4 = lane >> 3;
                int n  = wn + j * 16 + ((m4 >> 1) << 3) + (lane & 7);
                int c  = ks * 2 + (m4 & 1);
                uint32_t rh[4];
                ldsm4(rh, sb + GST_BHI + SW128R(n, c));
                bhi[2*j][0] = rh[0]; bhi[2*j][1] = rh[1];
                bhi[2*j+1][0] = rh[2]; bhi[2*j+1][1] = rh[3];
            }
            #pragma unroll
            for (int mi = 0; mi < 4; mi++)
                #pragma unroll
                for (int ni = 0; ni < 4; ni++) {
                    mma_fp16(acc[mi][ni], ahi[mi], bhi[ni]);
                    mma_fp16(acc[mi][ni], alo[mi], bhi[ni]);
                }
        }
        __syncthreads();
    }
}

// ---------------------------------------------------------------------------
// Mega QKVG GEMM: grid (48, 32). cb<8: Q | cb<16: K | cb<32: V | else G
// ---------------------------------------------------------------------------
__global__ void __launch_bounds__(256) qkvg_gemm()
{
    extern __shared__ char smem[];
    const uint32_t sbase = smem_u32(smem);
    const int tid  = threadIdx.x;
    const int wid  = tid >> 5;
    const int lane = tid & 31;
    const int row0 = blockIdx.y * 128;
    const int cb   = blockIdx.x;
    const int wm   = (wid & 1) * 64;
    const int wn   = (wid >> 1) * 32;

    int mode, lcol0;
    const __half* Bh;
    if (cb < 8)       { mode = 0; lcol0 = cb * 128;        Bh = g_WqT; }
    else if (cb < 16) { mode = 1; lcol0 = (cb - 8) * 128;  Bh = g_WkT; }
    else if (cb < 32) { mode = 2; lcol0 = (cb - 16) * 128; Bh = g_WvT; }
    else              { mode = 3; lcol0 = (cb - 32) * 128; Bh = g_WgT; }

    float acc[4][4][4];
    #pragma unroll
    for (int mi = 0; mi < 4; mi++)
        #pragma unroll
        for (int ni = 0; ni < 4; ni++)
            #pragma unroll
            for (int e = 0; e < 4; e++) acc[mi][ni][e] = 0.0f;

    GemmOps op{ g_hs_hi, g_hs_lo, Bh, HQ, row0, lcol0 };
    gemm_mainloop(op, sbase, acc);

    #pragma unroll
    for (int mi = 0; mi < 4; mi++) {
        const int row = row0 + wm + mi * 16 + (lane >> 2);
        #pragma unroll
        for (int ni = 0; ni < 4; ni++) {
            const int col = lcol0 + wn + ni * 8 + 2 * (lane & 3);
            float v0 = acc[mi][ni][0], v1 = acc[mi][ni][1];
            float v2 = acc[mi][ni][2], v3 = acc[mi][ni][3];
            if (mode <= 1) {   // Q or K: scale + RoPE
                if (mode == 0) { v0 *= QSCALE; v1 *= QSCALE; v2 *= QSCALE; v3 *= QSCALE; }
                const int p = (col & 127) >> 1;
                const float inv = exp2f((float)p * RF);
                float s0, c0f, s1, c1f;
                sincosf((float)(row & (LQ - 1)) * inv, &s0, &c0f);
                sincosf((float)((row + 8) & (LQ - 1)) * inv, &s1, &c1f);
                float x0 = v0, x1 = v1;
                v0 = x0 * c0f - x1 * s0;
                v1 = x1 * c0f + x0 * s0;
                x0 = v2; x1 = v3;
                v2 = x0 * c1f - x1 * s1;
                v3 = x1 * c1f + x0 * s1;
                if (mode == 0) {   // Q: fp16 hi/lo (A-side of attention)
                    __half h0 = __float2half(v0), h1 = __float2half(v1);
                    __half h2 = __float2half(v2), h3 = __float2half(v3);
                    __half l0 = __float2half(v0 - __half2float(h0));
                    __half l1 = __float2half(v1 - __half2float(h1));
                    __half l2 = __float2half(v2 - __half2float(h2));
                    __half l3 = __float2half(v3 - __half2float(h3));
                    *(__half2*)(g_Qhi + (size_t)row * HQ + col)       = __half2(h0, h1);
                    *(__half2*)(g_Qhi + (size_t)(row + 8) * HQ + col) = __half2(h2, h3);
                    *(__half2*)(g_Qlo + (size_t)row * HQ + col)       = __half2(l0, l1);
                    *(__half2*)(g_Qlo + (size_t)(row + 8) * HQ + col) = __half2(l2, l3);
                } else {           // K: fp16 hi only (B-side)
                    *(__half2*)(g_Khi + (size_t)row * HQ + col)       = __floats2half2_rn(v0, v1);
                    *(__half2*)(g_Khi + (size_t)(row + 8) * HQ + col) = __floats2half2_rn(v2, v3);
                }
            } else if (mode == 2) {   // V: fp16 hi only (B-side)
                *(__half2*)(g_Vhi + (size_t)row * VDIMQ + col)       = __floats2half2_rn(v0, v1);
                *(__half2*)(g_Vhi + (size_t)(row + 8) * VDIMQ + col) = __floats2half2_rn(v2, v3);
            } else {                  // G: fp32
                *(float2*)(g_G + (size_t)row * VDIMQ + col)       = make_float2(v0, v1);
                *(float2*)(g_G + (size_t)(row + 8) * VDIMQ + col) = make_float2(v2, v3);
            }
        }
    }
}

// ---------------------------------------------------------------------------
// Wo GEMM: fp32 out. K=2048, N=1024.
// ---------------------------------------------------------------------------
__global__ void __launch_bounds__(256) wo_gemm(float* __restrict__ C)
{
    extern __shared__ char smem[];
    const uint32_t sbase = smem_u32(smem);
    const int tid  = threadIdx.x;
    const int wid  = tid >> 5;
    const int lane = tid & 31;
    const int row0 = blockIdx.y * 128;
    const int col0 = blockIdx.x * 128;
    const int wm   = (wid & 1) * 64;
    const int wn   = (wid >> 1) * 32;

    float acc[4][4][4];
    #pragma unroll
    for (int mi = 0; mi < 4; mi++)
        #pragma unroll
        for (int ni = 0; ni < 4; ni++)
            #pragma unroll
            for (int e = 0; e < 4; e++) acc[mi][ni][e] = 0.0f;

    GemmOps op{ g_O_hi, g_O_lo, g_WoT, VDIMQ, row0, col0 };
    gemm_mainloop(op, sbase, acc);

    #pragma unroll
    for (int mi = 0; mi < 4; mi++) {
        const int row = row0 + wm + mi * 16 + (lane >> 2);
        #pragma unroll
        for (int ni = 0; ni < 4; ni++) {
            const int col = col0 + wn + ni * 8 + 2 * (lane & 3);
            *(float2*)(C + (size_t)row * HQ + col) =
                make_float2(acc[mi][ni][0], acc[mi][ni][1]);
            *(float2*)(C + (size_t)(row + 8) * HQ + col) =
                make_float2(acc[mi][ni][2], acc[mi][ni][3]);
        }
    }
}

// ---------------------------------------------------------------------------
// Split-K tensor-core retention attention, 512 threads (16 warps).
// fp16 2-term; K AND V double-buffered, loads issued at iteration start.
// SMEM: Q hi/lo 64K | K dbl 32K | V dbl 64K | S hi/lo 32K = 192K.
// ---------------------------------------------------------------------------
#define ATT2_SMEM 196608

__global__ void __launch_bounds__(512) attn_tc_kernel()
{
    extern __shared__ char smem[];
    const uint32_t SB  = smem_u32(smem);
    const uint32_t sQh = SB,           sQl = SB + 32768;
    const uint32_t sKB = SB + 65536;   // +(jt&1)*16384
    const uint32_t sVB = SB + 98304;   // +(jt&1)*32768
    const uint32_t sSh = SB + 163840,  sSl = SB + 180224;

    const int cid = blockIdx.x;
    const int bh  = cid & 15;
    const int c   = 39 - (cid >> 4);
    const unsigned char cum[17] = {0,1,2,3,4,6,8,10,12,15,18,21,24,28,32,36,40};
    int qt = 0;
    #pragma unroll
    for (int q = 1; q < 16; q++) if (c >= cum[q]) qt = q;
    const int chunk = c - cum[qt];
    const int t0 = chunk * 8;
    const int nkt = 2 * qt + 2;
    const int t1 = (t0 + 8 < nkt) ? t0 + 8 : nkt;

    const int b = bh >> 3, h = bh & 7;
    const int qb = qt * 128;
    const int tid = threadIdx.x, wid = tid >> 5, lane = tid & 31;
    const float sdec = log2f(1.0f - exp2f(-5.0f - (float)h));

    const __half* Qh_g = g_Qhi + (size_t)(b * LQ + qb) * HQ + h * DQKQ;
    const __half* Ql_g = g_Qlo + (size_t)(b * LQ + qb) * HQ + h * DQKQ;
    const __half* Kh_g = g_Khi + (size_t)(b * LQ) * HQ + h * DQKQ;
    const __half* Vh_g = g_Vhi + (size_t)(b * LQ) * VDIMQ + h * DVQ;

    auto load_k = [&](uint32_t kbuf, int kb) {
        #pragma unroll
        for (int t = 0; t < 2; t++) {
            int idx = tid + t * 512;       // 0..1023
            int r = idx >> 4, cc = idx & 15;
            ldgsts16(kbuf + SW256(r, cc), Kh_g + (size_t)(kb + r) * HQ + cc * 8);
        }
    };
    auto load_v = [&](uint32_t vbuf, int kb) {
        #pragma unroll
        for (int t = 0; t < 4; t++) {
            int idx = tid + t * 512;       // 0..2047
            int r = idx >> 5, cc = idx & 31;
            ldgsts16(vbuf + SW512(r, cc), Vh_g + (size_t)(kb + r) * VDIMQ + cc * 8);
        }
    };

    // Prologue: Q tile (hi/lo) + first K/V
    #pragma unroll
    for (int t = 0; t < 8; t++) {
        int idx = tid + t * 512;           // 0..4095
        int hl = idx >> 11, rem = idx & 2047;
        int r = rem >> 4, cc = rem & 15;
        const __half* src = (hl ? Ql_g : Qh_g) + (size_t)r * HQ + cc * 8;
        ldgsts16((hl ? sQl : sQh) + SW256(r, cc), src);
    }
    load_k(sKB + (uint32_t)(t0 & 1) * 16384, t0 * 64);
    load_v(sVB + (uint32_t)(t0 & 1) * 32768, t0 * 64);
    cp_commit();

    const int wms = (wid >> 1) * 16, wns = (wid & 1) * 32;   // S: 16x32
    const int wmo = (wid & 3) * 32,  wno = (wid >> 2) * 64;  // O: 32x64

    float oacc[2][8][4];
    #pragma unroll
    for (int mi = 0; mi < 2; mi++)
        #pragma unroll
        for (int nt = 0; nt < 8; nt++)
            #pragma unroll
            for (int e = 0; e < 4; e++) oacc[mi][nt][e] = 0.0f;

    for (int jt = t0; jt < t1; jt++) {
        const int kb = jt * 64;
        const uint32_t kh = sKB + (uint32_t)(jt & 1) * 16384;
        const uint32_t vh = sVB + (uint32_t)(jt & 1) * 32768;

        // Issue next tile's K+V immediately (into alternate buffers), then wait
        if (jt + 1 < t1) {
            load_k(sKB + (uint32_t)((jt + 1) & 1) * 16384, kb + 64);
            load_v(sVB + (uint32_t)((jt + 1) & 1) * 32768, kb + 64);
            cp_commit();
            cp_wait<1>();
        } else {
            cp_wait<0>();
        }
        __syncthreads();

        // ---- S = Q K^T (128x64), 2-term ----
        float sacc[4][4];
        #pragma unroll
        for (int ni = 0; ni < 4; ni++)
            #pragma unroll
            for (int e = 0; e < 4; e++) sacc[ni][e] = 0.0f;

        #pragma unroll
        for (int ks = 0; ks < 8; ks++) {
            uint32_t ah[4], al[4];
            {
                int r = wms + (lane & 15);
                int cc = ks * 2 + (lane >> 4);
                uint32_t ad = sQh + SW256(r, cc);
                ldsm4(ah, ad);
                ldsm4(al, ad + 32768);
            }
            uint32_t bhf[4][2];
            #pragma unroll
            for (int j = 0; j < 2; j++) {
                int m4 = lane >> 3;
                int n  = wns + j * 16 + ((m4 >> 1) << 3) + (lane & 7);
                int cc = ks * 2 + (m4 & 1);
                uint32_t rh[4];
                ldsm4(rh, kh + SW256(n, cc));
                bhf[2*j][0] = rh[0]; bhf[2*j][1] = rh[1];
                bhf[2*j+1][0] = rh[2]; bhf[2*j+1][1] = rh[3];
            }
            #pragma unroll
            for (int ni = 0; ni < 4; ni++) {
                mma_fp16(sacc[ni], ah, bhf[ni]);
                mma_fp16(sacc[ni], al, bhf[ni]);
            }
        }

        // ---- decay + causal + split + store S ----
        {
            int r0 = wms + (lane >> 2);
            int i0 = qb + r0, i1 = i0 + 8;
            #pragma unroll
            for (int ni = 0; ni < 4; ni++) {
                int c0 = wns + ni * 8 + 2 * (lane & 3);
                int j0 = kb + c0;
                float d00 = (i0 >= j0)     ? exp2f(sdec * (float)(i0 - j0))     : 0.0f;
                float d01 = (i0 >= j0 + 1) ? exp2f(sdec * (float)(i0 - j0 - 1)) : 0.0f;
                float d10 = (i1 >= j0)     ? exp2f(sdec * (float)(i1 - j0))     : 0.0f;
                float d11 = (i1 >= j0 + 1) ? exp2f(sdec * (float)(i1 - j0 - 1)) : 0.0f;
                float v0 = sacc[ni][0] * d00, v1 = sacc[ni][1] * d01;
                float v2 = sacc[ni][2] * d10, v3 = sacc[ni][3] * d11;
                float h0 = __half2float(__float2half(v0));
                float h1 = __half2float(__float2half(v1));
                float h2 = __half2float(__float2half(v2));
                float h3 = __half2float(__float2half(v3));
                int ch = c0 >> 3;
                int off = (c0 & 7) * 2;
                sts32(sSh + SW128R(r0, ch) + off,     pack_h2(v0, v1));
                sts32(sSl + SW128R(r0, ch) + off,     pack_h2(v0 - h0, v1 - h1));
                sts32(sSh + SW128R(r0 + 8, ch) + off, pack_h2(v2, v3));
                sts32(sSl + SW128R(r0 + 8, ch) + off, pack_h2(v2 - h2, v3 - h3));
            }
        }
        __syncthreads();

        // ---- O += S V (128x256), 2-term ----
        #pragma unroll
        for (int ks = 0; ks < 4; ks++) {
            uint32_t ah[2][4], al[2][4];
            #pragma unroll
            for (int mi = 0; mi < 2; mi++) {
                int r = wmo + mi * 16 + (lane & 15);
                int cc = ks * 2 + (lane >> 4);
                uint32_t ad = sSh + SW128R(r, cc);
                ldsm4(ah[mi], ad);
                ldsm4(al[mi], ad + 16384);
            }
            uint32_t bhf[8][2];
            #pragma unroll
            for (int np = 0; np < 4; np++) {
                int row = ks * 16 + ((lane >> 3) & 1) * 8 + (lane & 7);
                int cn  = (wno + np * 16 + (lane >> 4) * 8) >> 3;
                uint32_t rh[4];
                ldsm4t(rh, vh + SW512(row, cn));
                bhf[2*np][0] = rh[0]; bhf[2*np][1] = rh[1];
                bhf[2*np+1][0] = rh[2]; bhf[2*np+1][1] = rh[3];
            }
            #pragma unroll
            for (int mi = 0; mi < 2; mi++)
                #pragma unroll
                for (int nt = 0; nt < 8; nt++) {
                    mma_fp16(oacc[mi][nt], ah[mi], bhf[nt]);
                    mma_fp16(oacc[mi][nt], al[mi], bhf[nt]);
                }
        }
        __syncthreads();
    }

    // ---- accumulate partial O via atomicAdd ----
    float* Og = g_O + (size_t)(b * LQ + qb) * VDIMQ + h * DVQ;
    #pragma unroll
    for (int mi = 0; mi < 2; mi++) {
        int r = wmo + mi * 16 + (lane >> 2);
        #pragma unroll
        for (int nt = 0; nt < 8; nt++) {
            int col = wno + nt * 8 + 2 * (lane & 3);
            atomicAdd(Og + (size_t)r * VDIMQ + col,           oacc[mi][nt][0]);
            atomicAdd(Og + (size_t)r * VDIMQ + col + 1,       oacc[mi][nt][1]);
            atomicAdd(Og + (size_t)(r + 8) * VDIMQ + col,     oacc[mi][nt][2]);
            atomicAdd(Og + (size_t)(r + 8) * VDIMQ + col + 1, oacc[mi][nt][3]);
        }
    }
}

// ---------------------------------------------------------------------------
// Fused RMSNorm + swish gate + split -> fp16 hi/lo
// ---------------------------------------------------------------------------
__global__ void __launch_bounds__(256) normgate_split_kernel(const float* __restrict__ gw)
{
    const int warp = (blockIdx.x << 3) + (threadIdx.x >> 5);
    const int lane = threadIdx.x & 31;
    const size_t base = (size_t)(warp >> 3) * VDIMQ + (size_t)(warp & 7) * DVQ;
    const float* Op = g_O + base;
    const float* Gp = g_G + base;
    __half* Oh = g_O_hi + base;
    __half* Ol = g_O_lo + base;

    const int d0 = lane * 4;
    const int d1 = 128 + lane * 4;
    float4 o0 = *(const float4*)(Op + d0);
    float4 o1 = *(const float4*)(Op + d1);

    float ss = o0.x*o0.x + o0.y*o0.y + o0.z*o0.z + o0.w*o0.w
             + o1.x*o1.x + o1.y*o1.y + o1.z*o1.z + o1.w*o1.w;
    #pragma unroll
    for (int off = 16; off > 0; off >>= 1)
        ss += __shfl_xor_sync(0xFFFFFFFFu, ss, off);

    const float r = rsqrtf(ss * (1.0f / 256.0f) + 1e-5f);

    float4 g0 = *(const float4*)(Gp + d0);
    float4 g1 = *(const float4*)(Gp + d1);
    float4 w0 = *(const float4*)(gw + d0);
    float4 w1 = *(const float4*)(gw + d1);

    float v[8];
    v[0] = o0.x * r * w0.x * (g0.x / (1.0f + expf(-g0.x)));
    v[1] = o0.y * r * w0.y * (g0.y / (1.0f + expf(-g0.y)));
    v[2] = o0.z * r * w0.z * (g0.z / (1.0f + expf(-g0.z)));
    v[3] = o0.w * r * w0.w * (g0.w / (1.0f + expf(-g0.w)));
    v[4] = o1.x * r * w1.x * (g1.x / (1.0f + expf(-g1.x)));
    v[5] = o1.y * r * w1.y * (g1.y / (1.0f + expf(-g1.y)));
    v[6] = o1.z * r * w1.z * (g1.z / (1.0f + expf(-g1.z)));
    v[7] = o1.w * r * w1.w * (g1.w / (1.0f + expf(-g1.w)));

    __half h[8], l[8];
    #pragma unroll
    for (int i = 0; i < 8; i++) {
        h[i] = __float2half(v[i]);
        l[i] = __float2half(v[i] - __half2float(h[i]));
    }
    *(__half2*)(Oh + d0)     = __half2(h[0], h[1]);
    *(__half2*)(Oh + d0 + 2) = __half2(h[2], h[3]);
    *(__half2*)(Oh + d1)     = __half2(h[4], h[5]);
    *(__half2*)(Oh + d1 + 2) = __half2(h[6], h[7]);
    *(__half2*)(Ol + d0)     = __half2(l[0], l[1]);
    *(__half2*)(Ol + d0 + 2) = __half2(l[2], l[3]);
    *(__half2*)(Ol + d1)     = __half2(l[4], l[5]);
    *(__half2*)(Ol + d1 + 2) = __half2(l[6], l[7]);
}

// ---------------------------------------------------------------------------
// kernel_launch
// ---------------------------------------------------------------------------
extern "C" void kernel_launch(void* const* d_in, const int* in_sizes, int n_in,
                              void* d_out, int out_size)
{
    const float* hs = (const float*)d_in[0];
    const float* Wq = (const float*)d_in[1];
    const float* Wk = (const float*)d_in[2];
    const float* Wv = (const float*)d_in[3];
    const float* Wg = (const float*)d_in[4];
    const float* Wo = (const float*)d_in[5];
    const float* gw = (const float*)d_in[6];
    float* out = (float*)d_out;

    float* Op;
    cudaGetSymbolAddress((void**)&Op, g_O);

    __half *hsh, *hsl;
    __half *qw, *kw, *vw, *gwt, *ow;
    cudaGetSymbolAddress((void**)&hsh, g_hs_hi);
    cudaGetSymbolAddress((void**)&hsl, g_hs_lo);
    cudaGetSymbolAddress((void**)&qw, g_WqT);
    cudaGetSymbolAddress((void**)&kw, g_WkT);
    cudaGetSymbolAddress((void**)&vw, g_WvT);
    cudaGetSymbolAddress((void**)&gwt, g_WgT);
    cudaGetSymbolAddress((void**)&ow, g_WoT);

    cudaFuncSetAttribute(qkvg_gemm, cudaFuncAttributeMaxDynamicSharedMemorySize, TCG_SMEM);
    cudaFuncSetAttribute(wo_gemm,   cudaFuncAttributeMaxDynamicSharedMemorySize, TCG_SMEM);
    cudaFuncSetAttribute(attn_tc_kernel, cudaFuncAttributeMaxDynamicSharedMemorySize, ATT2_SMEM);

    dim3 blk(256);

    // 1) prep
    split_kernel<<<(MROWS*HQ/4 + 255)/256, blk>>>(hs, hsh, hsl, MROWS*HQ/4);
    TDescs ds;
    ds.d[0] = { Wq, qw,  HQ,    HQ,    0    };
    ds.d[1] = { Wk, kw,  HQ,    HQ,    1024 };
    ds.d[2] = { Wv, vw,  HQ,    VDIMQ, 2048 };
    ds.d[3] = { Wg, gwt, HQ,    VDIMQ, 4096 };
    ds.d[4] = { Wo, ow,  VDIMQ, HQ,    6144 };
    transpose_multi<<<8192, blk>>>(ds);

    // 2) mega QKVG projection
    qkvg_gemm<<<dim3(48, MROWS/128), blk, TCG_SMEM>>>();

    // 3) zero O accumulator + split-K attention
    cudaMemsetAsync(Op, 0, (size_t)MROWS * VDIMQ * sizeof(float));
    attn_tc_kernel<<<640, 512, ATT2_SMEM>>>();

    // 4) fused RMSNorm + swish gate + split
    normgate_split_kernel<<<4096, blk>>>(gw);

    // 5) output projection
    wo_gemm<<<dim3(HQ/128, MROWS/128), blk, TCG_SMEM>>>(out);
}

// round 9
// speedup vs baseline: 5.4563x; 1.1958x over previous
#include <cuda_runtime.h>
#include <cuda_fp16.h>
#include <math.h>
#include <stdint.h>

// Problem constants
#define BQ 2
#define LQ 2048
#define HQ 1024
#define NHQ 8
#define DQKQ 128
#define DVQ 256
#define VDIMQ 2048
#define MROWS (BQ*LQ)   // 4096
#define CHK 128         // retention chunk size
#define NCH (LQ/CHK)    // 16 chunks per sequence

#define QSCALE 0.08838834764831843f          // 128^-0.5
#define RF (-0.20762050593045852f)           // -2*log2(10000)/128

// ---------------------------------------------------------------------------
// Scratch (device globals)
// ---------------------------------------------------------------------------
__device__ float g_G[MROWS*VDIMQ];
__device__ float g_O[MROWS*VDIMQ];
__device__ float g_A[16*NCH*DQKQ*DVQ];            // per-chunk KV outer products (fp32)

__device__ __half g_hs_hi[MROWS*HQ],  g_hs_lo[MROWS*HQ];
__device__ __half g_O_hi[MROWS*VDIMQ], g_O_lo[MROWS*VDIMQ];
__device__ __half g_Qhi[MROWS*HQ],    g_Qlo[MROWS*HQ];
__device__ __half g_Khi[MROWS*HQ];
__device__ __half g_Kdec[MROWS*HQ];               // K * lam^(CHK - r%CHK)
__device__ __half g_Vhi[MROWS*VDIMQ];
__device__ __half g_Shi[16*NCH*DQKQ*DVQ];         // chunk-entry states hi
__device__ __half g_Slo[16*NCH*DQKQ*DVQ];         // chunk-entry states lo
__device__ __half g_WqT[HQ*HQ];
__device__ __half g_WkT[HQ*HQ];
__device__ __half g_WvT[VDIMQ*HQ];
__device__ __half g_WgT[VDIMQ*HQ];
__device__ __half g_WoT[HQ*VDIMQ];

// ---------------------------------------------------------------------------
// PTX helpers
// ---------------------------------------------------------------------------
__device__ __forceinline__ uint32_t smem_u32(const void* p) {
    uint32_t a;
    asm("{ .reg .u64 t; cvta.to.shared.u64 t, %1; cvt.u32.u64 %0, t; }"
        : "=r"(a) : "l"(p));
    return a;
}
__device__ __forceinline__ void ldgsts16(uint32_t dst, const void* src) {
    asm volatile("cp.async.cg.shared.global [%0], [%1], 16;" :: "r"(dst), "l"(src));
}
__device__ __forceinline__ void cp_commit() {
    asm volatile("cp.async.commit_group;" ::: "memory");
}
template<int N_>
__device__ __forceinline__ void cp_wait() {
    asm volatile("cp.async.wait_group %0;" :: "n"(N_) : "memory");
}
__device__ __forceinline__ void ldsm4(uint32_t* r, uint32_t addr) {
    asm volatile("ldmatrix.sync.aligned.m8n8.x4.shared.b16 {%0,%1,%2,%3}, [%4];"
        : "=r"(r[0]), "=r"(r[1]), "=r"(r[2]), "=r"(r[3]) : "r"(addr));
}
__device__ __forceinline__ void ldsm4t(uint32_t* r, uint32_t addr) {
    asm volatile("ldmatrix.sync.aligned.m8n8.x4.trans.shared.b16 {%0,%1,%2,%3}, [%4];"
        : "=r"(r[0]), "=r"(r[1]), "=r"(r[2]), "=r"(r[3]) : "r"(addr));
}
__device__ __forceinline__ void sts32(uint32_t addr, uint32_t v) {
    asm volatile("st.shared.b32 [%0], %1;" :: "r"(addr), "r"(v) : "memory");
}
__device__ __forceinline__ void mma_fp16(float* c, const uint32_t* a, const uint32_t* b) {
    asm volatile("mma.sync.aligned.m16n8k16.row.col.f32.f16.f16.f32 "
        "{%0,%1,%2,%3}, {%4,%5,%6,%7}, {%8,%9}, {%0,%1,%2,%3};"
        : "+f"(c[0]), "+f"(c[1]), "+f"(c[2]), "+f"(c[3])
        : "r"(a[0]), "r"(a[1]), "r"(a[2]), "r"(a[3]), "r"(b[0]), "r"(b[1]));
}
__device__ __forceinline__ uint32_t pack_h2(float a, float b) {
    __half2 t = __floats2half2_rn(a, b);
    return *(uint32_t*)&t;
}

// Swizzles: row stride in bytes; 16B chunk xor'd by (r&7)
#define SW128R(r, c) ((uint32_t)((r) * 128u + ((uint32_t)((c) ^ ((r) & 7)) << 4)))
#define SW256(r, c)  ((uint32_t)((r) * 256u + ((uint32_t)((c) ^ ((r) & 7)) << 4)))
#define SW512(r, c)  ((uint32_t)((r) * 512u + ((uint32_t)((c) ^ ((r) & 7)) << 4)))

// GEMM: K-chunk 64; tiles Ahi|Alo|Bhi of 128x64 fp16 = 16KB each; 3 stages
#define GST_AHI 0
#define GST_ALO 16384
#define GST_BHI 32768
#define G_STAGE 49152
#define TCG_SMEM (3 * G_STAGE)

// ---------------------------------------------------------------------------
// hs split -> fp16 hi/lo
// ---------------------------------------------------------------------------
__global__ void __launch_bounds__(256) split_kernel(const float* __restrict__ x,
                                                    __half* __restrict__ hi,
                                                    __half* __restrict__ lo,
                                                    int n4)
{
    int i = blockIdx.x * 256 + threadIdx.x;
    if (i >= n4) return;
    float4 v = ((const float4*)x)[i];
    __half h0 = __float2half(v.x), h1 = __float2half(v.y);
    __half h2 = __float2half(v.z), h3 = __float2half(v.w);
    __half l0 = __float2half(v.x - __half2float(h0));
    __half l1 = __float2half(v.y - __half2float(h1));
    __half l2 = __float2half(v.z - __half2float(h2));
    __half l3 = __float2half(v.w - __half2float(h3));
    ((__half2*)hi)[2*i]   = __half2(h0, h1);
    ((__half2*)hi)[2*i+1] = __half2(h2, h3);
    ((__half2*)lo)[2*i]   = __half2(l0, l1);
    ((__half2*)lo)[2*i+1] = __half2(l2, l3);
}

// ---------------------------------------------------------------------------
// Merged weight transpose (fp16): one launch for all 5 weights.
// ---------------------------------------------------------------------------
struct TDesc { const float* W; __half* hi; int K, N, start; };
struct TDescs { TDesc d[5]; };

__global__ void __launch_bounds__(256) transpose_multi(TDescs ds)
{
    __shared__ float s[32][33];
    int t = blockIdx.x;
    int i = 0;
    #pragma unroll
    for (int j = 1; j < 5; j++) if (t >= ds.d[j].start) i = j;
    const float* W = ds.d[i].W;
    __half* Th = ds.d[i].hi;
    const int K = ds.d[i].K, N = ds.d[i].N;
    int lt = t - ds.d[i].start;
    int ncols = N >> 5;
    int k0 = (lt / ncols) * 32;
    int n0 = (lt % ncols) * 32;

    const int tx = threadIdx.x & 31;
    const int ty = threadIdx.x >> 5;
    #pragma unroll
    for (int q = 0; q < 4; q++)
        s[ty + 8*q][tx] = W[(size_t)(k0 + ty + 8*q) * N + n0 + tx];
    __syncthreads();
    #pragma unroll
    for (int q = 0; q < 4; q++) {
        float v = s[tx][ty + 8*q];
        Th[(size_t)(n0 + ty + 8*q) * K + k0 + tx] = __float2half(v);
    }
}

// ---------------------------------------------------------------------------
// GEMM mainloop: 128x128 tile, 8 warps (64x32), K-chunk 64, 3-stage pipeline.
// ---------------------------------------------------------------------------
struct GemmOps {
    const __half *Ah, *Al, *Bh;
    int K, row0, bcol0;
};

__device__ __forceinline__ void gemm_mainloop(const GemmOps& op, uint32_t sbase,
                                              float acc[4][4][4])
{
    const int tid  = threadIdx.x;
    const int wid  = tid >> 5;
    const int lane = tid & 31;
    const int wm   = (wid & 1) * 64;
    const int wn   = (wid >> 1) * 32;
    const int K    = op.K;
    const int nchunks = K >> 6;

    auto load_chunk = [&](uint32_t sb, int k0) {
        #pragma unroll
        for (int t = 0; t < 4; t++) {
            int idx = tid + t * 256;
            int r   = idx >> 3;
            int c   = idx & 7;
            uint32_t soff = SW128R(r, c);
            size_t aoff = (size_t)(op.row0 + r) * K + k0 + c * 8;
            size_t boff = (size_t)(op.bcol0 + r) * K + k0 + c * 8;
            ldgsts16(sb + GST_AHI + soff, op.Ah + aoff);
            ldgsts16(sb + GST_ALO + soff, op.Al + aoff);
            ldgsts16(sb + GST_BHI + soff, op.Bh + boff);
        }
        cp_commit();
    };

    load_chunk(sbase, 0);
    if (nchunks > 1) load_chunk(sbase + G_STAGE, 64);

    uint32_t stage_of[3] = { sbase, sbase + G_STAGE, sbase + 2 * G_STAGE };

    for (int cch = 0; cch < nchunks; cch++) {
        const uint32_t sb = stage_of[cch % 3];
        if (cch + 2 < nchunks) {
            load_chunk(stage_of[(cch + 2) % 3], (cch + 2) * 64);
            cp_wait<2>();
        } else if (cch + 1 < nchunks) {
            cp_wait<1>();
        } else {
            cp_wait<0>();
        }
        __syncthreads();

        #pragma unroll
        for (int ks = 0; ks < 4; ks++) {
            uint32_t ahi[4][4], alo[4][4];
            #pragma unroll
            for (int mi = 0; mi < 4; mi++) {
                int r = wm + mi * 16 + (lane & 15);
                int c = ks * 2 + (lane >> 4);
                uint32_t ad = sb + GST_AHI + SW128R(r, c);
                ldsm4(ahi[mi], ad);
                ldsm4(alo[mi], ad + (GST_ALO - GST_AHI));
            }
            uint32_t bhi[4][2];
            #pragma unroll
            for (int j = 0; j < 2; j++) {
                int m4 = lane >> 3;
                int n  = wn + j * 16 + ((m4 >> 1) << 3) + (lane & 7);
                int c  = ks * 2 + (m4 & 1);
                uint32_t rh[4];
                ldsm4(rh, sb + GST_BHI + SW128R(n, c));
                bhi[2*j][0] = rh[0]; bhi[2*j][1] = rh[1];
                bhi[2*j+1][0] = rh[2]; bhi[2*j+1][1] = rh[3];
            }
            #pragma unroll
            for (int mi = 0; mi < 4; mi++)
                #pragma unroll
                for (int ni = 0; ni < 4; ni++) {
                    mma_fp16(acc[mi][ni], ahi[mi], bhi[ni]);
                    mma_fp16(acc[mi][ni], alo[mi], bhi[ni]);
                }
        }
        __syncthreads();
    }
}

// ---------------------------------------------------------------------------
// Mega QKVG GEMM: grid (48, 32). cb<8: Q | cb<16: K (+Kdec) | cb<32: V | else G
// ---------------------------------------------------------------------------
__global__ void __launch_bounds__(256) qkvg_gemm()
{
    extern __shared__ char smem[];
    const uint32_t sbase = smem_u32(smem);
    const int tid  = threadIdx.x;
    const int wid  = tid >> 5;
    const int lane = tid & 31;
    const int row0 = blockIdx.y * 128;
    const int cb   = blockIdx.x;
    const int wm   = (wid & 1) * 64;
    const int wn   = (wid >> 1) * 32;

    int mode, lcol0;
    const __half* Bh;
    if (cb < 8)       { mode = 0; lcol0 = cb * 128;        Bh = g_WqT; }
    else if (cb < 16) { mode = 1; lcol0 = (cb - 8) * 128;  Bh = g_WkT; }
    else if (cb < 32) { mode = 2; lcol0 = (cb - 16) * 128; Bh = g_WvT; }
    else              { mode = 3; lcol0 = (cb - 32) * 128; Bh = g_WgT; }

    float acc[4][4][4];
    #pragma unroll
    for (int mi = 0; mi < 4; mi++)
        #pragma unroll
        for (int ni = 0; ni < 4; ni++)
            #pragma unroll
            for (int e = 0; e < 4; e++) acc[mi][ni][e] = 0.0f;

    GemmOps op{ g_hs_hi, g_hs_lo, Bh, HQ, row0, lcol0 };
    gemm_mainloop(op, sbase, acc);

    // K decay scale (constant per CTA for mode 1: head = cb-8)
    float sdecK = 0.0f;
    if (mode == 1) sdecK = log2f(1.0f - exp2f(-5.0f - (float)(cb - 8)));

    #pragma unroll
    for (int mi = 0; mi < 4; mi++) {
        const int row = row0 + wm + mi * 16 + (lane >> 2);
        #pragma unroll
        for (int ni = 0; ni < 4; ni++) {
            const int col = lcol0 + wn + ni * 8 + 2 * (lane & 3);
            float v0 = acc[mi][ni][0], v1 = acc[mi][ni][1];
            float v2 = acc[mi][ni][2], v3 = acc[mi][ni][3];
            if (mode <= 1) {   // Q or K: scale + RoPE
                if (mode == 0) { v0 *= QSCALE; v1 *= QSCALE; v2 *= QSCALE; v3 *= QSCALE; }
                const int p = (col & 127) >> 1;
                const float inv = exp2f((float)p * RF);
                float s0, c0f, s1, c1f;
                sincosf((float)(row & (LQ - 1)) * inv, &s0, &c0f);
                sincosf((float)((row + 8) & (LQ - 1)) * inv, &s1, &c1f);
                float x0 = v0, x1 = v1;
                v0 = x0 * c0f - x1 * s0;
                v1 = x1 * c0f + x0 * s0;
                x0 = v2; x1 = v3;
                v2 = x0 * c1f - x1 * s1;
                v3 = x1 * c1f + x0 * s1;
                if (mode == 0) {   // Q: fp16 hi/lo
                    __half h0 = __float2half(v0), h1 = __float2half(v1);
                    __half h2 = __float2half(v2), h3 = __float2half(v3);
                    __half l0 = __float2half(v0 - __half2float(h0));
                    __half l1 = __float2half(v1 - __half2float(h1));
                    __half l2 = __float2half(v2 - __half2float(h2));
                    __half l3 = __float2half(v3 - __half2float(h3));
                    *(__half2*)(g_Qhi + (size_t)row * HQ + col)       = __half2(h0, h1);
                    *(__half2*)(g_Qhi + (size_t)(row + 8) * HQ + col) = __half2(h2, h3);
                    *(__half2*)(g_Qlo + (size_t)row * HQ + col)       = __half2(l0, l1);
                    *(__half2*)(g_Qlo + (size_t)(row + 8) * HQ + col) = __half2(l2, l3);
                } else {           // K: hi + decayed copy
                    *(__half2*)(g_Khi + (size_t)row * HQ + col)       = __floats2half2_rn(v0, v1);
                    *(__half2*)(g_Khi + (size_t)(row + 8) * HQ + col) = __floats2half2_rn(v2, v3);
                    float p0 = exp2f(sdecK * (float)(CHK - (row & (CHK - 1))));
                    float p1 = exp2f(sdecK * (float)(CHK - ((row + 8) & (CHK - 1))));
                    *(__half2*)(g_Kdec + (size_t)row * HQ + col)       = __floats2half2_rn(v0 * p0, v1 * p0);
                    *(__half2*)(g_Kdec + (size_t)(row + 8) * HQ + col) = __floats2half2_rn(v2 * p1, v3 * p1);
                }
            } else if (mode == 2) {
                *(__half2*)(g_Vhi + (size_t)row * VDIMQ + col)       = __floats2half2_rn(v0, v1);
                *(__half2*)(g_Vhi + (size_t)(row + 8) * VDIMQ + col) = __floats2half2_rn(v2, v3);
            } else {
                *(float2*)(g_G + (size_t)row * VDIMQ + col)       = make_float2(v0, v1);
                *(float2*)(g_G + (size_t)(row + 8) * VDIMQ + col) = make_float2(v2, v3);
            }
        }
    }
}

// ---------------------------------------------------------------------------
// Wo GEMM: fp32 out. K=2048, N=1024.
// ---------------------------------------------------------------------------
__global__ void __launch_bounds__(256) wo_gemm(float* __restrict__ C)
{
    extern __shared__ char smem[];
    const uint32_t sbase = smem_u32(smem);
    const int tid  = threadIdx.x;
    const int wid  = tid >> 5;
    const int lane = tid & 31;
    const int row0 = blockIdx.y * 128;
    const int col0 = blockIdx.x * 128;
    const int wm   = (wid & 1) * 64;
    const int wn   = (wid >> 1) * 32;

    float acc[4][4][4];
    #pragma unroll
    for (int mi = 0; mi < 4; mi++)
        #pragma unroll
        for (int ni = 0; ni < 4; ni++)
            #pragma unroll
            for (int e = 0; e < 4; e++) acc[mi][ni][e] = 0.0f;

    GemmOps op{ g_O_hi, g_O_lo, g_WoT, VDIMQ, row0, col0 };
    gemm_mainloop(op, sbase, acc);

    #pragma unroll
    for (int mi = 0; mi < 4; mi++) {
        const int row = row0 + wm + mi * 16 + (lane >> 2);
        #pragma unroll
        for (int ni = 0; ni < 4; ni++) {
            const int col = col0 + wn + ni * 8 + 2 * (lane & 3);
            *(float2*)(C + (size_t)row * HQ + col) =
                make_float2(acc[mi][ni][0], acc[mi][ni][1]);
            *(float2*)(C + (size_t)(row + 8) * HQ + col) =
                make_float2(acc[mi][ni][2], acc[mi][ni][3]);
        }
    }
}

// ---------------------------------------------------------------------------
// Attention Kernel A: per-chunk outer product  A_c = Kdec_c^T V_c
// grid (16 chunks, 16 bh), 512 threads. smem: Kdec 32K + V 64K = 96K.
// ---------------------------------------------------------------------------
#define ATTA_SMEM 98304

__global__ void __launch_bounds__(512) chunk_state_kernel()
{
    extern __shared__ char smem[];
    const uint32_t SB   = smem_u32(smem);
    const uint32_t kbuf = SB;            // [128 r][128 d1] fp16 SW256
    const uint32_t vbuf = SB + 32768;    // [128 r][256 d2] fp16 SW512

    const int ch = blockIdx.x, bh = blockIdx.y;
    const int b = bh >> 3, h = bh & 7;
    const int tid = threadIdx.x, wid = tid >> 5, lane = tid & 31;
    const int trow = ch * CHK;

    const __half* Kd_g = g_Kdec + (size_t)(b * LQ + trow) * HQ + h * DQKQ;
    const __half* Vh_g = g_Vhi + (size_t)(b * LQ + trow) * VDIMQ + h * DVQ;

    #pragma unroll
    for (int t = 0; t < 4; t++) {
        int idx = tid + t * 512;           // 0..2047
        int r = idx >> 4, cc = idx & 15;
        ldgsts16(kbuf + SW256(r, cc), Kd_g + (size_t)r * HQ + cc * 8);
    }
    #pragma unroll
    for (int t = 0; t < 8; t++) {
        int idx = tid + t * 512;           // 0..4095
        int r = idx >> 5, cc = idx & 31;
        ldgsts16(vbuf + SW512(r, cc), Vh_g + (size_t)r * VDIMQ + cc * 8);
    }
    cp_commit();
    cp_wait<0>();
    __syncthreads();

    const int wm = (wid & 3) * 32;     // d1
    const int wn = (wid >> 2) * 64;    // d2

    float acc[2][8][4];
    #pragma unroll
    for (int mi = 0; mi < 2; mi++)
        #pragma unroll
        for (int nt = 0; nt < 8; nt++)
            #pragma unroll
            for (int e = 0; e < 4; e++) acc[mi][nt][e] = 0.0f;

    #pragma unroll
    for (int ks = 0; ks < 8; ks++) {
        // A-side: Kdec^T via trans-ldsm (m = d1, k = r)
        uint32_t af[2][4];
        #pragma unroll
        for (int mi = 0; mi < 2; mi++) {
            int m0 = wm + mi * 16;
            int r_src = ks * 16 + ((lane >> 4) << 3) + (lane & 7);
            int d_off = (m0 >> 3) + ((lane >> 3) & 1);
            ldsm4t(af[mi], kbuf + SW256(r_src, d_off));
        }
        // B-side: V via trans-ldsm (n = d2, k = r)
        uint32_t bf[8][2];
        #pragma unroll
        for (int np = 0; np < 4; np++) {
            int row = ks * 16 + ((lane >> 3) & 1) * 8 + (lane & 7);
            int cn  = (wn + np * 16 + (lane >> 4) * 8) >> 3;
            uint32_t rh[4];
            ldsm4t(rh, vbuf + SW512(row, cn));
            bf[2*np][0] = rh[0]; bf[2*np][1] = rh[1];
            bf[2*np+1][0] = rh[2]; bf[2*np+1][1] = rh[3];
        }
        #pragma unroll
        for (int mi = 0; mi < 2; mi++)
            #pragma unroll
            for (int nt = 0; nt < 8; nt++)
                mma_fp16(acc[mi][nt], af[mi], bf[nt]);
    }

    float* Ag = g_A + ((size_t)(bh * NCH + ch) << 15);
    #pragma unroll
    for (int mi = 0; mi < 2; mi++) {
        int d1 = wm + mi * 16 + (lane >> 2);
        #pragma unroll
        for (int nt = 0; nt < 8; nt++) {
            int d2 = wn + nt * 8 + 2 * (lane & 3);
            *(float2*)(Ag + (size_t)d1 * DVQ + d2) =
                make_float2(acc[mi][nt][0], acc[mi][nt][1]);
            *(float2*)(Ag + (size_t)(d1 + 8) * DVQ + d2) =
                make_float2(acc[mi][nt][2], acc[mi][nt][3]);
        }
    }
}

// ---------------------------------------------------------------------------
// Attention Kernel B: per-element decay scan over chunks -> states S_c (hi/lo)
// grid (64, 16 bh), 512 threads. S_c = state ENTERING chunk c.
// ---------------------------------------------------------------------------
__global__ void __launch_bounds__(512) scan_kernel()
{
    const int e  = blockIdx.x * 512 + threadIdx.x;   // 0..32767
    const int bh = blockIdx.y;
    const int h  = bh & 7;
    const float sdec = log2f(1.0f - exp2f(-5.0f - (float)h));
    const float lamC = exp2f(sdec * (float)CHK);

    const size_t base = (size_t)bh * NCH << 15;
    float S = 0.0f;
    #pragma unroll
    for (int c = 0; c < NCH; c++) {
        size_t off = base + ((size_t)c << 15) + e;
        __half hi = __float2half(S);
        g_Shi[off] = hi;
        g_Slo[off] = __float2half(S - __half2float(hi));
        S = S * lamC + g_A[off];
    }
}

// ---------------------------------------------------------------------------
// Attention Kernel C: per (chunk, bh, dv-half) output.
// O = (QK^T ∘ decay) V + lam^r (Q S_c).  No atomics.
// SMEM: Qh 32 | Ql 32 | K 32 (→aliased Ph) | Sh 32 | Sl 32 | V 32 | Pl 32 = 224K
// ---------------------------------------------------------------------------
#define ATTC_SMEM 229376

__global__ void __launch_bounds__(512) attn_chunk_kernel()
{
    extern __shared__ char smem[];
    const uint32_t SB  = smem_u32(smem);
    const uint32_t sQh = SB;
    const uint32_t sQl = SB + 32768;
    const uint32_t sK  = SB + 65536;
    const uint32_t sSh = SB + 98304;
    const uint32_t sSl = SB + 131072;
    const uint32_t sV  = SB + 163840;
    const uint32_t sPl = SB + 196608;
    const uint32_t sPh = sK;            // aliased after K consumed

    const int vh = blockIdx.x;          // dv half (0/1)
    const int ch = blockIdx.y;          // chunk
    const int bh = blockIdx.z;
    const int b = bh >> 3, h = bh & 7;
    const int tid = threadIdx.x, wid = tid >> 5, lane = tid & 31;
    const int trow = ch * CHK;
    const float sdec = log2f(1.0f - exp2f(-5.0f - (float)h));

    const __half* Qh_g = g_Qhi + (size_t)(b * LQ + trow) * HQ + h * DQKQ;
    const __half* Ql_g = g_Qlo + (size_t)(b * LQ + trow) * HQ + h * DQKQ;
    const __half* Kh_g = g_Khi + (size_t)(b * LQ + trow) * HQ + h * DQKQ;
    const __half* Vh_g = g_Vhi + (size_t)(b * LQ + trow) * VDIMQ + h * DVQ + vh * 128;
    const __half* Sh_g = g_Shi + ((size_t)(bh * NCH + ch) << 15) + vh * 128;
    const __half* Sl_g = g_Slo + ((size_t)(bh * NCH + ch) << 15) + vh * 128;

    // group 1: Qh, Ql, K
    #pragma unroll
    for (int t = 0; t < 4; t++) {
        int idx = tid + t * 512;
        int r = idx >> 4, cc = idx & 15;
        ldgsts16(sQh + SW256(r, cc), Qh_g + (size_t)r * HQ + cc * 8);
        ldgsts16(sQl + SW256(r, cc), Ql_g + (size_t)r * HQ + cc * 8);
        ldgsts16(sK  + SW256(r, cc), Kh_g + (size_t)r * HQ + cc * 8);
    }
    cp_commit();
    // group 2: Sh, Sl, V
    #pragma unroll
    for (int t = 0; t < 4; t++) {
        int idx = tid + t * 512;
        int r = idx >> 4, cc = idx & 15;
        ldgsts16(sSh + SW256(r, cc), Sh_g + (size_t)r * DVQ + cc * 8);
        ldgsts16(sSl + SW256(r, cc), Sl_g + (size_t)r * DVQ + cc * 8);
        ldgsts16(sV  + SW256(r, cc), Vh_g + (size_t)r * VDIMQ + cc * 8);
    }
    cp_commit();

    const int wm = (wid & 3) * 32;
    const int wn = (wid >> 2) * 32;

    cp_wait<1>();
    __syncthreads();

    // ---- P = Q K^T (128x128), 2 terms ----
    float sacc[2][4][4];
    #pragma unroll
    for (int mi = 0; mi < 2; mi++)
        #pragma unroll
        for (int ni = 0; ni < 4; ni++)
            #pragma unroll
            for (int e = 0; e < 4; e++) sacc[mi][ni][e] = 0.0f;

    #pragma unroll
    for (int ks = 0; ks < 8; ks++) {
        uint32_t qh[2][4], ql[2][4];
        #pragma unroll
        for (int mi = 0; mi < 2; mi++) {
            int r = wm + mi * 16 + (lane & 15);
            int cc = ks * 2 + (lane >> 4);
            uint32_t ad = sQh + SW256(r, cc);
            ldsm4(qh[mi], ad);
            ldsm4(ql[mi], ad + 32768);
        }
        uint32_t kb[4][2];
        #pragma unroll
        for (int j = 0; j < 2; j++) {
            int m4 = lane >> 3;
            int n  = wn + j * 16 + ((m4 >> 1) << 3) + (lane & 7);
            int cc = ks * 2 + (m4 & 1);
            uint32_t rh[4];
            ldsm4(rh, sK + SW256(n, cc));
            kb[2*j][0] = rh[0]; kb[2*j][1] = rh[1];
            kb[2*j+1][0] = rh[2]; kb[2*j+1][1] = rh[3];
        }
        #pragma unroll
        for (int mi = 0; mi < 2; mi++)
            #pragma unroll
            for (int ni = 0; ni < 4; ni++) {
                mma_fp16(sacc[mi][ni], qh[mi], kb[ni]);
                mma_fp16(sacc[mi][ni], ql[mi], kb[ni]);
            }
    }
    __syncthreads();   // all K reads done before overwriting sK with Ph

    // ---- decay + causal + split -> store P hi/lo ----
    #pragma unroll
    for (int mi = 0; mi < 2; mi++) {
        int r0 = wm + mi * 16 + (lane >> 2);
        #pragma unroll
        for (int ni = 0; ni < 4; ni++) {
            int j0 = wn + ni * 8 + 2 * (lane & 3);
            float d00 = (r0 >= j0)         ? exp2f(sdec * (float)(r0 - j0))     : 0.0f;
            float d01 = (r0 >= j0 + 1)     ? exp2f(sdec * (float)(r0 - j0 - 1)) : 0.0f;
            float d10 = (r0 + 8 >= j0)     ? exp2f(sdec * (float)(r0 + 8 - j0))     : 0.0f;
            float d11 = (r0 + 8 >= j0 + 1) ? exp2f(sdec * (float)(r0 + 8 - j0 - 1)) : 0.0f;
            float v0 = sacc[mi][ni][0] * d00, v1 = sacc[mi][ni][1] * d01;
            float v2 = sacc[mi][ni][2] * d10, v3 = sacc[mi][ni][3] * d11;
            float h0 = __half2float(__float2half(v0));
            float h1 = __half2float(__float2half(v1));
            float h2 = __half2float(__float2half(v2));
            float h3 = __half2float(__float2half(v3));
            int cc = j0 >> 3;
            int off = (j0 & 7) * 2;
            sts32(sPh + SW256(r0, cc) + off,     pack_h2(v0, v1));
            sts32(sPl + SW256(r0, cc) + off,     pack_h2(v0 - h0, v1 - h1));
            sts32(sPh + SW256(r0 + 8, cc) + off, pack_h2(v2, v3));
            sts32(sPl + SW256(r0 + 8, cc) + off, pack_h2(v2 - h2, v3 - h3));
        }
    }
    cp_wait<0>();
    __syncthreads();

    // ---- X = Q @ S (128x128), 3 terms ----
    float xacc[2][4][4];
    #pragma unroll
    for (int mi = 0; mi < 2; mi++)
        #pragma unroll
        for (int ni = 0; ni < 4; ni++)
            #pragma unroll
            for (int e = 0; e < 4; e++) xacc[mi][ni][e] = 0.0f;

    #pragma unroll
    for (int ks = 0; ks < 8; ks++) {
        uint32_t qh[2][4], ql[2][4];
        #pragma unroll
        for (int mi = 0; mi < 2; mi++) {
            int r = wm + mi * 16 + (lane & 15);
            int cc = ks * 2 + (lane >> 4);
            uint32_t ad = sQh + SW256(r, cc);
            ldsm4(qh[mi], ad);
            ldsm4(ql[mi], ad + 32768);
        }
        uint32_t sbh[4][2], sbl[4][2];
        #pragma unroll
        for (int np = 0; np < 2; np++) {
            int row = ks * 16 + ((lane >> 3) & 1) * 8 + (lane & 7);
            int cn  = (wn + np * 16 + (lane >> 4) * 8) >> 3;
            uint32_t rh[4], rl[4];
            ldsm4t(rh, sSh + SW256(row, cn));
            ldsm4t(rl, sSl + SW256(row, cn));
            sbh[2*np][0] = rh[0]; sbh[2*np][1] = rh[1];
            sbh[2*np+1][0] = rh[2]; sbh[2*np+1][1] = rh[3];
            sbl[2*np][0] = rl[0]; sbl[2*np][1] = rl[1];
            sbl[2*np+1][0] = rl[2]; sbl[2*np+1][1] = rl[3];
        }
        #pragma unroll
        for (int mi = 0; mi < 2; mi++)
            #pragma unroll
            for (int ni = 0; ni < 4; ni++) {
                mma_fp16(xacc[mi][ni], qh[mi], sbh[ni]);
                mma_fp16(xacc[mi][ni], ql[mi], sbh[ni]);
                mma_fp16(xacc[mi][ni], qh[mi], sbl[ni]);
            }
    }

    // ---- O_intra = P @ V (128x128), 2 terms ----
    float oacc[2][4][4];
    #pragma unroll
    for (int mi = 0; mi < 2; mi++)
        #pragma unroll
        for (int ni = 0; ni < 4; ni++)
            #pragma unroll
            for (int e = 0; e < 4; e++) oacc[mi][ni][e] = 0.0f;

    #pragma unroll
    for (int ks = 0; ks < 8; ks++) {
        uint32_t ph[2][4], pl[2][4];
        #pragma unroll
        for (int mi = 0; mi < 2; mi++) {
            int r = wm + mi * 16 + (lane & 15);
            int cc = ks * 2 + (lane >> 4);
            ldsm4(ph[mi], sPh + SW256(r, cc));
            ldsm4(pl[mi], sPl + SW256(r, cc));
        }
        uint32_t vb[4][2];
        #pragma unroll
        for (int np = 0; np < 2; np++) {
            int row = ks * 16 + ((lane >> 3) & 1) * 8 + (lane & 7);
            int cn  = (wn + np * 16 + (lane >> 4) * 8) >> 3;
            uint32_t rh[4];
            ldsm4t(rh, sV + SW256(row, cn));
            vb[2*np][0] = rh[0]; vb[2*np][1] = rh[1];
            vb[2*np+1][0] = rh[2]; vb[2*np+1][1] = rh[3];
        }
        #pragma unroll
        for (int mi = 0; mi < 2; mi++)
            #pragma unroll
            for (int ni = 0; ni < 4; ni++) {
                mma_fp16(oacc[mi][ni], ph[mi], vb[ni]);
                mma_fp16(oacc[mi][ni], pl[mi], vb[ni]);
            }
    }

    // ---- combine + write O ----
    float* Og = g_O + (size_t)(b * LQ + trow) * VDIMQ + h * DVQ + vh * 128;
    #pragma unroll
    for (int mi = 0; mi < 2; mi++) {
        int r0 = wm + mi * 16 + (lane >> 2);
        float lam0 = exp2f(sdec * (float)r0);
        float lam1 = exp2f(sdec * (float)(r0 + 8));
        #pragma unroll
        for (int ni = 0; ni < 4; ni++) {
            int col = wn + ni * 8 + 2 * (lane & 3);
            *(float2*)(Og + (size_t)r0 * VDIMQ + col) =
                make_float2(oacc[mi][ni][0] + lam0 * xacc[mi][ni][0],
                            oacc[mi][ni][1] + lam0 * xacc[mi][ni][1]);
            *(float2*)(Og + (size_t)(r0 + 8) * VDIMQ + col) =
                make_float2(oacc[mi][ni][2] + lam1 * xacc[mi][ni][2],
                            oacc[mi][ni][3] + lam1 * xacc[mi][ni][3]);
        }
    }
}

// ---------------------------------------------------------------------------
// Fused RMSNorm + swish gate + split -> fp16 hi/lo
// ---------------------------------------------------------------------------
__global__ void __launch_bounds__(256) normgate_split_kernel(const float* __restrict__ gw)
{
    const int warp = (blockIdx.x << 3) + (threadIdx.x >> 5);
    const int lane = threadIdx.x & 31;
    const size_t base = (size_t)(warp >> 3) * VDIMQ + (size_t)(warp & 7) * DVQ;
    const float* Op = g_O + base;
    const float* Gp = g_G + base;
    __half* Oh = g_O_hi + base;
    __half* Ol = g_O_lo + base;

    const int d0 = lane * 4;
    const int d1 = 128 + lane * 4;
    float4 o0 = *(const float4*)(Op + d0);
    float4 o1 = *(const float4*)(Op + d1);

    float ss = o0.x*o0.x + o0.y*o0.y + o0.z*o0.z + o0.w*o0.w
             + o1.x*o1.x + o1.y*o1.y + o1.z*o1.z + o1.w*o1.w;
    #pragma unroll
    for (int off = 16; off > 0; off >>= 1)
        ss += __shfl_xor_sync(0xFFFFFFFFu, ss, off);

    const float r = rsqrtf(ss * (1.0f / 256.0f) + 1e-5f);

    float4 g0 = *(const float4*)(Gp + d0);
    float4 g1 = *(const float4*)(Gp + d1);
    float4 w0 = *(const float4*)(gw + d0);
    float4 w1 = *(const float4*)(gw + d1);

    float v[8];
    v[0] = o0.x * r * w0.x * (g0.x / (1.0f + expf(-g0.x)));
    v[1] = o0.y * r * w0.y * (g0.y / (1.0f + expf(-g0.y)));
    v[2] = o0.z * r * w0.z * (g0.z / (1.0f + expf(-g0.z)));
    v[3] = o0.w * r * w0.w * (g0.w / (1.0f + expf(-g0.w)));
    v[4] = o1.x * r * w1.x * (g1.x / (1.0f + expf(-g1.x)));
    v[5] = o1.y * r * w1.y * (g1.y / (1.0f + expf(-g1.y)));
    v[6] = o1.z * r * w1.z * (g1.z / (1.0f + expf(-g1.z)));
    v[7] = o1.w * r * w1.w * (g1.w / (1.0f + expf(-g1.w)));

    __half h[8], l[8];
    #pragma unroll
    for (int i = 0; i < 8; i++) {
        h[i] = __float2half(v[i]);
        l[i] = __float2half(v[i] - __half2float(h[i]));
    }
    *(__half2*)(Oh + d0)     = __half2(h[0], h[1]);
    *(__half2*)(Oh + d0 + 2) = __half2(h[2], h[3]);
    *(__half2*)(Oh + d1)     = __half2(h[4], h[5]);
    *(__half2*)(Oh + d1 + 2) = __half2(h[6], h[7]);
    *(__half2*)(Ol + d0)     = __half2(l[0], l[1]);
    *(__half2*)(Ol + d0 + 2) = __half2(l[2], l[3]);
    *(__half2*)(Ol + d1)     = __half2(l[4], l[5]);
    *(__half2*)(Ol + d1 + 2) = __half2(l[6], l[7]);
}

// ---------------------------------------------------------------------------
// kernel_launch
// ---------------------------------------------------------------------------
extern "C" void kernel_launch(void* const* d_in, const int* in_sizes, int n_in,
                              void* d_out, int out_size)
{
    const float* hs = (const float*)d_in[0];
    const float* Wq = (const float*)d_in[1];
    const float* Wk = (const float*)d_in[2];
    const float* Wv = (const float*)d_in[3];
    const float* Wg = (const float*)d_in[4];
    const float* Wo = (const float*)d_in[5];
    const float* gw = (const float*)d_in[6];
    float* out = (float*)d_out;

    __half *hsh, *hsl;
    __half *qw, *kw, *vw, *gwt, *ow;
    cudaGetSymbolAddress((void**)&hsh, g_hs_hi);
    cudaGetSymbolAddress((void**)&hsl, g_hs_lo);
    cudaGetSymbolAddress((void**)&qw, g_WqT);
    cudaGetSymbolAddress((void**)&kw, g_WkT);
    cudaGetSymbolAddress((void**)&vw, g_WvT);
    cudaGetSymbolAddress((void**)&gwt, g_WgT);
    cudaGetSymbolAddress((void**)&ow, g_WoT);

    cudaFuncSetAttribute(qkvg_gemm, cudaFuncAttributeMaxDynamicSharedMemorySize, TCG_SMEM);
    cudaFuncSetAttribute(wo_gemm,   cudaFuncAttributeMaxDynamicSharedMemorySize, TCG_SMEM);
    cudaFuncSetAttribute(chunk_state_kernel, cudaFuncAttributeMaxDynamicSharedMemorySize, ATTA_SMEM);
    cudaFuncSetAttribute(attn_chunk_kernel,  cudaFuncAttributeMaxDynamicSharedMemorySize, ATTC_SMEM);

    dim3 blk(256);

    // 1) prep
    split_kernel<<<(MROWS*HQ/4 + 255)/256, blk>>>(hs, hsh, hsl, MROWS*HQ/4);
    TDescs ds;
    ds.d[0] = { Wq, qw,  HQ,    HQ,    0    };
    ds.d[1] = { Wk, kw,  HQ,    HQ,    1024 };
    ds.d[2] = { Wv, vw,  HQ,    VDIMQ, 2048 };
    ds.d[3] = { Wg, gwt, HQ,    VDIMQ, 4096 };
    ds.d[4] = { Wo, ow,  VDIMQ, HQ,    6144 };
    transpose_multi<<<8192, blk>>>(ds);

    // 2) mega QKVG projection (emits Q hi/lo, K hi + Kdec, V hi, G)
    qkvg_gemm<<<dim3(48, MROWS/128), blk, TCG_SMEM>>>();

    // 3) chunked-recurrent retention: states -> scan -> outputs
    chunk_state_kernel<<<dim3(NCH, 16), 512, ATTA_SMEM>>>();
    scan_kernel<<<dim3(64, 16), 512>>>();
    attn_chunk_kernel<<<dim3(2, NCH, 16), 512, ATTC_SMEM>>>();

    // 4) fused RMSNorm + swish gate + split
    normgate_split_kernel<<<4096, blk>>>(gw);

    // 5) output projection
    wo_gemm<<<dim3(HQ/128, MROWS/128), blk, TCG_SMEM>>>(out);
}